// round 2
// baseline (speedup 1.0000x reference)
#include <cuda_runtime.h>
#include <math.h>

// Problem constants
#define BB   128      // batch
#define TT   512      // time steps
#define HH   512      // hidden
#define II   128      // input dim
#define G4   2048     // 4*H

#define WS_PITCH 516  // Whh smem row pitch (floats)
#define HS_PITCH 516  // h   smem row pitch (floats)

// ---------------- scratch (static device memory; no allocations) ----------
__device__ float    g_pre [(size_t)BB * TT * G4];   // per-layer input pre-activations (+bias)
__device__ float    g_bufX[(size_t)BB * TT * HH];   // enc0 out, then dec0 out
__device__ float    g_bufY[(size_t)BB * TT * HH];   // enc1 out, then dec1 out
__device__ unsigned g_barrier[16];                  // 4 groups x 4 layers

// ---------------- tiny init kernel ----------------------------------------
__global__ void zero_bar(unsigned* p, int n) {
    int i = blockIdx.x * blockDim.x + threadIdx.x;
    if (i < n) p[i] = 0u;
}

// ---------------- tiled fp32 GEMM: C[M,N] = A[M,K] * W[N,K]^T + b1 + b2 ---
// 128x64 tile, 256 threads, 8x4 per-thread accumulators.
// shiftT != 0: A logical row r (t = r % shiftT) is zeros when t==0, else
// physical row r-1 (teacher-forcing shifted input).
__global__ __launch_bounds__(256) void gemm_nt(
    const float* __restrict__ A, const float* __restrict__ W,
    const float* __restrict__ b1, const float* __restrict__ b2,
    float* __restrict__ C, int M, int N, int K, int shiftT)
{
    __shared__ float As[16][132];
    __shared__ float Ws[16][68];

    const int tid  = threadIdx.x;
    const int row0 = blockIdx.y * 128;
    const int col0 = blockIdx.x * 64;
    const int ty = tid >> 4;          // 0..15 -> 8 rows each
    const int tx = tid & 15;          // 0..15 -> 4 cols each

    float acc[8][4];
#pragma unroll
    for (int i = 0; i < 8; i++)
#pragma unroll
        for (int j = 0; j < 4; j++) acc[i][j] = 0.0f;

    const int wlr = tid >> 2;         // 0..63
    const int wlc = (tid & 3) << 2;   // 0,4,8,12

    for (int k0 = 0; k0 < K; k0 += 16) {
        // ---- A tile: 128 rows x 16 k (2 float4 per thread) ----
#pragma unroll
        for (int p = 0; p < 2; p++) {
            int e   = tid * 4 + p * 1024;
            int ar  = e >> 4;           // row in tile
            int ak  = e & 15;           // k offset
            float4 av;
            int grow = row0 + ar;
            if (shiftT) {
                if ((grow % shiftT) == 0) av = make_float4(0.f, 0.f, 0.f, 0.f);
                else av = *(const float4*)&A[(size_t)(grow - 1) * K + k0 + ak];
            } else {
                av = *(const float4*)&A[(size_t)grow * K + k0 + ak];
            }
            As[ak + 0][ar] = av.x; As[ak + 1][ar] = av.y;
            As[ak + 2][ar] = av.z; As[ak + 3][ar] = av.w;
        }
        // ---- W tile: 64 rows x 16 k (1 float4 per thread) ----
        {
            float4 wv = *(const float4*)&W[(size_t)(col0 + wlr) * K + k0 + wlc];
            Ws[wlc + 0][wlr] = wv.x; Ws[wlc + 1][wlr] = wv.y;
            Ws[wlc + 2][wlr] = wv.z; Ws[wlc + 3][wlr] = wv.w;
        }
        __syncthreads();

#pragma unroll
        for (int kk = 0; kk < 16; kk++) {
            float4 a0 = *(float4*)&As[kk][ty * 8];
            float4 a1 = *(float4*)&As[kk][ty * 8 + 4];
            float4 w4 = *(float4*)&Ws[kk][tx * 4];
            float a[8] = {a0.x, a0.y, a0.z, a0.w, a1.x, a1.y, a1.z, a1.w};
#pragma unroll
            for (int i = 0; i < 8; i++) {
                acc[i][0] += a[i] * w4.x;
                acc[i][1] += a[i] * w4.y;
                acc[i][2] += a[i] * w4.z;
                acc[i][3] += a[i] * w4.w;
            }
        }
        __syncthreads();
    }

    float bv[4];
#pragma unroll
    for (int j = 0; j < 4; j++) {
        int cc = col0 + tx * 4 + j;
        float b = 0.0f;
        if (b1) b += b1[cc];
        if (b2) b += b2[cc];
        bv[j] = b;
    }
#pragma unroll
    for (int i = 0; i < 8; i++) {
        int r = row0 + ty * 8 + i;
        float4 o;
        o.x = acc[i][0] + bv[0];
        o.y = acc[i][1] + bv[1];
        o.z = acc[i][2] + bv[2];
        o.w = acc[i][3] + bv[3];
        *(float4*)&C[(size_t)r * N + col0 + tx * 4] = o;
    }
}

// ---------------- persistent LSTM scan ------------------------------------
// One launch per layer. Grid (4 batch-groups, 32 hc-tiles), 128 threads/CTA,
// 1 CTA/SM (198KB smem). Whh slice cached in smem for the whole scan; cell
// state lives in registers; inter-CTA sync per batch-group via monotonic
// release/acquire counter (32 CTAs per group).
__global__ __launch_bounds__(128) void lstm_scan(
    const float* __restrict__ pre,    // [B,T,4H]
    const float* __restrict__ Whh,    // [4H,H]
    const float* __restrict__ h0,     // initial hidden (row stride h0s) or null (zeros)
    long long h0s,
    const float* __restrict__ cinit,  // [B,H] initial cell or null (zeros)
    float* __restrict__ hseq,         // [B,T,H]: read row t-1, write row t
    unsigned* __restrict__ bar)       // 4 counters (one per batch group), pre-zeroed
{
    extern __shared__ float sm[];
    float* ws = sm;                    // [64][WS_PITCH]
    float* hs = sm + 64 * WS_PITCH;    // [32][HS_PITCH]

    const int tid = threadIdx.x;
    const int grp = blockIdx.x;        // batch group 0..3
    const int bi0 = grp * 32;
    const int hc0 = blockIdx.y * 16;
    const int hc  = tid & 15;
    const int bq  = tid >> 4;          // 0..7 (4 batch rows each)
    const int col = hc0 + hc;
    unsigned* mybar = bar + grp;

    // ---- load Whh slice: 64 rows (4 gates x 16 hc) x 512 k ----
    for (int idx = tid * 4; idx < 64 * 512; idx += 128 * 4) {
        int r    = idx >> 9;
        int k    = idx & 511;
        int gate = r >> 4;
        int rr   = r & 15;
        float4 v = *(const float4*)&Whh[((size_t)gate * HH + hc0 + rr) * HH + k];
        *(float4*)&ws[r * WS_PITCH + k] = v;
    }

    // ---- cell state in registers ----
    float c_r[4];
#pragma unroll
    for (int i = 0; i < 4; i++) {
        int b = bi0 + bq * 4 + i;
        c_r[i] = cinit ? cinit[b * HH + col] : 0.0f;
    }

    for (int t = 0; t < TT; t++) {
        if (t > 0) {
            // group barrier: all 32 CTAs of this batch group finished step t-1
            __syncthreads();
            if (tid == 0) {
                unsigned target = (unsigned)t * 32u;
                asm volatile("red.release.gpu.global.add.u32 [%0], 1;"
                             :: "l"(mybar) : "memory");
                unsigned v;
                do {
                    asm volatile("ld.acquire.gpu.global.u32 %0, [%1];"
                                 : "=r"(v) : "l"(mybar));
                } while (v < target);
            }
            __syncthreads();
        } else {
            __syncthreads();  // ws ready
        }

        // ---- stage h(t-1) tile [32 x 512] ----
        for (int idx = tid * 4; idx < 32 * 512; idx += 128 * 4) {
            int r = idx >> 9;
            int k = idx & 511;
            int b = bi0 + r;
            float4 v;
            if (t == 0) {
                if (h0) v = *(const float4*)&h0[(size_t)b * h0s + k];
                else    v = make_float4(0.f, 0.f, 0.f, 0.f);
            } else {
                v = *(const float4*)&hseq[((size_t)b * TT + (t - 1)) * HH + k];
            }
            *(float4*)&hs[r * HS_PITCH + k] = v;
        }
        __syncthreads();

        // ---- recurrent GEMM slice: [4 batch x 4 gates] per thread, K=512 ----
        float acc[4][4];
#pragma unroll
        for (int i = 0; i < 4; i++)
#pragma unroll
            for (int g = 0; g < 4; g++) acc[i][g] = 0.0f;

#pragma unroll 4
        for (int k = 0; k < 512; k += 4) {
            float4 hv[4];
#pragma unroll
            for (int i = 0; i < 4; i++)
                hv[i] = *(float4*)&hs[(bq * 4 + i) * HS_PITCH + k];
#pragma unroll
            for (int g = 0; g < 4; g++) {
                float4 wv = *(float4*)&ws[(g * 16 + hc) * WS_PITCH + k];
#pragma unroll
                for (int i = 0; i < 4; i++)
                    acc[i][g] += hv[i].x * wv.x + hv[i].y * wv.y
                               + hv[i].z * wv.z + hv[i].w * wv.w;
            }
        }

        // ---- gates + state update ----
#pragma unroll
        for (int i = 0; i < 4; i++) {
            int b = bi0 + bq * 4 + i;
            size_t prow = ((size_t)b * TT + t) * (size_t)G4;
            float gi = acc[i][0] + pre[prow + 0 * HH + col];
            float gf = acc[i][1] + pre[prow + 1 * HH + col];
            float gg = acc[i][2] + pre[prow + 2 * HH + col];
            float go = acc[i][3] + pre[prow + 3 * HH + col];

            float i_ = 1.0f / (1.0f + __expf(-gi));
            float f_ = 1.0f / (1.0f + __expf(-gf));
            float e2 = __expf(2.0f * gg);
            float g_ = (e2 - 1.0f) / (e2 + 1.0f);
            float o_ = 1.0f / (1.0f + __expf(-go));

            float cn = f_ * c_r[i] + i_ * g_;
            c_r[i] = cn;
            float ec = __expf(2.0f * cn);
            float th = (ec - 1.0f) / (ec + 1.0f);
            hseq[((size_t)b * TT + t) * HH + col] = o_ * th;
        }
    }
}

// ---------------- host driver --------------------------------------------
extern "C" void kernel_launch(void* const* d_in, const int* in_sizes, int n_in,
                              void* d_out, int out_size)
{
    const float* x     = (const float*)d_in[0];
    const float* c_dec = (const float*)d_in[1];
    const float* eWih0 = (const float*)d_in[2];
    const float* eWhh0 = (const float*)d_in[3];
    const float* ebih0 = (const float*)d_in[4];
    const float* ebhh0 = (const float*)d_in[5];
    const float* eWih1 = (const float*)d_in[6];
    const float* eWhh1 = (const float*)d_in[7];
    const float* ebih1 = (const float*)d_in[8];
    const float* ebhh1 = (const float*)d_in[9];
    const float* dWih0 = (const float*)d_in[10];
    const float* dWhh0 = (const float*)d_in[11];
    const float* dbih0 = (const float*)d_in[12];
    const float* dbhh0 = (const float*)d_in[13];
    const float* dWih1 = (const float*)d_in[14];
    const float* dWhh1 = (const float*)d_in[15];
    const float* dbih1 = (const float*)d_in[16];
    const float* dbhh1 = (const float*)d_in[17];
    const float* fcW   = (const float*)d_in[18];
    const float* fcB   = (const float*)d_in[19];
    float*       out   = (float*)d_out;

    static float    *pre = nullptr, *bufX = nullptr, *bufY = nullptr;
    static unsigned *bars = nullptr;
    static bool      inited = false;
    const int scanSmem = (64 * WS_PITCH + 32 * HS_PITCH) * (int)sizeof(float);
    if (!inited) {
        cudaGetSymbolAddress((void**)&pre,  g_pre);
        cudaGetSymbolAddress((void**)&bufX, g_bufX);
        cudaGetSymbolAddress((void**)&bufY, g_bufY);
        cudaGetSymbolAddress((void**)&bars, g_barrier);
        cudaFuncSetAttribute(lstm_scan,
                             cudaFuncAttributeMaxDynamicSharedMemorySize, scanSmem);
        inited = true;
    }

    const int M = BB * TT;                          // 65536
    const dim3 gemmGrid2048(G4 / 64, M / 128);      // projections -> [M,2048]
    const dim3 gemmGrid128(II / 64,  M / 128);      // FC head -> [M,128]
    const dim3 scanGrid(4, 32);                     // 128 persistent CTAs

    // reset barrier counters (deterministic across graph replays)
    zero_bar<<<1, 32>>>(bars, 16);

    // ---- encoder layer 0 (h0 = c0 = 0) ----
    gemm_nt<<<gemmGrid2048, 256>>>(x, eWih0, ebih0, ebhh0, pre, M, G4, II, 0);
    lstm_scan<<<scanGrid, 128, scanSmem>>>(pre, eWhh0, nullptr, 0, nullptr,
                                           bufX, bars + 0);

    // ---- encoder layer 1 ----
    gemm_nt<<<gemmGrid2048, 256>>>(bufX, eWih1, ebih1, ebhh1, pre, M, G4, HH, 0);
    lstm_scan<<<scanGrid, 128, scanSmem>>>(pre, eWhh1, nullptr, 0, nullptr,
                                           bufY, bars + 4);

    // ---- decoder layer 0 (shifted input; h0 = enc0 final h; c0 = c_dec[0]) ----
    gemm_nt<<<gemmGrid2048, 256>>>(x, dWih0, dbih0, dbhh0, pre, M, G4, II, TT);
    lstm_scan<<<scanGrid, 128, scanSmem>>>(pre, dWhh0,
                                           bufX + (size_t)(TT - 1) * HH,
                                           (long long)TT * HH,
                                           c_dec, bufX, bars + 8);

    // ---- decoder layer 1 (h0 = enc1 final h; c0 = c_dec[1]) ----
    gemm_nt<<<gemmGrid2048, 256>>>(bufX, dWih1, dbih1, dbhh1, pre, M, G4, HH, 0);
    lstm_scan<<<scanGrid, 128, scanSmem>>>(pre, dWhh1,
                                           bufY + (size_t)(TT - 1) * HH,
                                           (long long)TT * HH,
                                           c_dec + BB * HH, bufY, bars + 12);

    // ---- FC head ----
    gemm_nt<<<gemmGrid128, 256>>>(bufY, fcW, fcB, nullptr, out, M, II, HH, 0);
}

// round 4
// speedup vs baseline: 1.0714x; 1.0714x over previous
#include <cuda_runtime.h>
#include <cuda_bf16.h>
#include <math.h>
#include <stdint.h>

// Problem constants
#define BB   128      // batch
#define TT   512      // time steps
#define HH   512      // hidden
#define II   128      // input dim
#define G4   2048     // 4*H

#define WS_PITCH 516
#define HS_PITCH 516

// ---------------- scratch (static device memory; no allocations) ----------
__device__ float    g_pre [(size_t)BB * TT * G4];
__device__ float    g_bufX[(size_t)BB * TT * HH];
__device__ float    g_bufY[(size_t)BB * TT * HH];
__device__ unsigned g_barrier[16];

// ---------------- tiny init kernel ----------------------------------------
__global__ void zero_bar(unsigned* p, int n) {
    int i = blockIdx.x * blockDim.x + threadIdx.x;
    if (i < n) p[i] = 0u;
}

// ======================= mma.sync helpers (compute_103-safe) ===============
__device__ __forceinline__ uint32_t smem_u32(const void* p) {
    return (uint32_t)__cvta_generic_to_shared(p);
}

#define LDSM4(d, addr)                                                        \
    asm volatile("ldmatrix.sync.aligned.m8n8.x4.shared.b16 "                  \
                 "{%0,%1,%2,%3}, [%4];"                                       \
                 : "=r"((d)[0]), "=r"((d)[1]), "=r"((d)[2]), "=r"((d)[3])     \
                 : "r"(addr))

#define MMA_BF16(cc, a, bb0, bb1)                                             \
    asm volatile("mma.sync.aligned.m16n8k16.row.col.f32.bf16.bf16.f32 "       \
                 "{%0,%1,%2,%3}, {%4,%5,%6,%7}, {%8,%9}, {%0,%1,%2,%3};"      \
                 : "+f"((cc)[0]), "+f"((cc)[1]), "+f"((cc)[2]), "+f"((cc)[3]) \
                 : "r"((a)[0]), "r"((a)[1]), "r"((a)[2]), "r"((a)[3]),        \
                   "r"(bb0), "r"(bb1))

// split x into bf16 hi + bf16 lo (lo = bf16(x - hi)); pack pairs into u32
__device__ __forceinline__ void split2(float x, float y,
                                       uint32_t& hi, uint32_t& lo) {
    __nv_bfloat16 hx = __float2bfloat16_rn(x);
    __nv_bfloat16 hy = __float2bfloat16_rn(y);
    __nv_bfloat16 lx = __float2bfloat16_rn(x - __bfloat162float(hx));
    __nv_bfloat16 ly = __float2bfloat16_rn(y - __bfloat162float(hy));
    hi = ((uint32_t)__bfloat16_as_ushort(hy) << 16) | __bfloat16_as_ushort(hx);
    lo = ((uint32_t)__bfloat16_as_ushort(ly) << 16) | __bfloat16_as_ushort(lx);
}

// ===================== bf16x3 mma.sync GEMM ================================
// C[M,N] = A[M,K] * W[N,K]^T + b1 (+ b2), fp32 I/O.
// CTA 128x128, 8 warps (2 m x 4 n), warp tile 64x32, K chunks of 32,
// double-buffered smem. shiftT != 0: logical A row r (t = r % shiftT) is
// zeros at t==0, else physical row r-1 (teacher-forced shifted input).
#define APITCH    40                      // bf16 elements per smem row (80B)
#define TILE_U16  (128 * APITCH)          // 5120 u16 = 10240 B per tile
#define TILE_B    (TILE_U16 * 2)
#define STAGE_U16 (4 * TILE_U16)          // Ahi, Alo, Bhi, Blo
#define GM_SMEM   (2 * STAGE_U16 * 2)     // 81920 B

__device__ __forceinline__ void load_chunk(
    const float* __restrict__ A, const float* __restrict__ W,
    int row0, int col0, int K, int k0, int shiftT, int tid,
    float4* Ar, float4* Br)
{
#pragma unroll
    for (int p = 0; p < 4; p++) {
        int e  = p * 256 + tid;
        int r  = e >> 3;
        int c4 = e & 7;
        int grow = row0 + r;
        float4 av;
        if (shiftT) {
            if ((grow % shiftT) == 0) av = make_float4(0.f, 0.f, 0.f, 0.f);
            else av = *(const float4*)&A[(size_t)(grow - 1) * K + k0 + c4 * 4];
        } else {
            av = *(const float4*)&A[(size_t)grow * K + k0 + c4 * 4];
        }
        Ar[p] = av;
        Br[p] = *(const float4*)&W[(size_t)(col0 + r) * K + k0 + c4 * 4];
    }
}

__device__ __forceinline__ void store_chunk(
    uint16_t* st, int tid, const float4* Ar, const float4* Br)
{
#pragma unroll
    for (int p = 0; p < 4; p++) {
        int e  = p * 256 + tid;
        int r  = e >> 3;
        int c4 = e & 7;
        int off = r * APITCH + c4 * 4;
        uint32_t h0, l0, h1, l1;
        split2(Ar[p].x, Ar[p].y, h0, l0);
        split2(Ar[p].z, Ar[p].w, h1, l1);
        *(uint2*)&st[off]                = make_uint2(h0, h1);
        *(uint2*)&st[TILE_U16 + off]     = make_uint2(l0, l1);
        split2(Br[p].x, Br[p].y, h0, l0);
        split2(Br[p].z, Br[p].w, h1, l1);
        *(uint2*)&st[2 * TILE_U16 + off] = make_uint2(h0, h1);
        *(uint2*)&st[3 * TILE_U16 + off] = make_uint2(l0, l1);
    }
}

__global__ __launch_bounds__(256) void gemm_mma(
    const float* __restrict__ A, const float* __restrict__ W,
    const float* __restrict__ b1, const float* __restrict__ b2,
    float* __restrict__ C, int M, int N, int K, int shiftT)
{
    extern __shared__ __align__(16) uint16_t sm16[];

    const int tid  = threadIdx.x;
    const int lane = tid & 31;
    const int wid  = tid >> 5;
    const int wm   = (wid & 1) * 64;    // warp m offset within CTA tile
    const int wn   = (wid >> 1) * 32;   // warp n offset
    const int row0 = blockIdx.y * 128;
    const int col0 = blockIdx.x * 128;

    float c[4][4][4];
#pragma unroll
    for (int i = 0; i < 4; i++)
#pragma unroll
        for (int j = 0; j < 4; j++)
#pragma unroll
            for (int q = 0; q < 4; q++) c[i][j][q] = 0.0f;

    float4 Ar[4], Br[4];
    const int nch = K / 32;
    load_chunk(A, W, row0, col0, K, 0, shiftT, tid, Ar, Br);

    for (int i = 0; i < nch; i++) {
        const int s = i & 1;
        uint16_t* st = sm16 + s * STAGE_U16;
        store_chunk(st, tid, Ar, Br);
        __syncthreads();
        if (i + 1 < nch)
            load_chunk(A, W, row0, col0, K, (i + 1) * 32, shiftT, tid, Ar, Br);

        const uint32_t base = smem_u32(st);
#pragma unroll
        for (int kh = 0; kh < 2; kh++) {
            // ---- A fragments (hi & lo), 4 m-tiles ----
            uint32_t ah[4][4], al[4][4];
            const int arow = wm + (lane & 15);
            const int akk  = kh * 16 + (lane >> 4) * 8;
#pragma unroll
            for (int mt = 0; mt < 4; mt++) {
                uint32_t boff = (uint32_t)(((arow + mt * 16) * APITCH + akk) * 2);
                LDSM4(ah[mt], base + boff);
                LDSM4(al[mt], base + TILE_B + boff);
            }
            // ---- B fragments (hi & lo), 2 n-pairs (2 n8-tiles each) ----
            uint32_t bh[2][4], bl[2][4];
            const int brow = wn + (lane & 7) + ((lane >> 4) << 3);
            const int bkk  = kh * 16 + ((lane >> 3) & 1) * 8;
#pragma unroll
            for (int np = 0; np < 2; np++) {
                uint32_t boff = (uint32_t)(((brow + np * 16) * APITCH + bkk) * 2);
                LDSM4(bh[np], base + 2 * TILE_B + boff);
                LDSM4(bl[np], base + 3 * TILE_B + boff);
            }
            // ---- 48 mma: hi*hi + hi*lo + lo*hi ----
#pragma unroll
            for (int mt = 0; mt < 4; mt++)
#pragma unroll
                for (int np = 0; np < 2; np++)
#pragma unroll
                    for (int h = 0; h < 2; h++) {
                        int nt = np * 2 + h;
                        MMA_BF16(c[mt][nt], ah[mt], bh[np][h * 2], bh[np][h * 2 + 1]);
                        MMA_BF16(c[mt][nt], ah[mt], bl[np][h * 2], bl[np][h * 2 + 1]);
                        MMA_BF16(c[mt][nt], al[mt], bh[np][h * 2], bh[np][h * 2 + 1]);
                    }
        }
        __syncthreads();
    }

    // ---- epilogue: fragment layout c0,c1 = (row, col/col+1), c2,c3 = row+8
#pragma unroll
    for (int mt = 0; mt < 4; mt++) {
#pragma unroll
        for (int nt = 0; nt < 4; nt++) {
            int m = row0 + wm + mt * 16 + (lane >> 2);
            int n = col0 + wn + nt * 8 + (lane & 3) * 2;
            float bx = b1[n]     + (b2 ? b2[n]     : 0.f);
            float by = b1[n + 1] + (b2 ? b2[n + 1] : 0.f);
            float2 v0 = make_float2(c[mt][nt][0] + bx, c[mt][nt][1] + by);
            float2 v1 = make_float2(c[mt][nt][2] + bx, c[mt][nt][3] + by);
            *(float2*)&C[(size_t)m * N + n]       = v0;
            *(float2*)&C[(size_t)(m + 8) * N + n] = v1;
        }
    }
}

// ---------------- persistent LSTM scan (unchanged, known-good) ------------
__global__ __launch_bounds__(128) void lstm_scan(
    const float* __restrict__ pre,
    const float* __restrict__ Whh,
    const float* __restrict__ h0,
    long long h0s,
    const float* __restrict__ cinit,
    float* __restrict__ hseq,
    unsigned* __restrict__ bar)
{
    extern __shared__ float smf[];
    float* ws = smf;
    float* hs = smf + 64 * WS_PITCH;

    const int tid = threadIdx.x;
    const int grp = blockIdx.x;
    const int bi0 = grp * 32;
    const int hc0 = blockIdx.y * 16;
    const int hc  = tid & 15;
    const int bq  = tid >> 4;
    const int col = hc0 + hc;
    unsigned* mybar = bar + grp;

    for (int idx = tid * 4; idx < 64 * 512; idx += 128 * 4) {
        int r    = idx >> 9;
        int k    = idx & 511;
        int gate = r >> 4;
        int rr   = r & 15;
        float4 v = *(const float4*)&Whh[((size_t)gate * HH + hc0 + rr) * HH + k];
        *(float4*)&ws[r * WS_PITCH + k] = v;
    }

    float c_r[4];
#pragma unroll
    for (int i = 0; i < 4; i++) {
        int b = bi0 + bq * 4 + i;
        c_r[i] = cinit ? cinit[b * HH + col] : 0.0f;
    }

    for (int t = 0; t < TT; t++) {
        if (t > 0) {
            __syncthreads();
            if (tid == 0) {
                unsigned target = (unsigned)t * 32u;
                asm volatile("red.release.gpu.global.add.u32 [%0], 1;"
                             :: "l"(mybar) : "memory");
                unsigned v;
                do {
                    asm volatile("ld.acquire.gpu.global.u32 %0, [%1];"
                                 : "=r"(v) : "l"(mybar));
                } while (v < target);
            }
            __syncthreads();
        } else {
            __syncthreads();
        }

        for (int idx = tid * 4; idx < 32 * 512; idx += 128 * 4) {
            int r = idx >> 9;
            int k = idx & 511;
            int b = bi0 + r;
            float4 v;
            if (t == 0) {
                if (h0) v = *(const float4*)&h0[(size_t)b * h0s + k];
                else    v = make_float4(0.f, 0.f, 0.f, 0.f);
            } else {
                v = *(const float4*)&hseq[((size_t)b * TT + (t - 1)) * HH + k];
            }
            *(float4*)&hs[r * HS_PITCH + k] = v;
        }
        __syncthreads();

        float acc[4][4];
#pragma unroll
        for (int i = 0; i < 4; i++)
#pragma unroll
            for (int g = 0; g < 4; g++) acc[i][g] = 0.0f;

#pragma unroll 4
        for (int k = 0; k < 512; k += 4) {
            float4 hv[4];
#pragma unroll
            for (int i = 0; i < 4; i++)
                hv[i] = *(float4*)&hs[(bq * 4 + i) * HS_PITCH + k];
#pragma unroll
            for (int g = 0; g < 4; g++) {
                float4 wv = *(float4*)&ws[(g * 16 + hc) * WS_PITCH + k];
#pragma unroll
                for (int i = 0; i < 4; i++)
                    acc[i][g] += hv[i].x * wv.x + hv[i].y * wv.y
                               + hv[i].z * wv.z + hv[i].w * wv.w;
            }
        }

#pragma unroll
        for (int i = 0; i < 4; i++) {
            int b = bi0 + bq * 4 + i;
            size_t prow = ((size_t)b * TT + t) * (size_t)G4;
            float gi = acc[i][0] + pre[prow + 0 * HH + col];
            float gf = acc[i][1] + pre[prow + 1 * HH + col];
            float gg = acc[i][2] + pre[prow + 2 * HH + col];
            float go = acc[i][3] + pre[prow + 3 * HH + col];

            float i_ = 1.0f / (1.0f + __expf(-gi));
            float f_ = 1.0f / (1.0f + __expf(-gf));
            float e2 = __expf(2.0f * gg);
            float g_ = (e2 - 1.0f) / (e2 + 1.0f);
            float o_ = 1.0f / (1.0f + __expf(-go));

            float cn = f_ * c_r[i] + i_ * g_;
            c_r[i] = cn;
            float ec = __expf(2.0f * cn);
            float th = (ec - 1.0f) / (ec + 1.0f);
            hseq[((size_t)b * TT + t) * HH + col] = o_ * th;
        }
    }
}

// ---------------- host driver --------------------------------------------
extern "C" void kernel_launch(void* const* d_in, const int* in_sizes, int n_in,
                              void* d_out, int out_size)
{
    const float* x     = (const float*)d_in[0];
    const float* c_dec = (const float*)d_in[1];
    const float* eWih0 = (const float*)d_in[2];
    const float* eWhh0 = (const float*)d_in[3];
    const float* ebih0 = (const float*)d_in[4];
    const float* ebhh0 = (const float*)d_in[5];
    const float* eWih1 = (const float*)d_in[6];
    const float* eWhh1 = (const float*)d_in[7];
    const float* ebih1 = (const float*)d_in[8];
    const float* ebhh1 = (const float*)d_in[9];
    const float* dWih0 = (const float*)d_in[10];
    const float* dWhh0 = (const float*)d_in[11];
    const float* dbih0 = (const float*)d_in[12];
    const float* dbhh0 = (const float*)d_in[13];
    const float* dWih1 = (const float*)d_in[14];
    const float* dWhh1 = (const float*)d_in[15];
    const float* dbih1 = (const float*)d_in[16];
    const float* dbhh1 = (const float*)d_in[17];
    const float* fcW   = (const float*)d_in[18];
    const float* fcB   = (const float*)d_in[19];
    float*       out   = (float*)d_out;

    static float    *pre = nullptr, *bufX = nullptr, *bufY = nullptr;
    static unsigned *bars = nullptr;
    static bool      inited = false;
    const int scanSmem = (64 * WS_PITCH + 32 * HS_PITCH) * (int)sizeof(float);
    if (!inited) {
        cudaGetSymbolAddress((void**)&pre,  g_pre);
        cudaGetSymbolAddress((void**)&bufX, g_bufX);
        cudaGetSymbolAddress((void**)&bufY, g_bufY);
        cudaGetSymbolAddress((void**)&bars, g_barrier);
        cudaFuncSetAttribute(lstm_scan,
                             cudaFuncAttributeMaxDynamicSharedMemorySize, scanSmem);
        cudaFuncSetAttribute(gemm_mma,
                             cudaFuncAttributeMaxDynamicSharedMemorySize, GM_SMEM);
        inited = true;
    }

    const int M = BB * TT;                          // 65536
    const dim3 gemmGrid2048(G4 / 128, M / 128);     // (16, 512)
    const dim3 gemmGrid128(II / 128,  M / 128);     // (1, 512)
    const dim3 scanGrid(4, 32);

    zero_bar<<<1, 32>>>(bars, 16);

    // ---- encoder layer 0 ----
    gemm_mma<<<gemmGrid2048, 256, GM_SMEM>>>(x, eWih0, ebih0, ebhh0, pre, M, G4, II, 0);
    lstm_scan<<<scanGrid, 128, scanSmem>>>(pre, eWhh0, nullptr, 0, nullptr,
                                           bufX, bars + 0);

    // ---- encoder layer 1 ----
    gemm_mma<<<gemmGrid2048, 256, GM_SMEM>>>(bufX, eWih1, ebih1, ebhh1, pre, M, G4, HH, 0);
    lstm_scan<<<scanGrid, 128, scanSmem>>>(pre, eWhh1, nullptr, 0, nullptr,
                                           bufY, bars + 4);

    // ---- decoder layer 0 (shifted input; h0 = enc0 final h; c0 = c_dec[0]) ----
    gemm_mma<<<gemmGrid2048, 256, GM_SMEM>>>(x, dWih0, dbih0, dbhh0, pre, M, G4, II, TT);
    lstm_scan<<<scanGrid, 128, scanSmem>>>(pre, dWhh0,
                                           bufX + (size_t)(TT - 1) * HH,
                                           (long long)TT * HH,
                                           c_dec, bufX, bars + 8);

    // ---- decoder layer 1 (h0 = enc1 final h; c0 = c_dec[1]) ----
    gemm_mma<<<gemmGrid2048, 256, GM_SMEM>>>(bufX, dWih1, dbih1, dbhh1, pre, M, G4, HH, 0);
    lstm_scan<<<scanGrid, 128, scanSmem>>>(pre, dWhh1,
                                           bufY + (size_t)(TT - 1) * HH,
                                           (long long)TT * HH,
                                           c_dec + BB * HH, bufY, bars + 12);

    // ---- FC head ----
    gemm_mma<<<gemmGrid128, 256, GM_SMEM>>>(bufY, fcW, fcB, nullptr, out, M, II, HH, 0);
}

// round 5
// speedup vs baseline: 1.2377x; 1.1552x over previous
#include <cuda_runtime.h>
#include <cuda_bf16.h>
#include <math.h>
#include <stdint.h>

// Problem constants
#define BB   128      // batch
#define TT   512      // time steps
#define HH   512      // hidden
#define II   128      // input dim
#define G4   2048     // 4*H

// ---------------- scratch (static device memory; no allocations) ----------
__device__ float    g_pre [(size_t)BB * TT * G4];
__device__ float    g_bufX[(size_t)BB * TT * HH];
__device__ float    g_bufY[(size_t)BB * TT * HH];
__device__ unsigned g_barrier[16];

// ---------------- tiny init kernel ----------------------------------------
__global__ void zero_bar(unsigned* p, int n) {
    int i = blockIdx.x * blockDim.x + threadIdx.x;
    if (i < n) p[i] = 0u;
}

// ======================= mma.sync helpers (compute_103-safe) ===============
__device__ __forceinline__ uint32_t smem_u32(const void* p) {
    return (uint32_t)__cvta_generic_to_shared(p);
}

#define LDSM4(d, addr)                                                        \
    asm volatile("ldmatrix.sync.aligned.m8n8.x4.shared.b16 "                  \
                 "{%0,%1,%2,%3}, [%4];"                                       \
                 : "=r"((d)[0]), "=r"((d)[1]), "=r"((d)[2]), "=r"((d)[3])     \
                 : "r"(addr))

#define MMA_BF16(cc, a, bb0, bb1)                                             \
    asm volatile("mma.sync.aligned.m16n8k16.row.col.f32.bf16.bf16.f32 "       \
                 "{%0,%1,%2,%3}, {%4,%5,%6,%7}, {%8,%9}, {%0,%1,%2,%3};"      \
                 : "+f"((cc)[0]), "+f"((cc)[1]), "+f"((cc)[2]), "+f"((cc)[3]) \
                 : "r"((a)[0]), "r"((a)[1]), "r"((a)[2]), "r"((a)[3]),        \
                   "r"(bb0), "r"(bb1))

// split x into bf16 hi + bf16 lo (lo = bf16(x - hi)); pack pairs into u32
__device__ __forceinline__ void split2(float x, float y,
                                       uint32_t& hi, uint32_t& lo) {
    __nv_bfloat16 hx = __float2bfloat16_rn(x);
    __nv_bfloat16 hy = __float2bfloat16_rn(y);
    __nv_bfloat16 lx = __float2bfloat16_rn(x - __bfloat162float(hx));
    __nv_bfloat16 ly = __float2bfloat16_rn(y - __bfloat162float(hy));
    hi = ((uint32_t)__bfloat16_as_ushort(hy) << 16) | __bfloat16_as_ushort(hx);
    lo = ((uint32_t)__bfloat16_as_ushort(ly) << 16) | __bfloat16_as_ushort(lx);
}

// ===================== bf16x3 mma.sync GEMM (validated) ====================
#define APITCH    40
#define TILE_U16  (128 * APITCH)
#define TILE_B    (TILE_U16 * 2)
#define STAGE_U16 (4 * TILE_U16)
#define GM_SMEM   (2 * STAGE_U16 * 2)

__device__ __forceinline__ void load_chunk(
    const float* __restrict__ A, const float* __restrict__ W,
    int row0, int col0, int K, int k0, int shiftT, int tid,
    float4* Ar, float4* Br)
{
#pragma unroll
    for (int p = 0; p < 4; p++) {
        int e  = p * 256 + tid;
        int r  = e >> 3;
        int c4 = e & 7;
        int grow = row0 + r;
        float4 av;
        if (shiftT) {
            if ((grow % shiftT) == 0) av = make_float4(0.f, 0.f, 0.f, 0.f);
            else av = *(const float4*)&A[(size_t)(grow - 1) * K + k0 + c4 * 4];
        } else {
            av = *(const float4*)&A[(size_t)grow * K + k0 + c4 * 4];
        }
        Ar[p] = av;
        Br[p] = *(const float4*)&W[(size_t)(col0 + r) * K + k0 + c4 * 4];
    }
}

__device__ __forceinline__ void store_chunk(
    uint16_t* st, int tid, const float4* Ar, const float4* Br)
{
#pragma unroll
    for (int p = 0; p < 4; p++) {
        int e  = p * 256 + tid;
        int r  = e >> 3;
        int c4 = e & 7;
        int off = r * APITCH + c4 * 4;
        uint32_t h0, l0, h1, l1;
        split2(Ar[p].x, Ar[p].y, h0, l0);
        split2(Ar[p].z, Ar[p].w, h1, l1);
        *(uint2*)&st[off]                = make_uint2(h0, h1);
        *(uint2*)&st[TILE_U16 + off]     = make_uint2(l0, l1);
        split2(Br[p].x, Br[p].y, h0, l0);
        split2(Br[p].z, Br[p].w, h1, l1);
        *(uint2*)&st[2 * TILE_U16 + off] = make_uint2(h0, h1);
        *(uint2*)&st[3 * TILE_U16 + off] = make_uint2(l0, l1);
    }
}

__global__ __launch_bounds__(256) void gemm_mma(
    const float* __restrict__ A, const float* __restrict__ W,
    const float* __restrict__ b1, const float* __restrict__ b2,
    float* __restrict__ C, int M, int N, int K, int shiftT)
{
    extern __shared__ __align__(16) uint16_t sm16[];

    const int tid  = threadIdx.x;
    const int lane = tid & 31;
    const int wid  = tid >> 5;
    const int wm   = (wid & 1) * 64;
    const int wn   = (wid >> 1) * 32;
    const int row0 = blockIdx.y * 128;
    const int col0 = blockIdx.x * 128;

    float c[4][4][4];
#pragma unroll
    for (int i = 0; i < 4; i++)
#pragma unroll
        for (int j = 0; j < 4; j++)
#pragma unroll
            for (int q = 0; q < 4; q++) c[i][j][q] = 0.0f;

    float4 Ar[4], Br[4];
    const int nch = K / 32;
    load_chunk(A, W, row0, col0, K, 0, shiftT, tid, Ar, Br);

    for (int i = 0; i < nch; i++) {
        const int s = i & 1;
        uint16_t* st = sm16 + s * STAGE_U16;
        store_chunk(st, tid, Ar, Br);
        __syncthreads();
        if (i + 1 < nch)
            load_chunk(A, W, row0, col0, K, (i + 1) * 32, shiftT, tid, Ar, Br);

        const uint32_t base = smem_u32(st);
#pragma unroll
        for (int kh = 0; kh < 2; kh++) {
            uint32_t ah[4][4], al[4][4];
            const int arow = wm + (lane & 15);
            const int akk  = kh * 16 + (lane >> 4) * 8;
#pragma unroll
            for (int mt = 0; mt < 4; mt++) {
                uint32_t boff = (uint32_t)(((arow + mt * 16) * APITCH + akk) * 2);
                LDSM4(ah[mt], base + boff);
                LDSM4(al[mt], base + TILE_B + boff);
            }
            uint32_t bh[2][4], bl[2][4];
            const int brow = wn + (lane & 7) + ((lane >> 4) << 3);
            const int bkk  = kh * 16 + ((lane >> 3) & 1) * 8;
#pragma unroll
            for (int np = 0; np < 2; np++) {
                uint32_t boff = (uint32_t)(((brow + np * 16) * APITCH + bkk) * 2);
                LDSM4(bh[np], base + 2 * TILE_B + boff);
                LDSM4(bl[np], base + 3 * TILE_B + boff);
            }
#pragma unroll
            for (int mt = 0; mt < 4; mt++)
#pragma unroll
                for (int np = 0; np < 2; np++)
#pragma unroll
                    for (int h = 0; h < 2; h++) {
                        int nt = np * 2 + h;
                        MMA_BF16(c[mt][nt], ah[mt], bh[np][h * 2], bh[np][h * 2 + 1]);
                        MMA_BF16(c[mt][nt], ah[mt], bl[np][h * 2], bl[np][h * 2 + 1]);
                        MMA_BF16(c[mt][nt], al[mt], bh[np][h * 2], bh[np][h * 2 + 1]);
                    }
        }
        __syncthreads();
    }

#pragma unroll
    for (int mt = 0; mt < 4; mt++) {
#pragma unroll
        for (int nt = 0; nt < 4; nt++) {
            int m = row0 + wm + mt * 16 + (lane >> 2);
            int n = col0 + wn + nt * 8 + (lane & 3) * 2;
            float bx = b1[n]     + (b2 ? b2[n]     : 0.f);
            float by = b1[n + 1] + (b2 ? b2[n + 1] : 0.f);
            float2 v0 = make_float2(c[mt][nt][0] + bx, c[mt][nt][1] + by);
            float2 v1 = make_float2(c[mt][nt][2] + bx, c[mt][nt][3] + by);
            *(float2*)&C[(size_t)m * N + n]       = v0;
            *(float2*)&C[(size_t)(m + 8) * N + n] = v1;
        }
    }
}

// ===================== tensor-core persistent LSTM scan ====================
// Grid (4 batch-groups, 32 hc-tiles), 128 threads (4 warps). Warp w computes
// gate w for [32 batch x 16 h-cols] via bf16x3 mma.sync. Whh slice split to
// bf16 hi/lo in smem once; h(t-1) staged+split each step; cell state in regs.
#define WPITCH 520                     // bf16 elems per smem row (1040 B)
#define W_U16  (64 * WPITCH)           // one weight tile (hi or lo)
#define H_U16  (32 * WPITCH)           // one h tile (hi or lo)
#define GPITCH 18
#define SCAN_SMEM ((2 * W_U16 + 2 * H_U16) * 2 + 4 * 32 * GPITCH * 4)

__global__ __launch_bounds__(128) void lstm_scan(
    const float* __restrict__ pre,    // [B,T,4H]
    const float* __restrict__ Whh,    // [4H,H]
    const float* __restrict__ h0,     // initial hidden (row stride h0s) or null
    long long h0s,
    const float* __restrict__ cinit,  // [B,H] initial cell or null
    float* __restrict__ hseq,         // [B,T,H]
    unsigned* __restrict__ bar)
{
    extern __shared__ __align__(16) uint16_t sm16[];
    uint16_t* wsh = sm16;
    uint16_t* wsl = wsh + W_U16;
    uint16_t* hsh = wsl + W_U16;
    uint16_t* hsl = hsh + H_U16;
    float*    gsm = (float*)(hsl + H_U16);   // [4][32][GPITCH]

    const int tid  = threadIdx.x;
    const int lane = tid & 31;
    const int wid  = tid >> 5;
    const int grp  = blockIdx.x;
    const int bi0  = grp * 32;
    const int hc0  = blockIdx.y * 16;
    unsigned* mybar = bar + grp;

    // ---- load + split Whh slice: rows n = gate*16 + rr  (n = 0..63) ----
    for (int idx = tid * 4; idx < 64 * 512; idx += 128 * 4) {
        int r    = idx >> 9;
        int k    = idx & 511;
        int gate = r >> 4;
        int rr   = r & 15;
        float4 v = *(const float4*)&Whh[((size_t)gate * HH + hc0 + rr) * HH + k];
        uint32_t h0w, l0w, h1w, l1w;
        split2(v.x, v.y, h0w, l0w);
        split2(v.z, v.w, h1w, l1w);
        *(uint2*)&wsh[r * WPITCH + k] = make_uint2(h0w, h1w);
        *(uint2*)&wsl[r * WPITCH + k] = make_uint2(l0w, l1w);
    }

    // ---- cell state in registers: thread owns (b = bq*4+i, j = tid&15) ----
    const int j   = tid & 15;
    const int bq  = tid >> 4;            // 0..7
    const int col = hc0 + j;
    float c_r[4];
#pragma unroll
    for (int i = 0; i < 4; i++) {
        int b = bi0 + bq * 4 + i;
        c_r[i] = cinit ? cinit[b * HH + col] : 0.0f;
    }

    const uint32_t hshb = smem_u32(hsh);
    const uint32_t hslb = smem_u32(hsl);
    const uint32_t wshb = smem_u32(wsh);
    const uint32_t wslb = smem_u32(wsl);

    for (int t = 0; t < TT; t++) {
        __syncthreads();
        if (t > 0) {
            if (tid == 0) {
                unsigned target = (unsigned)t * 32u;
                asm volatile("red.release.gpu.global.add.u32 [%0], 1;"
                             :: "l"(mybar) : "memory");
                unsigned v;
                do {
                    asm volatile("ld.acquire.gpu.global.u32 %0, [%1];"
                                 : "=r"(v) : "l"(mybar));
                } while (v < target);
            }
            __syncthreads();
        }

        // ---- stage h(t-1): fp32 -> bf16 hi/lo smem ----
        for (int idx = tid * 4; idx < 32 * 512; idx += 128 * 4) {
            int r = idx >> 9;
            int k = idx & 511;
            int b = bi0 + r;
            float4 v;
            if (t == 0) {
                if (h0) v = *(const float4*)&h0[(size_t)b * h0s + k];
                else    v = make_float4(0.f, 0.f, 0.f, 0.f);
            } else {
                v = *(const float4*)&hseq[((size_t)b * TT + (t - 1)) * HH + k];
            }
            uint32_t h0w, l0w, h1w, l1w;
            split2(v.x, v.y, h0w, l0w);
            split2(v.z, v.w, h1w, l1w);
            *(uint2*)&hsh[r * WPITCH + k] = make_uint2(h0w, h1w);
            *(uint2*)&hsl[r * WPITCH + k] = make_uint2(l0w, l1w);
        }
        __syncthreads();

        // ---- recurrent GEMM: warp wid computes gate wid, [32 x 16] ----
        float c[2][2][4];
#pragma unroll
        for (int mt = 0; mt < 2; mt++)
#pragma unroll
            for (int nt = 0; nt < 2; nt++)
#pragma unroll
                for (int q = 0; q < 4; q++) c[mt][nt][q] = 0.0f;

        const int arow = lane & 15;
        const int aoff = (lane >> 4) * 8;
        const int brow = wid * 16 + (lane & 7) + ((lane >> 4) << 3);
        const int boff = ((lane >> 3) & 1) * 8;

#pragma unroll 4
        for (int kc = 0; kc < 512; kc += 16) {
            uint32_t ah[2][4], al[2][4], bh4[4], bl4[4];
#pragma unroll
            for (int mt = 0; mt < 2; mt++) {
                uint32_t off = (uint32_t)(((mt * 16 + arow) * WPITCH + kc + aoff) * 2);
                LDSM4(ah[mt], hshb + off);
                LDSM4(al[mt], hslb + off);
            }
            {
                uint32_t off = (uint32_t)((brow * WPITCH + kc + boff) * 2);
                LDSM4(bh4, wshb + off);
                LDSM4(bl4, wslb + off);
            }
#pragma unroll
            for (int mt = 0; mt < 2; mt++)
#pragma unroll
                for (int h = 0; h < 2; h++) {
                    MMA_BF16(c[mt][h], ah[mt], bh4[h * 2], bh4[h * 2 + 1]);
                    MMA_BF16(c[mt][h], ah[mt], bl4[h * 2], bl4[h * 2 + 1]);
                    MMA_BF16(c[mt][h], al[mt], bh4[h * 2], bh4[h * 2 + 1]);
                }
        }

        // ---- fragments -> smem gate buffer: gsm[wid][m][n] ----
#pragma unroll
        for (int mt = 0; mt < 2; mt++)
#pragma unroll
            for (int nt = 0; nt < 2; nt++) {
                int m = mt * 16 + (lane >> 2);
                int n = nt * 8 + (lane & 3) * 2;
                float* gbase = gsm + (wid * 32 + m) * GPITCH + n;
                *(float2*)gbase                = make_float2(c[mt][nt][0], c[mt][nt][1]);
                *(float2*)(gbase + 8 * GPITCH) = make_float2(c[mt][nt][2], c[mt][nt][3]);
            }
        __syncthreads();

        // ---- gates + state update ----
#pragma unroll
        for (int i = 0; i < 4; i++) {
            int bl_ = bq * 4 + i;            // local batch 0..31
            int b   = bi0 + bl_;
            size_t prow = ((size_t)b * TT + t) * (size_t)G4;
            float gi = gsm[(0 * 32 + bl_) * GPITCH + j] + pre[prow + 0 * HH + col];
            float gf = gsm[(1 * 32 + bl_) * GPITCH + j] + pre[prow + 1 * HH + col];
            float gg = gsm[(2 * 32 + bl_) * GPITCH + j] + pre[prow + 2 * HH + col];
            float go = gsm[(3 * 32 + bl_) * GPITCH + j] + pre[prow + 3 * HH + col];

            float i_ = 1.0f / (1.0f + __expf(-gi));
            float f_ = 1.0f / (1.0f + __expf(-gf));
            float e2 = __expf(2.0f * gg);
            float g_ = (e2 - 1.0f) / (e2 + 1.0f);
            float o_ = 1.0f / (1.0f + __expf(-go));

            float cn = f_ * c_r[i] + i_ * g_;
            c_r[i] = cn;
            float ec = __expf(2.0f * cn);
            float th = (ec - 1.0f) / (ec + 1.0f);
            hseq[((size_t)b * TT + t) * HH + col] = o_ * th;
        }
    }
}

// ---------------- host driver --------------------------------------------
extern "C" void kernel_launch(void* const* d_in, const int* in_sizes, int n_in,
                              void* d_out, int out_size)
{
    const float* x     = (const float*)d_in[0];
    const float* c_dec = (const float*)d_in[1];
    const float* eWih0 = (const float*)d_in[2];
    const float* eWhh0 = (const float*)d_in[3];
    const float* ebih0 = (const float*)d_in[4];
    const float* ebhh0 = (const float*)d_in[5];
    const float* eWih1 = (const float*)d_in[6];
    const float* eWhh1 = (const float*)d_in[7];
    const float* ebih1 = (const float*)d_in[8];
    const float* ebhh1 = (const float*)d_in[9];
    const float* dWih0 = (const float*)d_in[10];
    const float* dWhh0 = (const float*)d_in[11];
    const float* dbih0 = (const float*)d_in[12];
    const float* dbhh0 = (const float*)d_in[13];
    const float* dWih1 = (const float*)d_in[14];
    const float* dWhh1 = (const float*)d_in[15];
    const float* dbih1 = (const float*)d_in[16];
    const float* dbhh1 = (const float*)d_in[17];
    const float* fcW   = (const float*)d_in[18];
    const float* fcB   = (const float*)d_in[19];
    float*       out   = (float*)d_out;

    static float    *pre = nullptr, *bufX = nullptr, *bufY = nullptr;
    static unsigned *bars = nullptr;
    static bool      inited = false;
    if (!inited) {
        cudaGetSymbolAddress((void**)&pre,  g_pre);
        cudaGetSymbolAddress((void**)&bufX, g_bufX);
        cudaGetSymbolAddress((void**)&bufY, g_bufY);
        cudaGetSymbolAddress((void**)&bars, g_barrier);
        cudaFuncSetAttribute(lstm_scan,
                             cudaFuncAttributeMaxDynamicSharedMemorySize, SCAN_SMEM);
        cudaFuncSetAttribute(gemm_mma,
                             cudaFuncAttributeMaxDynamicSharedMemorySize, GM_SMEM);
        inited = true;
    }

    const int M = BB * TT;                          // 65536
    const dim3 gemmGrid2048(G4 / 128, M / 128);     // (16, 512)
    const dim3 gemmGrid128(II / 128,  M / 128);     // (1, 512)
    const dim3 scanGrid(4, 32);

    zero_bar<<<1, 32>>>(bars, 16);

    // ---- encoder layer 0 ----
    gemm_mma<<<gemmGrid2048, 256, GM_SMEM>>>(x, eWih0, ebih0, ebhh0, pre, M, G4, II, 0);
    lstm_scan<<<scanGrid, 128, SCAN_SMEM>>>(pre, eWhh0, nullptr, 0, nullptr,
                                            bufX, bars + 0);

    // ---- encoder layer 1 ----
    gemm_mma<<<gemmGrid2048, 256, GM_SMEM>>>(bufX, eWih1, ebih1, ebhh1, pre, M, G4, HH, 0);
    lstm_scan<<<scanGrid, 128, SCAN_SMEM>>>(pre, eWhh1, nullptr, 0, nullptr,
                                            bufY, bars + 4);

    // ---- decoder layer 0 (shifted input; h0 = enc0 final h; c0 = c_dec[0]) ----
    gemm_mma<<<gemmGrid2048, 256, GM_SMEM>>>(x, dWih0, dbih0, dbhh0, pre, M, G4, II, TT);
    lstm_scan<<<scanGrid, 128, SCAN_SMEM>>>(pre, dWhh0,
                                            bufX + (size_t)(TT - 1) * HH,
                                            (long long)TT * HH,
                                            c_dec, bufX, bars + 8);

    // ---- decoder layer 1 (h0 = enc1 final h; c0 = c_dec[1]) ----
    gemm_mma<<<gemmGrid2048, 256, GM_SMEM>>>(bufX, dWih1, dbih1, dbhh1, pre, M, G4, HH, 0);
    lstm_scan<<<scanGrid, 128, SCAN_SMEM>>>(pre, dWhh1,
                                            bufY + (size_t)(TT - 1) * HH,
                                            (long long)TT * HH,
                                            c_dec + BB * HH, bufY, bars + 12);

    // ---- FC head ----
    gemm_mma<<<gemmGrid128, 256, GM_SMEM>>>(bufY, fcW, fcB, nullptr, out, M, II, HH, 0);
}

// round 6
// speedup vs baseline: 2.2316x; 1.8031x over previous
#include <cuda_runtime.h>
#include <cuda_bf16.h>
#include <math.h>
#include <stdint.h>

// Problem constants
#define BB   128      // batch
#define TT   512      // time steps
#define HH   512      // hidden
#define II   128      // input dim
#define G4   2048     // 4*H

// ---------------- scratch (static device memory; no allocations) ----------
__device__ float    g_pre [(size_t)BB * TT * G4];
__device__ float    g_bufX[(size_t)BB * TT * HH];
__device__ float    g_bufY[(size_t)BB * TT * HH];
__device__ unsigned g_barrier[512];   // 4 layers x 4 groups, 128B-padded

// ---------------- tiny init kernel ----------------------------------------
__global__ void zero_bar(unsigned* p, int n) {
    int i = blockIdx.x * blockDim.x + threadIdx.x;
    if (i < n) p[i] = 0u;
}

// ======================= mma.sync helpers (compute_103-safe) ===============
__device__ __forceinline__ uint32_t smem_u32(const void* p) {
    return (uint32_t)__cvta_generic_to_shared(p);
}

#define LDSM4(d, addr)                                                        \
    asm volatile("ldmatrix.sync.aligned.m8n8.x4.shared.b16 "                  \
                 "{%0,%1,%2,%3}, [%4];"                                       \
                 : "=r"((d)[0]), "=r"((d)[1]), "=r"((d)[2]), "=r"((d)[3])     \
                 : "r"(addr))

#define MMA_BF16(cc, a, bb0, bb1)                                             \
    asm volatile("mma.sync.aligned.m16n8k16.row.col.f32.bf16.bf16.f32 "       \
                 "{%0,%1,%2,%3}, {%4,%5,%6,%7}, {%8,%9}, {%0,%1,%2,%3};"      \
                 : "+f"((cc)[0]), "+f"((cc)[1]), "+f"((cc)[2]), "+f"((cc)[3]) \
                 : "r"((a)[0]), "r"((a)[1]), "r"((a)[2]), "r"((a)[3]),        \
                   "r"(bb0), "r"(bb1))

// split x into bf16 hi + bf16 lo (lo = bf16(x - hi)); pack pairs into u32
__device__ __forceinline__ void split2(float x, float y,
                                       uint32_t& hi, uint32_t& lo) {
    __nv_bfloat16 hx = __float2bfloat16_rn(x);
    __nv_bfloat16 hy = __float2bfloat16_rn(y);
    __nv_bfloat16 lx = __float2bfloat16_rn(x - __bfloat162float(hx));
    __nv_bfloat16 ly = __float2bfloat16_rn(y - __bfloat162float(hy));
    hi = ((uint32_t)__bfloat16_as_ushort(hy) << 16) | __bfloat16_as_ushort(hx);
    lo = ((uint32_t)__bfloat16_as_ushort(ly) << 16) | __bfloat16_as_ushort(lx);
}

// ===================== bf16x3 mma.sync GEMM (validated, unchanged) ========
#define APITCH    40
#define TILE_U16  (128 * APITCH)
#define TILE_B    (TILE_U16 * 2)
#define STAGE_U16 (4 * TILE_U16)
#define GM_SMEM   (2 * STAGE_U16 * 2)

__device__ __forceinline__ void load_chunk(
    const float* __restrict__ A, const float* __restrict__ W,
    int row0, int col0, int K, int k0, int shiftT, int tid,
    float4* Ar, float4* Br)
{
#pragma unroll
    for (int p = 0; p < 4; p++) {
        int e  = p * 256 + tid;
        int r  = e >> 3;
        int c4 = e & 7;
        int grow = row0 + r;
        float4 av;
        if (shiftT) {
            if ((grow % shiftT) == 0) av = make_float4(0.f, 0.f, 0.f, 0.f);
            else av = *(const float4*)&A[(size_t)(grow - 1) * K + k0 + c4 * 4];
        } else {
            av = *(const float4*)&A[(size_t)grow * K + k0 + c4 * 4];
        }
        Ar[p] = av;
        Br[p] = *(const float4*)&W[(size_t)(col0 + r) * K + k0 + c4 * 4];
    }
}

__device__ __forceinline__ void store_chunk(
    uint16_t* st, int tid, const float4* Ar, const float4* Br)
{
#pragma unroll
    for (int p = 0; p < 4; p++) {
        int e  = p * 256 + tid;
        int r  = e >> 3;
        int c4 = e & 7;
        int off = r * APITCH + c4 * 4;
        uint32_t h0, l0, h1, l1;
        split2(Ar[p].x, Ar[p].y, h0, l0);
        split2(Ar[p].z, Ar[p].w, h1, l1);
        *(uint2*)&st[off]                = make_uint2(h0, h1);
        *(uint2*)&st[TILE_U16 + off]     = make_uint2(l0, l1);
        split2(Br[p].x, Br[p].y, h0, l0);
        split2(Br[p].z, Br[p].w, h1, l1);
        *(uint2*)&st[2 * TILE_U16 + off] = make_uint2(h0, h1);
        *(uint2*)&st[3 * TILE_U16 + off] = make_uint2(l0, l1);
    }
}

__global__ __launch_bounds__(256) void gemm_mma(
    const float* __restrict__ A, const float* __restrict__ W,
    const float* __restrict__ b1, const float* __restrict__ b2,
    float* __restrict__ C, int M, int N, int K, int shiftT)
{
    extern __shared__ __align__(16) uint16_t sm16[];

    const int tid  = threadIdx.x;
    const int lane = tid & 31;
    const int wid  = tid >> 5;
    const int wm   = (wid & 1) * 64;
    const int wn   = (wid >> 1) * 32;
    const int row0 = blockIdx.y * 128;
    const int col0 = blockIdx.x * 128;

    float c[4][4][4];
#pragma unroll
    for (int i = 0; i < 4; i++)
#pragma unroll
        for (int j = 0; j < 4; j++)
#pragma unroll
            for (int q = 0; q < 4; q++) c[i][j][q] = 0.0f;

    float4 Ar[4], Br[4];
    const int nch = K / 32;
    load_chunk(A, W, row0, col0, K, 0, shiftT, tid, Ar, Br);

    for (int i = 0; i < nch; i++) {
        const int s = i & 1;
        uint16_t* st = sm16 + s * STAGE_U16;
        store_chunk(st, tid, Ar, Br);
        __syncthreads();
        if (i + 1 < nch)
            load_chunk(A, W, row0, col0, K, (i + 1) * 32, shiftT, tid, Ar, Br);

        const uint32_t base = smem_u32(st);
#pragma unroll
        for (int kh = 0; kh < 2; kh++) {
            uint32_t ah[4][4], al[4][4];
            const int arow = wm + (lane & 15);
            const int akk  = kh * 16 + (lane >> 4) * 8;
#pragma unroll
            for (int mt = 0; mt < 4; mt++) {
                uint32_t boff = (uint32_t)(((arow + mt * 16) * APITCH + akk) * 2);
                LDSM4(ah[mt], base + boff);
                LDSM4(al[mt], base + TILE_B + boff);
            }
            uint32_t bh[2][4], bl[2][4];
            const int brow = wn + (lane & 7) + ((lane >> 4) << 3);
            const int bkk  = kh * 16 + ((lane >> 3) & 1) * 8;
#pragma unroll
            for (int np = 0; np < 2; np++) {
                uint32_t boff = (uint32_t)(((brow + np * 16) * APITCH + bkk) * 2);
                LDSM4(bh[np], base + 2 * TILE_B + boff);
                LDSM4(bl[np], base + 3 * TILE_B + boff);
            }
#pragma unroll
            for (int mt = 0; mt < 4; mt++)
#pragma unroll
                for (int np = 0; np < 2; np++)
#pragma unroll
                    for (int h = 0; h < 2; h++) {
                        int nt = np * 2 + h;
                        MMA_BF16(c[mt][nt], ah[mt], bh[np][h * 2], bh[np][h * 2 + 1]);
                        MMA_BF16(c[mt][nt], ah[mt], bl[np][h * 2], bl[np][h * 2 + 1]);
                        MMA_BF16(c[mt][nt], al[mt], bh[np][h * 2], bh[np][h * 2 + 1]);
                    }
        }
        __syncthreads();
    }

#pragma unroll
    for (int mt = 0; mt < 4; mt++) {
#pragma unroll
        for (int nt = 0; nt < 4; nt++) {
            int m = row0 + wm + mt * 16 + (lane >> 2);
            int n = col0 + wn + nt * 8 + (lane & 3) * 2;
            float bx = b1[n]     + (b2 ? b2[n]     : 0.f);
            float by = b1[n + 1] + (b2 ? b2[n + 1] : 0.f);
            float2 v0 = make_float2(c[mt][nt][0] + bx, c[mt][nt][1] + by);
            float2 v1 = make_float2(c[mt][nt][2] + bx, c[mt][nt][3] + by);
            *(float2*)&C[(size_t)m * N + n]       = v0;
            *(float2*)&C[(size_t)(m + 8) * N + n] = v1;
        }
    }
}

// ===================== tensor-core persistent LSTM scan v3 =================
// Latency-overlapped: pre(t) prefetched before barrier; h staging pipelined
// with mma in 8 k-blocks of 64; all-thread barrier poll; end-of-step arrival.
#define WPITCH 520
#define W_U16  (64 * WPITCH)
#define H_U16  (32 * WPITCH)
#define GPITCH 18
#define SCAN_SMEM ((2 * W_U16 + 2 * H_U16) * 2 + 4 * 32 * GPITCH * 4)

__global__ __launch_bounds__(128) void lstm_scan(
    const float* __restrict__ pre,    // [B,T,4H]
    const float* __restrict__ Whh,    // [4H,H]
    const float* __restrict__ h0,     // initial hidden (row stride h0s) or null
    long long h0s,
    const float* __restrict__ cinit,  // [B,H] initial cell or null
    float* __restrict__ hseq,         // [B,T,H]
    unsigned* __restrict__ bar)       // layer base; group counter at grp*32
{
    extern __shared__ __align__(16) uint16_t sm16[];
    uint16_t* wsh = sm16;
    uint16_t* wsl = wsh + W_U16;
    uint16_t* hsh = wsl + W_U16;
    uint16_t* hsl = hsh + H_U16;
    float*    gsm = (float*)(hsl + H_U16);   // [4][32][GPITCH]

    const int tid  = threadIdx.x;
    const int lane = tid & 31;
    const int wid  = tid >> 5;
    const int grp  = blockIdx.x;
    const int bi0  = grp * 32;
    const int hc0  = blockIdx.y * 16;
    unsigned* mybar = bar + grp * 32;        // 128B apart per group

    // ---- load + split Whh slice: rows n = gate*16 + rr ----
    for (int idx = tid * 4; idx < 64 * 512; idx += 128 * 4) {
        int r    = idx >> 9;
        int k    = idx & 511;
        int gate = r >> 4;
        int rr   = r & 15;
        float4 v = *(const float4*)&Whh[((size_t)gate * HH + hc0 + rr) * HH + k];
        uint32_t h0w, l0w, h1w, l1w;
        split2(v.x, v.y, h0w, l0w);
        split2(v.z, v.w, h1w, l1w);
        *(uint2*)&wsh[r * WPITCH + k] = make_uint2(h0w, h1w);
        *(uint2*)&wsl[r * WPITCH + k] = make_uint2(l0w, l1w);
    }

    const int j   = tid & 15;
    const int bq  = tid >> 4;
    const int col = hc0 + j;
    float c_r[4];
#pragma unroll
    for (int i = 0; i < 4; i++) {
        int b = bi0 + bq * 4 + i;
        c_r[i] = cinit ? cinit[b * HH + col] : 0.0f;
    }

    const uint32_t hshb = smem_u32(hsh);
    const uint32_t hslb = smem_u32(hsl);
    const uint32_t wshb = smem_u32(wsh);
    const uint32_t wslb = smem_u32(wsl);

    // staging map: per block b (64 k-cols), thread handles 4 float4:
    //   p=0..3: row = p*8 + (tid>>4), kc = (tid&15)*4 + b*64
    const int srow = tid >> 4;
    const int scol = (tid & 15) * 4;

    for (int t = 0; t < TT; t++) {
        // ---- prefetch pre(t) (independent of h; overlaps poll+staging) ----
        float pr[4][4];
#pragma unroll
        for (int i = 0; i < 4; i++) {
            int b = bi0 + bq * 4 + i;
            size_t prow = ((size_t)b * TT + t) * (size_t)G4;
#pragma unroll
            for (int g = 0; g < 4; g++)
                pr[i][g] = pre[prow + g * HH + col];
        }

        // ---- wait for all 32 group CTAs to finish step t-1 ----
        if (t > 0) {
            unsigned target = (unsigned)t * 32u;
            unsigned v;
            do {
                asm volatile("ld.acquire.gpu.global.u32 %0, [%1];"
                             : "=r"(v) : "l"(mybar));
            } while (v < target);
        }

        float c[2][2][4];
#pragma unroll
        for (int mt = 0; mt < 2; mt++)
#pragma unroll
            for (int nt = 0; nt < 2; nt++)
#pragma unroll
                for (int q = 0; q < 4; q++) c[mt][nt][q] = 0.0f;

        const int arow = lane & 15;
        const int aoff = (lane >> 4) * 8;
        const int brow = wid * 16 + (lane & 7) + ((lane >> 4) << 3);
        const int boff = ((lane >> 3) & 1) * 8;

        // ---- pipelined staging + mma over 8 k-blocks of 64 ----
        float4 hv[4];
        // ldg block 0
#pragma unroll
        for (int p = 0; p < 4; p++) {
            int r  = p * 8 + srow;
            int kc = scol;
            int b  = bi0 + r;
            if (t == 0) {
                hv[p] = h0 ? *(const float4*)&h0[(size_t)b * h0s + kc]
                           : make_float4(0.f, 0.f, 0.f, 0.f);
            } else {
                hv[p] = *(const float4*)&hseq[((size_t)b * TT + (t - 1)) * HH + kc];
            }
        }

#pragma unroll
        for (int blk = 0; blk < 8; blk++) {
            // split + store block blk
#pragma unroll
            for (int p = 0; p < 4; p++) {
                int r  = p * 8 + srow;
                int kc = scol + blk * 64;
                uint32_t h0w, l0w, h1w, l1w;
                split2(hv[p].x, hv[p].y, h0w, l0w);
                split2(hv[p].z, hv[p].w, h1w, l1w);
                *(uint2*)&hsh[r * WPITCH + kc] = make_uint2(h0w, h1w);
                *(uint2*)&hsl[r * WPITCH + kc] = make_uint2(l0w, l1w);
            }
            __syncthreads();
            // ldg block blk+1 (latency hides under mma below)
            if (blk < 7) {
#pragma unroll
                for (int p = 0; p < 4; p++) {
                    int r  = p * 8 + srow;
                    int kc = scol + (blk + 1) * 64;
                    int b  = bi0 + r;
                    if (t == 0) {
                        hv[p] = h0 ? *(const float4*)&h0[(size_t)b * h0s + kc]
                                   : make_float4(0.f, 0.f, 0.f, 0.f);
                    } else {
                        hv[p] = *(const float4*)&hseq[((size_t)b * TT + (t - 1)) * HH + kc];
                    }
                }
            }
            // mma on block blk (4 k16 chunks)
#pragma unroll
            for (int q = 0; q < 4; q++) {
                int kc = blk * 64 + q * 16;
                uint32_t ah[2][4], al[2][4], bh4[4], bl4[4];
#pragma unroll
                for (int mt = 0; mt < 2; mt++) {
                    uint32_t off = (uint32_t)(((mt * 16 + arow) * WPITCH + kc + aoff) * 2);
                    LDSM4(ah[mt], hshb + off);
                    LDSM4(al[mt], hslb + off);
                }
                {
                    uint32_t off = (uint32_t)((brow * WPITCH + kc + boff) * 2);
                    LDSM4(bh4, wshb + off);
                    LDSM4(bl4, wslb + off);
                }
#pragma unroll
                for (int mt = 0; mt < 2; mt++)
#pragma unroll
                    for (int h = 0; h < 2; h++) {
                        MMA_BF16(c[mt][h], ah[mt], bh4[h * 2], bh4[h * 2 + 1]);
                        MMA_BF16(c[mt][h], ah[mt], bl4[h * 2], bl4[h * 2 + 1]);
                        MMA_BF16(c[mt][h], al[mt], bh4[h * 2], bh4[h * 2 + 1]);
                    }
            }
        }

        // ---- fragments -> smem gate buffer ----
#pragma unroll
        for (int mt = 0; mt < 2; mt++)
#pragma unroll
            for (int nt = 0; nt < 2; nt++) {
                int m = mt * 16 + (lane >> 2);
                int n = nt * 8 + (lane & 3) * 2;
                float* gbase = gsm + (wid * 32 + m) * GPITCH + n;
                *(float2*)gbase                = make_float2(c[mt][nt][0], c[mt][nt][1]);
                *(float2*)(gbase + 8 * GPITCH) = make_float2(c[mt][nt][2], c[mt][nt][3]);
            }
        __syncthreads();

        // ---- gates + state update (pre already in registers) ----
#pragma unroll
        for (int i = 0; i < 4; i++) {
            int bl_ = bq * 4 + i;
            int b   = bi0 + bl_;
            float gi = gsm[(0 * 32 + bl_) * GPITCH + j] + pr[i][0];
            float gf = gsm[(1 * 32 + bl_) * GPITCH + j] + pr[i][1];
            float gg = gsm[(2 * 32 + bl_) * GPITCH + j] + pr[i][2];
            float go = gsm[(3 * 32 + bl_) * GPITCH + j] + pr[i][3];

            float i_ = 1.0f / (1.0f + __expf(-gi));
            float f_ = 1.0f / (1.0f + __expf(-gf));
            float e2 = __expf(2.0f * gg);
            float g_ = (e2 - 1.0f) / (e2 + 1.0f);
            float o_ = 1.0f / (1.0f + __expf(-go));

            float cn = f_ * c_r[i] + i_ * g_;
            c_r[i] = cn;
            float ec = __expf(2.0f * cn);
            float th = (ec - 1.0f) / (ec + 1.0f);
            hseq[((size_t)b * TT + t) * HH + col] = o_ * th;
        }

        // ---- arrive: this CTA finished step t ----
        __syncthreads();
        if (tid == 0)
            asm volatile("red.release.gpu.global.add.u32 [%0], 1;"
                         :: "l"(mybar) : "memory");
    }
}

// ---------------- host driver --------------------------------------------
extern "C" void kernel_launch(void* const* d_in, const int* in_sizes, int n_in,
                              void* d_out, int out_size)
{
    const float* x     = (const float*)d_in[0];
    const float* c_dec = (const float*)d_in[1];
    const float* eWih0 = (const float*)d_in[2];
    const float* eWhh0 = (const float*)d_in[3];
    const float* ebih0 = (const float*)d_in[4];
    const float* ebhh0 = (const float*)d_in[5];
    const float* eWih1 = (const float*)d_in[6];
    const float* eWhh1 = (const float*)d_in[7];
    const float* ebih1 = (const float*)d_in[8];
    const float* ebhh1 = (const float*)d_in[9];
    const float* dWih0 = (const float*)d_in[10];
    const float* dWhh0 = (const float*)d_in[11];
    const float* dbih0 = (const float*)d_in[12];
    const float* dbhh0 = (const float*)d_in[13];
    const float* dWih1 = (const float*)d_in[14];
    const float* dWhh1 = (const float*)d_in[15];
    const float* dbih1 = (const float*)d_in[16];
    const float* dbhh1 = (const float*)d_in[17];
    const float* fcW   = (const float*)d_in[18];
    const float* fcB   = (const float*)d_in[19];
    float*       out   = (float*)d_out;

    static float    *pre = nullptr, *bufX = nullptr, *bufY = nullptr;
    static unsigned *bars = nullptr;
    static bool      inited = false;
    if (!inited) {
        cudaGetSymbolAddress((void**)&pre,  g_pre);
        cudaGetSymbolAddress((void**)&bufX, g_bufX);
        cudaGetSymbolAddress((void**)&bufY, g_bufY);
        cudaGetSymbolAddress((void**)&bars, g_barrier);
        cudaFuncSetAttribute(lstm_scan,
                             cudaFuncAttributeMaxDynamicSharedMemorySize, SCAN_SMEM);
        cudaFuncSetAttribute(gemm_mma,
                             cudaFuncAttributeMaxDynamicSharedMemorySize, GM_SMEM);
        inited = true;
    }

    const int M = BB * TT;                          // 65536
    const dim3 gemmGrid2048(G4 / 128, M / 128);     // (16, 512)
    const dim3 gemmGrid128(II / 128,  M / 128);     // (1, 512)
    const dim3 scanGrid(4, 32);

    zero_bar<<<2, 256>>>(bars, 512);

    // ---- encoder layer 0 ----
    gemm_mma<<<gemmGrid2048, 256, GM_SMEM>>>(x, eWih0, ebih0, ebhh0, pre, M, G4, II, 0);
    lstm_scan<<<scanGrid, 128, SCAN_SMEM>>>(pre, eWhh0, nullptr, 0, nullptr,
                                            bufX, bars + 0 * 128);

    // ---- encoder layer 1 ----
    gemm_mma<<<gemmGrid2048, 256, GM_SMEM>>>(bufX, eWih1, ebih1, ebhh1, pre, M, G4, HH, 0);
    lstm_scan<<<scanGrid, 128, SCAN_SMEM>>>(pre, eWhh1, nullptr, 0, nullptr,
                                            bufY, bars + 1 * 128);

    // ---- decoder layer 0 (shifted input; h0 = enc0 final h; c0 = c_dec[0]) ----
    gemm_mma<<<gemmGrid2048, 256, GM_SMEM>>>(x, dWih0, dbih0, dbhh0, pre, M, G4, II, TT);
    lstm_scan<<<scanGrid, 128, SCAN_SMEM>>>(pre, dWhh0,
                                            bufX + (size_t)(TT - 1) * HH,
                                            (long long)TT * HH,
                                            c_dec, bufX, bars + 2 * 128);

    // ---- decoder layer 1 (h0 = enc1 final h; c0 = c_dec[1]) ----
    gemm_mma<<<gemmGrid2048, 256, GM_SMEM>>>(bufX, dWih1, dbih1, dbhh1, pre, M, G4, HH, 0);
    lstm_scan<<<scanGrid, 128, SCAN_SMEM>>>(pre, dWhh1,
                                            bufY + (size_t)(TT - 1) * HH,
                                            (long long)TT * HH,
                                            c_dec + BB * HH, bufY, bars + 3 * 128);

    // ---- FC head ----
    gemm_mma<<<gemmGrid128, 256, GM_SMEM>>>(bufY, fcW, fcB, nullptr, out, M, II, HH, 0);
}

// round 7
// speedup vs baseline: 2.4085x; 1.0793x over previous
#include <cuda_runtime.h>
#include <cuda_bf16.h>
#include <math.h>
#include <stdint.h>

// Problem constants
#define BB   128      // batch
#define TT   512      // time steps
#define HH   512      // hidden
#define II   128      // input dim
#define G4   2048     // 4*H

// ---------------- scratch (static device memory; no allocations) ----------
__device__ float    g_pre [(size_t)BB * TT * G4];
__device__ float    g_bufX[(size_t)BB * TT * HH];
__device__ float    g_bufY[(size_t)BB * TT * HH];
__device__ unsigned g_barrier[1024];  // 4 layers x 4 groups x 64 u32
                                      // counter at +0, flag at +32 (128B apart)

// ---------------- tiny init kernel ----------------------------------------
__global__ void zero_bar(unsigned* p, int n) {
    int i = blockIdx.x * blockDim.x + threadIdx.x;
    if (i < n) p[i] = 0u;
}

// ======================= mma.sync helpers (compute_103-safe) ===============
__device__ __forceinline__ uint32_t smem_u32(const void* p) {
    return (uint32_t)__cvta_generic_to_shared(p);
}

#define LDSM4(d, addr)                                                        \
    asm volatile("ldmatrix.sync.aligned.m8n8.x4.shared.b16 "                  \
                 "{%0,%1,%2,%3}, [%4];"                                       \
                 : "=r"((d)[0]), "=r"((d)[1]), "=r"((d)[2]), "=r"((d)[3])     \
                 : "r"(addr))

#define MMA_BF16(cc, a, bb0, bb1)                                             \
    asm volatile("mma.sync.aligned.m16n8k16.row.col.f32.bf16.bf16.f32 "       \
                 "{%0,%1,%2,%3}, {%4,%5,%6,%7}, {%8,%9}, {%0,%1,%2,%3};"      \
                 : "+f"((cc)[0]), "+f"((cc)[1]), "+f"((cc)[2]), "+f"((cc)[3]) \
                 : "r"((a)[0]), "r"((a)[1]), "r"((a)[2]), "r"((a)[3]),        \
                   "r"(bb0), "r"(bb1))

// split x into bf16 hi + bf16 lo (lo = bf16(x - hi)); pack pairs into u32
__device__ __forceinline__ void split2(float x, float y,
                                       uint32_t& hi, uint32_t& lo) {
    __nv_bfloat16 hx = __float2bfloat16_rn(x);
    __nv_bfloat16 hy = __float2bfloat16_rn(y);
    __nv_bfloat16 lx = __float2bfloat16_rn(x - __bfloat162float(hx));
    __nv_bfloat16 ly = __float2bfloat16_rn(y - __bfloat162float(hy));
    hi = ((uint32_t)__bfloat16_as_ushort(hy) << 16) | __bfloat16_as_ushort(hx);
    lo = ((uint32_t)__bfloat16_as_ushort(ly) << 16) | __bfloat16_as_ushort(lx);
}

// ===================== bf16x3 mma.sync GEMM v2 =============================
// CTA tile 64x128 (M x N), 8 warps (2 m x 4 n), warp tile 32x32.
// Smaller tile -> ~110 regs -> 2 CTAs/SM so syncs/loads of one CTA hide
// under the other's HMMA. K chunks of 32, double-buffered smem.
#define APITCH   40                    // bf16 elems per smem row (80B)
#define A_U16    (64 * APITCH)         // 2560 u16 per A tile (hi or lo)
#define W_U16G   (128 * APITCH)        // 5120 u16 per W tile (hi or lo)
#define STAGE_U16 (2 * A_U16 + 2 * W_U16G)   // 15360 u16
#define OFF_AH   0
#define OFF_AL   A_U16
#define OFF_WH   (2 * A_U16)
#define OFF_WL   (2 * A_U16 + W_U16G)
#define GM_SMEM  (2 * STAGE_U16 * 2)   // 61440 B

__device__ __forceinline__ void load_chunk(
    const float* __restrict__ A, const float* __restrict__ W,
    int row0, int col0, int K, int k0, int shiftT, int tid,
    float4* Ar, float4* Br)
{
#pragma unroll
    for (int p = 0; p < 2; p++) {      // A: 64x32 = 512 float4
        int e  = p * 256 + tid;
        int r  = e >> 3;
        int c4 = e & 7;
        int grow = row0 + r;
        float4 av;
        if (shiftT) {
            if ((grow % shiftT) == 0) av = make_float4(0.f, 0.f, 0.f, 0.f);
            else av = *(const float4*)&A[(size_t)(grow - 1) * K + k0 + c4 * 4];
        } else {
            av = *(const float4*)&A[(size_t)grow * K + k0 + c4 * 4];
        }
        Ar[p] = av;
    }
#pragma unroll
    for (int p = 0; p < 4; p++) {      // W: 128x32 = 1024 float4
        int e  = p * 256 + tid;
        int r  = e >> 3;
        int c4 = e & 7;
        Br[p] = *(const float4*)&W[(size_t)(col0 + r) * K + k0 + c4 * 4];
    }
}

__device__ __forceinline__ void store_chunk(
    uint16_t* st, int tid, const float4* Ar, const float4* Br)
{
#pragma unroll
    for (int p = 0; p < 2; p++) {
        int e  = p * 256 + tid;
        int r  = e >> 3;
        int c4 = e & 7;
        int off = r * APITCH + c4 * 4;
        uint32_t h0, l0, h1, l1;
        split2(Ar[p].x, Ar[p].y, h0, l0);
        split2(Ar[p].z, Ar[p].w, h1, l1);
        *(uint2*)&st[OFF_AH + off] = make_uint2(h0, h1);
        *(uint2*)&st[OFF_AL + off] = make_uint2(l0, l1);
    }
#pragma unroll
    for (int p = 0; p < 4; p++) {
        int e  = p * 256 + tid;
        int r  = e >> 3;
        int c4 = e & 7;
        int off = r * APITCH + c4 * 4;
        uint32_t h0, l0, h1, l1;
        split2(Br[p].x, Br[p].y, h0, l0);
        split2(Br[p].z, Br[p].w, h1, l1);
        *(uint2*)&st[OFF_WH + off] = make_uint2(h0, h1);
        *(uint2*)&st[OFF_WL + off] = make_uint2(l0, l1);
    }
}

__global__ __launch_bounds__(256, 2) void gemm_mma(
    const float* __restrict__ A, const float* __restrict__ W,
    const float* __restrict__ b1, const float* __restrict__ b2,
    float* __restrict__ C, int M, int N, int K, int shiftT)
{
    extern __shared__ __align__(16) uint16_t sm16[];

    const int tid  = threadIdx.x;
    const int lane = tid & 31;
    const int wid  = tid >> 5;
    const int wm   = (wid & 1) * 32;    // warp m offset (0 or 32)
    const int wn   = (wid >> 1) * 32;   // warp n offset (0,32,64,96)
    const int row0 = blockIdx.y * 64;
    const int col0 = blockIdx.x * 128;

    float c[2][4][4];
#pragma unroll
    for (int i = 0; i < 2; i++)
#pragma unroll
        for (int j = 0; j < 4; j++)
#pragma unroll
            for (int q = 0; q < 4; q++) c[i][j][q] = 0.0f;

    float4 Ar[2], Br[4];
    const int nch = K / 32;
    load_chunk(A, W, row0, col0, K, 0, shiftT, tid, Ar, Br);

    for (int i = 0; i < nch; i++) {
        const int s = i & 1;
        uint16_t* st = sm16 + s * STAGE_U16;
        store_chunk(st, tid, Ar, Br);
        __syncthreads();
        if (i + 1 < nch)
            load_chunk(A, W, row0, col0, K, (i + 1) * 32, shiftT, tid, Ar, Br);

        const uint32_t base = smem_u32(st);
#pragma unroll
        for (int kh = 0; kh < 2; kh++) {
            uint32_t ah[2][4], al[2][4];
            const int arow = wm + (lane & 15);
            const int akk  = kh * 16 + (lane >> 4) * 8;
#pragma unroll
            for (int mt = 0; mt < 2; mt++) {
                uint32_t boff = (uint32_t)(((arow + mt * 16) * APITCH + akk) * 2);
                LDSM4(ah[mt], base + OFF_AH * 2 + boff);
                LDSM4(al[mt], base + OFF_AL * 2 + boff);
            }
            uint32_t bh[2][4], bl[2][4];
            const int brow = wn + (lane & 7) + ((lane >> 4) << 3);
            const int bkk  = kh * 16 + ((lane >> 3) & 1) * 8;
#pragma unroll
            for (int np = 0; np < 2; np++) {
                uint32_t boff = (uint32_t)(((brow + np * 16) * APITCH + bkk) * 2);
                LDSM4(bh[np], base + OFF_WH * 2 + boff);
                LDSM4(bl[np], base + OFF_WL * 2 + boff);
            }
#pragma unroll
            for (int mt = 0; mt < 2; mt++)
#pragma unroll
                for (int np = 0; np < 2; np++)
#pragma unroll
                    for (int h = 0; h < 2; h++) {
                        int nt = np * 2 + h;
                        MMA_BF16(c[mt][nt], ah[mt], bh[np][h * 2], bh[np][h * 2 + 1]);
                        MMA_BF16(c[mt][nt], ah[mt], bl[np][h * 2], bl[np][h * 2 + 1]);
                        MMA_BF16(c[mt][nt], al[mt], bh[np][h * 2], bh[np][h * 2 + 1]);
                    }
        }
        __syncthreads();
    }

#pragma unroll
    for (int mt = 0; mt < 2; mt++) {
#pragma unroll
        for (int nt = 0; nt < 4; nt++) {
            int m = row0 + wm + mt * 16 + (lane >> 2);
            int n = col0 + wn + nt * 8 + (lane & 3) * 2;
            float bx = b1[n]     + (b2 ? b2[n]     : 0.f);
            float by = b1[n + 1] + (b2 ? b2[n + 1] : 0.f);
            float2 v0 = make_float2(c[mt][nt][0] + bx, c[mt][nt][1] + by);
            float2 v1 = make_float2(c[mt][nt][2] + bx, c[mt][nt][3] + by);
            *(float2*)&C[(size_t)m * N + n]       = v0;
            *(float2*)&C[(size_t)(m + 8) * N + n] = v1;
        }
    }
}

// ===================== tensor-core persistent LSTM scan v4 =================
// Same math as v3; barrier redesigned as ticket+flag: arrivals atomically
// bump a counter, the LAST arriver release-stores a flag on a separate line,
// pollers spin on the read-only flag (no RMW/read interference).
#define WPITCH 520
#define W_U16S (64 * WPITCH)
#define H_U16S (32 * WPITCH)
#define GPITCH 18
#define SCAN_SMEM ((2 * W_U16S + 2 * H_U16S) * 2 + 4 * 32 * GPITCH * 4)

__global__ __launch_bounds__(128) void lstm_scan(
    const float* __restrict__ pre,    // [B,T,4H]
    const float* __restrict__ Whh,    // [4H,H]
    const float* __restrict__ h0,     // initial hidden (row stride h0s) or null
    long long h0s,
    const float* __restrict__ cinit,  // [B,H] initial cell or null
    float* __restrict__ hseq,         // [B,T,H]
    unsigned* __restrict__ bar)       // layer base: group g counter at g*64, flag at g*64+32
{
    extern __shared__ __align__(16) uint16_t sm16[];
    uint16_t* wsh = sm16;
    uint16_t* wsl = wsh + W_U16S;
    uint16_t* hsh = wsl + W_U16S;
    uint16_t* hsl = hsh + H_U16S;
    float*    gsm = (float*)(hsl + H_U16S);   // [4][32][GPITCH]

    const int tid  = threadIdx.x;
    const int lane = tid & 31;
    const int wid  = tid >> 5;
    const int grp  = blockIdx.x;
    const int bi0  = grp * 32;
    const int hc0  = blockIdx.y * 16;
    unsigned* ctr  = bar + grp * 64;
    unsigned* flag = ctr + 32;               // separate 128B line

    // ---- load + split Whh slice: rows n = gate*16 + rr ----
    for (int idx = tid * 4; idx < 64 * 512; idx += 128 * 4) {
        int r    = idx >> 9;
        int k    = idx & 511;
        int gate = r >> 4;
        int rr   = r & 15;
        float4 v = *(const float4*)&Whh[((size_t)gate * HH + hc0 + rr) * HH + k];
        uint32_t h0w, l0w, h1w, l1w;
        split2(v.x, v.y, h0w, l0w);
        split2(v.z, v.w, h1w, l1w);
        *(uint2*)&wsh[r * WPITCH + k] = make_uint2(h0w, h1w);
        *(uint2*)&wsl[r * WPITCH + k] = make_uint2(l0w, l1w);
    }

    const int j   = tid & 15;
    const int bq  = tid >> 4;
    const int col = hc0 + j;
    float c_r[4];
#pragma unroll
    for (int i = 0; i < 4; i++) {
        int b = bi0 + bq * 4 + i;
        c_r[i] = cinit ? cinit[b * HH + col] : 0.0f;
    }

    const uint32_t hshb = smem_u32(hsh);
    const uint32_t hslb = smem_u32(hsl);
    const uint32_t wshb = smem_u32(wsh);
    const uint32_t wslb = smem_u32(wsl);

    const int srow = tid >> 4;
    const int scol = (tid & 15) * 4;

    for (int t = 0; t < TT; t++) {
        // ---- prefetch pre(t) (independent of h; overlaps poll) ----
        float pr[4][4];
#pragma unroll
        for (int i = 0; i < 4; i++) {
            int b = bi0 + bq * 4 + i;
            size_t prow = ((size_t)b * TT + t) * (size_t)G4;
#pragma unroll
            for (int g = 0; g < 4; g++)
                pr[i][g] = pre[prow + g * HH + col];
        }

        // ---- wait on read-only flag: step t-1 complete across group ----
        if (t > 0) {
            unsigned v;
            do {
                asm volatile("ld.acquire.gpu.global.u32 %0, [%1];"
                             : "=r"(v) : "l"(flag) : "memory");
            } while (v < (unsigned)t);
        }

        float c[2][2][4];
#pragma unroll
        for (int mt = 0; mt < 2; mt++)
#pragma unroll
            for (int nt = 0; nt < 2; nt++)
#pragma unroll
                for (int q = 0; q < 4; q++) c[mt][nt][q] = 0.0f;

        const int arow = lane & 15;
        const int aoff = (lane >> 4) * 8;
        const int brow = wid * 16 + (lane & 7) + ((lane >> 4) << 3);
        const int boff = ((lane >> 3) & 1) * 8;

        // ---- pipelined staging + mma over 8 k-blocks of 64 ----
        float4 hv[4];
#pragma unroll
        for (int p = 0; p < 4; p++) {
            int r  = p * 8 + srow;
            int kc = scol;
            int b  = bi0 + r;
            if (t == 0) {
                hv[p] = h0 ? *(const float4*)&h0[(size_t)b * h0s + kc]
                           : make_float4(0.f, 0.f, 0.f, 0.f);
            } else {
                hv[p] = *(const float4*)&hseq[((size_t)b * TT + (t - 1)) * HH + kc];
            }
        }

#pragma unroll
        for (int blk = 0; blk < 8; blk++) {
#pragma unroll
            for (int p = 0; p < 4; p++) {
                int r  = p * 8 + srow;
                int kc = scol + blk * 64;
                uint32_t h0w, l0w, h1w, l1w;
                split2(hv[p].x, hv[p].y, h0w, l0w);
                split2(hv[p].z, hv[p].w, h1w, l1w);
                *(uint2*)&hsh[r * WPITCH + kc] = make_uint2(h0w, h1w);
                *(uint2*)&hsl[r * WPITCH + kc] = make_uint2(l0w, l1w);
            }
            __syncthreads();
            if (blk < 7) {
#pragma unroll
                for (int p = 0; p < 4; p++) {
                    int r  = p * 8 + srow;
                    int kc = scol + (blk + 1) * 64;
                    int b  = bi0 + r;
                    if (t == 0) {
                        hv[p] = h0 ? *(const float4*)&h0[(size_t)b * h0s + kc]
                                   : make_float4(0.f, 0.f, 0.f, 0.f);
                    } else {
                        hv[p] = *(const float4*)&hseq[((size_t)b * TT + (t - 1)) * HH + kc];
                    }
                }
            }
#pragma unroll
            for (int q = 0; q < 4; q++) {
                int kc = blk * 64 + q * 16;
                uint32_t ah[2][4], al[2][4], bh4[4], bl4[4];
#pragma unroll
                for (int mt = 0; mt < 2; mt++) {
                    uint32_t off = (uint32_t)(((mt * 16 + arow) * WPITCH + kc + aoff) * 2);
                    LDSM4(ah[mt], hshb + off);
                    LDSM4(al[mt], hslb + off);
                }
                {
                    uint32_t off = (uint32_t)((brow * WPITCH + kc + boff) * 2);
                    LDSM4(bh4, wshb + off);
                    LDSM4(bl4, wslb + off);
                }
#pragma unroll
                for (int mt = 0; mt < 2; mt++)
#pragma unroll
                    for (int h = 0; h < 2; h++) {
                        MMA_BF16(c[mt][h], ah[mt], bh4[h * 2], bh4[h * 2 + 1]);
                        MMA_BF16(c[mt][h], ah[mt], bl4[h * 2], bl4[h * 2 + 1]);
                        MMA_BF16(c[mt][h], al[mt], bh4[h * 2], bh4[h * 2 + 1]);
                    }
            }
        }

        // ---- fragments -> smem gate buffer ----
#pragma unroll
        for (int mt = 0; mt < 2; mt++)
#pragma unroll
            for (int nt = 0; nt < 2; nt++) {
                int m = mt * 16 + (lane >> 2);
                int n = nt * 8 + (lane & 3) * 2;
                float* gbase = gsm + (wid * 32 + m) * GPITCH + n;
                *(float2*)gbase                = make_float2(c[mt][nt][0], c[mt][nt][1]);
                *(float2*)(gbase + 8 * GPITCH) = make_float2(c[mt][nt][2], c[mt][nt][3]);
            }
        __syncthreads();

        // ---- gates + state update (pre already in registers) ----
#pragma unroll
        for (int i = 0; i < 4; i++) {
            int bl_ = bq * 4 + i;
            int b   = bi0 + bl_;
            float gi = gsm[(0 * 32 + bl_) * GPITCH + j] + pr[i][0];
            float gf = gsm[(1 * 32 + bl_) * GPITCH + j] + pr[i][1];
            float gg = gsm[(2 * 32 + bl_) * GPITCH + j] + pr[i][2];
            float go = gsm[(3 * 32 + bl_) * GPITCH + j] + pr[i][3];

            float i_ = 1.0f / (1.0f + __expf(-gi));
            float f_ = 1.0f / (1.0f + __expf(-gf));
            float e2 = __expf(2.0f * gg);
            float g_ = (e2 - 1.0f) / (e2 + 1.0f);
            float o_ = 1.0f / (1.0f + __expf(-go));

            float cn = f_ * c_r[i] + i_ * g_;
            c_r[i] = cn;
            float ec = __expf(2.0f * cn);
            float th = (ec - 1.0f) / (ec + 1.0f);
            hseq[((size_t)b * TT + t) * HH + col] = o_ * th;
        }

        // ---- arrive: counter RMW; last arriver release-stores the flag ----
        __syncthreads();
        if (tid == 0) {
            unsigned old;
            asm volatile("atom.acq_rel.gpu.global.add.u32 %0, [%1], %2;"
                         : "=r"(old) : "l"(ctr), "r"(1u) : "memory");
            if (old == (unsigned)(t * 32 + 31)) {
                asm volatile("st.release.gpu.global.u32 [%0], %1;"
                             :: "l"(flag), "r"((unsigned)(t + 1)) : "memory");
            }
        }
    }
}

// ---------------- host driver --------------------------------------------
extern "C" void kernel_launch(void* const* d_in, const int* in_sizes, int n_in,
                              void* d_out, int out_size)
{
    const float* x     = (const float*)d_in[0];
    const float* c_dec = (const float*)d_in[1];
    const float* eWih0 = (const float*)d_in[2];
    const float* eWhh0 = (const float*)d_in[3];
    const float* ebih0 = (const float*)d_in[4];
    const float* ebhh0 = (const float*)d_in[5];
    const float* eWih1 = (const float*)d_in[6];
    const float* eWhh1 = (const float*)d_in[7];
    const float* ebih1 = (const float*)d_in[8];
    const float* ebhh1 = (const float*)d_in[9];
    const float* dWih0 = (const float*)d_in[10];
    const float* dWhh0 = (const float*)d_in[11];
    const float* dbih0 = (const float*)d_in[12];
    const float* dbhh0 = (const float*)d_in[13];
    const float* dWih1 = (const float*)d_in[14];
    const float* dWhh1 = (const float*)d_in[15];
    const float* dbih1 = (const float*)d_in[16];
    const float* dbhh1 = (const float*)d_in[17];
    const float* fcW   = (const float*)d_in[18];
    const float* fcB   = (const float*)d_in[19];
    float*       out   = (float*)d_out;

    static float    *pre = nullptr, *bufX = nullptr, *bufY = nullptr;
    static unsigned *bars = nullptr;
    static bool      inited = false;
    if (!inited) {
        cudaGetSymbolAddress((void**)&pre,  g_pre);
        cudaGetSymbolAddress((void**)&bufX, g_bufX);
        cudaGetSymbolAddress((void**)&bufY, g_bufY);
        cudaGetSymbolAddress((void**)&bars, g_barrier);
        cudaFuncSetAttribute(lstm_scan,
                             cudaFuncAttributeMaxDynamicSharedMemorySize, SCAN_SMEM);
        cudaFuncSetAttribute(gemm_mma,
                             cudaFuncAttributeMaxDynamicSharedMemorySize, GM_SMEM);
        inited = true;
    }

    const int M = BB * TT;                          // 65536
    const dim3 gemmGrid2048(G4 / 128, M / 64);      // (16, 1024)
    const dim3 gemmGrid128(II / 128,  M / 64);      // (1, 1024)
    const dim3 scanGrid(4, 32);

    zero_bar<<<4, 256>>>(bars, 1024);

    // ---- encoder layer 0 ----
    gemm_mma<<<gemmGrid2048, 256, GM_SMEM>>>(x, eWih0, ebih0, ebhh0, pre, M, G4, II, 0);
    lstm_scan<<<scanGrid, 128, SCAN_SMEM>>>(pre, eWhh0, nullptr, 0, nullptr,
                                            bufX, bars + 0 * 256);

    // ---- encoder layer 1 ----
    gemm_mma<<<gemmGrid2048, 256, GM_SMEM>>>(bufX, eWih1, ebih1, ebhh1, pre, M, G4, HH, 0);
    lstm_scan<<<scanGrid, 128, SCAN_SMEM>>>(pre, eWhh1, nullptr, 0, nullptr,
                                            bufY, bars + 1 * 256);

    // ---- decoder layer 0 (shifted input; h0 = enc0 final h; c0 = c_dec[0]) ----
    gemm_mma<<<gemmGrid2048, 256, GM_SMEM>>>(x, dWih0, dbih0, dbhh0, pre, M, G4, II, TT);
    lstm_scan<<<scanGrid, 128, SCAN_SMEM>>>(pre, dWhh0,
                                            bufX + (size_t)(TT - 1) * HH,
                                            (long long)TT * HH,
                                            c_dec, bufX, bars + 2 * 256);

    // ---- decoder layer 1 (h0 = enc1 final h; c0 = c_dec[1]) ----
    gemm_mma<<<gemmGrid2048, 256, GM_SMEM>>>(bufX, dWih1, dbih1, dbhh1, pre, M, G4, HH, 0);
    lstm_scan<<<scanGrid, 128, SCAN_SMEM>>>(pre, dWhh1,
                                            bufY + (size_t)(TT - 1) * HH,
                                            (long long)TT * HH,
                                            c_dec + BB * HH, bufY, bars + 3 * 256);

    // ---- FC head ----
    gemm_mma<<<gemmGrid128, 256, GM_SMEM>>>(bufY, fcW, fcB, nullptr, out, M, II, HH, 0);
}

// round 8
// speedup vs baseline: 2.7862x; 1.1568x over previous
#include <cuda_runtime.h>
#include <cuda_bf16.h>
#include <math.h>
#include <stdint.h>

// Problem constants
#define BB   128      // batch
#define TT   512      // time steps
#define HH   512      // hidden
#define II   128      // input dim
#define G4   2048     // 4*H

// ---------------- scratch (static device memory; no allocations) ----------
__device__ float    g_pre [(size_t)BB * TT * G4];
__device__ float    g_bufX[(size_t)BB * TT * HH];
__device__ float    g_bufY[(size_t)BB * TT * HH];
__device__ unsigned g_barrier[1024];  // 4 layers x 4 groups x 64 u32
                                      // counter at +0, flag at +32 (128B apart)

// ---------------- tiny init kernel ----------------------------------------
__global__ void zero_bar(unsigned* p, int n) {
    int i = blockIdx.x * blockDim.x + threadIdx.x;
    if (i < n) p[i] = 0u;
}

// ======================= mma.sync helpers (compute_103-safe) ===============
__device__ __forceinline__ uint32_t smem_u32(const void* p) {
    return (uint32_t)__cvta_generic_to_shared(p);
}

#define LDSM4(d, addr)                                                        \
    asm volatile("ldmatrix.sync.aligned.m8n8.x4.shared.b16 "                  \
                 "{%0,%1,%2,%3}, [%4];"                                       \
                 : "=r"((d)[0]), "=r"((d)[1]), "=r"((d)[2]), "=r"((d)[3])     \
                 : "r"(addr))

#define MMA_BF16(cc, a, bb0, bb1)                                             \
    asm volatile("mma.sync.aligned.m16n8k16.row.col.f32.bf16.bf16.f32 "       \
                 "{%0,%1,%2,%3}, {%4,%5,%6,%7}, {%8,%9}, {%0,%1,%2,%3};"      \
                 : "+f"((cc)[0]), "+f"((cc)[1]), "+f"((cc)[2]), "+f"((cc)[3]) \
                 : "r"((a)[0]), "r"((a)[1]), "r"((a)[2]), "r"((a)[3]),        \
                   "r"(bb0), "r"(bb1))

// split x into bf16 hi + bf16 lo (lo = bf16(x - hi)); pack pairs into u32
__device__ __forceinline__ void split2(float x, float y,
                                       uint32_t& hi, uint32_t& lo) {
    __nv_bfloat16 hx = __float2bfloat16_rn(x);
    __nv_bfloat16 hy = __float2bfloat16_rn(y);
    __nv_bfloat16 lx = __float2bfloat16_rn(x - __bfloat162float(hx));
    __nv_bfloat16 ly = __float2bfloat16_rn(y - __bfloat162float(hy));
    hi = ((uint32_t)__bfloat16_as_ushort(hy) << 16) | __bfloat16_as_ushort(hx);
    lo = ((uint32_t)__bfloat16_as_ushort(ly) << 16) | __bfloat16_as_ushort(lx);
}

// ===================== bf16x3 mma.sync GEMM v2 (validated, unchanged) =====
#define APITCH   40
#define A_U16    (64 * APITCH)
#define W_U16G   (128 * APITCH)
#define STAGE_U16 (2 * A_U16 + 2 * W_U16G)
#define OFF_AH   0
#define OFF_AL   A_U16
#define OFF_WH   (2 * A_U16)
#define OFF_WL   (2 * A_U16 + W_U16G)
#define GM_SMEM  (2 * STAGE_U16 * 2)

__device__ __forceinline__ void load_chunk(
    const float* __restrict__ A, const float* __restrict__ W,
    int row0, int col0, int K, int k0, int shiftT, int tid,
    float4* Ar, float4* Br)
{
#pragma unroll
    for (int p = 0; p < 2; p++) {
        int e  = p * 256 + tid;
        int r  = e >> 3;
        int c4 = e & 7;
        int grow = row0 + r;
        float4 av;
        if (shiftT) {
            if ((grow % shiftT) == 0) av = make_float4(0.f, 0.f, 0.f, 0.f);
            else av = *(const float4*)&A[(size_t)(grow - 1) * K + k0 + c4 * 4];
        } else {
            av = *(const float4*)&A[(size_t)grow * K + k0 + c4 * 4];
        }
        Ar[p] = av;
    }
#pragma unroll
    for (int p = 0; p < 4; p++) {
        int e  = p * 256 + tid;
        int r  = e >> 3;
        int c4 = e & 7;
        Br[p] = *(const float4*)&W[(size_t)(col0 + r) * K + k0 + c4 * 4];
    }
}

__device__ __forceinline__ void store_chunk(
    uint16_t* st, int tid, const float4* Ar, const float4* Br)
{
#pragma unroll
    for (int p = 0; p < 2; p++) {
        int e  = p * 256 + tid;
        int r  = e >> 3;
        int c4 = e & 7;
        int off = r * APITCH + c4 * 4;
        uint32_t h0, l0, h1, l1;
        split2(Ar[p].x, Ar[p].y, h0, l0);
        split2(Ar[p].z, Ar[p].w, h1, l1);
        *(uint2*)&st[OFF_AH + off] = make_uint2(h0, h1);
        *(uint2*)&st[OFF_AL + off] = make_uint2(l0, l1);
    }
#pragma unroll
    for (int p = 0; p < 4; p++) {
        int e  = p * 256 + tid;
        int r  = e >> 3;
        int c4 = e & 7;
        int off = r * APITCH + c4 * 4;
        uint32_t h0, l0, h1, l1;
        split2(Br[p].x, Br[p].y, h0, l0);
        split2(Br[p].z, Br[p].w, h1, l1);
        *(uint2*)&st[OFF_WH + off] = make_uint2(h0, h1);
        *(uint2*)&st[OFF_WL + off] = make_uint2(l0, l1);
    }
}

__global__ __launch_bounds__(256, 2) void gemm_mma(
    const float* __restrict__ A, const float* __restrict__ W,
    const float* __restrict__ b1, const float* __restrict__ b2,
    float* __restrict__ C, int M, int N, int K, int shiftT)
{
    extern __shared__ __align__(16) uint16_t sm16[];

    const int tid  = threadIdx.x;
    const int lane = tid & 31;
    const int wid  = tid >> 5;
    const int wm   = (wid & 1) * 32;
    const int wn   = (wid >> 1) * 32;
    const int row0 = blockIdx.y * 64;
    const int col0 = blockIdx.x * 128;

    float c[2][4][4];
#pragma unroll
    for (int i = 0; i < 2; i++)
#pragma unroll
        for (int j = 0; j < 4; j++)
#pragma unroll
            for (int q = 0; q < 4; q++) c[i][j][q] = 0.0f;

    float4 Ar[2], Br[4];
    const int nch = K / 32;
    load_chunk(A, W, row0, col0, K, 0, shiftT, tid, Ar, Br);

    for (int i = 0; i < nch; i++) {
        const int s = i & 1;
        uint16_t* st = sm16 + s * STAGE_U16;
        store_chunk(st, tid, Ar, Br);
        __syncthreads();
        if (i + 1 < nch)
            load_chunk(A, W, row0, col0, K, (i + 1) * 32, shiftT, tid, Ar, Br);

        const uint32_t base = smem_u32(st);
#pragma unroll
        for (int kh = 0; kh < 2; kh++) {
            uint32_t ah[2][4], al[2][4];
            const int arow = wm + (lane & 15);
            const int akk  = kh * 16 + (lane >> 4) * 8;
#pragma unroll
            for (int mt = 0; mt < 2; mt++) {
                uint32_t boff = (uint32_t)(((arow + mt * 16) * APITCH + akk) * 2);
                LDSM4(ah[mt], base + OFF_AH * 2 + boff);
                LDSM4(al[mt], base + OFF_AL * 2 + boff);
            }
            uint32_t bh[2][4], bl[2][4];
            const int brow = wn + (lane & 7) + ((lane >> 4) << 3);
            const int bkk  = kh * 16 + ((lane >> 3) & 1) * 8;
#pragma unroll
            for (int np = 0; np < 2; np++) {
                uint32_t boff = (uint32_t)(((brow + np * 16) * APITCH + bkk) * 2);
                LDSM4(bh[np], base + OFF_WH * 2 + boff);
                LDSM4(bl[np], base + OFF_WL * 2 + boff);
            }
#pragma unroll
            for (int mt = 0; mt < 2; mt++)
#pragma unroll
                for (int np = 0; np < 2; np++)
#pragma unroll
                    for (int h = 0; h < 2; h++) {
                        int nt = np * 2 + h;
                        MMA_BF16(c[mt][nt], ah[mt], bh[np][h * 2], bh[np][h * 2 + 1]);
                        MMA_BF16(c[mt][nt], ah[mt], bl[np][h * 2], bl[np][h * 2 + 1]);
                        MMA_BF16(c[mt][nt], al[mt], bh[np][h * 2], bh[np][h * 2 + 1]);
                    }
        }
        __syncthreads();
    }

#pragma unroll
    for (int mt = 0; mt < 2; mt++) {
#pragma unroll
        for (int nt = 0; nt < 4; nt++) {
            int m = row0 + wm + mt * 16 + (lane >> 2);
            int n = col0 + wn + nt * 8 + (lane & 3) * 2;
            float bx = b1[n]     + (b2 ? b2[n]     : 0.f);
            float by = b1[n + 1] + (b2 ? b2[n + 1] : 0.f);
            float2 v0 = make_float2(c[mt][nt][0] + bx, c[mt][nt][1] + by);
            float2 v1 = make_float2(c[mt][nt][2] + bx, c[mt][nt][3] + by);
            *(float2*)&C[(size_t)m * N + n]       = v0;
            *(float2*)&C[(size_t)(m + 8) * N + n] = v1;
        }
    }
}

// ===================== tensor-core persistent LSTM scan v5 =================
// 256 threads (8 warps), K-split: warps 0-3 = gates 0-3 over K[0,256),
// warps 4-7 = gates 0-3 over K[256,512). 2 warps/SMSP fill HMMA issue gaps.
// Partial sums in two smem gate buffers, summed in the gate update.
#define WPITCH 520
#define W_U16S (64 * WPITCH)
#define H_U16S (32 * WPITCH)
#define GPITCH 18
#define GHALF  (4 * 32 * GPITCH)
#define SCAN_SMEM ((2 * W_U16S + 2 * H_U16S) * 2 + 2 * GHALF * 4)

__global__ __launch_bounds__(256, 1) void lstm_scan(
    const float* __restrict__ pre,    // [B,T,4H]
    const float* __restrict__ Whh,    // [4H,H]
    const float* __restrict__ h0,     // initial hidden (row stride h0s) or null
    long long h0s,
    const float* __restrict__ cinit,  // [B,H] initial cell or null
    float* __restrict__ hseq,         // [B,T,H]
    unsigned* __restrict__ bar)       // group g: counter at g*64, flag at g*64+32
{
    extern __shared__ __align__(16) uint16_t sm16[];
    uint16_t* wsh = sm16;
    uint16_t* wsl = wsh + W_U16S;
    uint16_t* hsh = wsl + W_U16S;
    uint16_t* hsl = hsh + H_U16S;
    float*    gsm = (float*)(hsl + H_U16S);   // [2][4][32][GPITCH]

    const int tid  = threadIdx.x;
    const int lane = tid & 31;
    const int wid  = tid >> 5;
    const int gate = wid & 3;
    const int kbase = (wid >> 2) * 256;       // K half
    const int grp  = blockIdx.x;
    const int bi0  = grp * 32;
    const int hc0  = blockIdx.y * 16;
    unsigned* ctr  = bar + grp * 64;
    unsigned* flag = ctr + 32;

    // ---- load + split Whh slice: rows n = gate*16 + rr ----
    for (int idx = tid * 4; idx < 64 * 512; idx += 256 * 4) {
        int r    = idx >> 9;
        int k    = idx & 511;
        int gt   = r >> 4;
        int rr   = r & 15;
        float4 v = *(const float4*)&Whh[((size_t)gt * HH + hc0 + rr) * HH + k];
        uint32_t h0w, l0w, h1w, l1w;
        split2(v.x, v.y, h0w, l0w);
        split2(v.z, v.w, h1w, l1w);
        *(uint2*)&wsh[r * WPITCH + k] = make_uint2(h0w, h1w);
        *(uint2*)&wsl[r * WPITCH + k] = make_uint2(l0w, l1w);
    }

    // ---- cell state: thread owns (b = bq*2 + i, col j), i<2 ----
    const int j   = tid & 15;
    const int bq  = tid >> 4;           // 0..15
    const int col = hc0 + j;
    float c_r[2];
#pragma unroll
    for (int i = 0; i < 2; i++) {
        int b = bi0 + bq * 2 + i;
        c_r[i] = cinit ? cinit[b * HH + col] : 0.0f;
    }

    const uint32_t hshb = smem_u32(hsh);
    const uint32_t hslb = smem_u32(hsl);
    const uint32_t wshb = smem_u32(wsh);
    const uint32_t wslb = smem_u32(wsl);

    const int arow = lane & 15;
    const int aoff = (lane >> 4) * 8;
    const int brow = gate * 16 + (lane & 7) + ((lane >> 4) << 3);
    const int boff = ((lane >> 3) & 1) * 8;

    for (int t = 0; t < TT; t++) {
        // ---- prefetch pre(t) (h-independent; overlaps poll) ----
        float pr[2][4];
#pragma unroll
        for (int i = 0; i < 2; i++) {
            int b = bi0 + bq * 2 + i;
            size_t prow = ((size_t)b * TT + t) * (size_t)G4;
#pragma unroll
            for (int g = 0; g < 4; g++)
                pr[i][g] = pre[prow + g * HH + col];
        }

        // ---- wait on read-only flag: step t-1 complete across group ----
        if (t > 0) {
            unsigned v;
            do {
                asm volatile("ld.acquire.gpu.global.u32 %0, [%1];"
                             : "=r"(v) : "l"(flag) : "memory");
            } while (v < (unsigned)t);
        }

        // ---- batched h(t-1) load: 16 float4 per thread (MLP=16) ----
        float4 hv[16];
#pragma unroll
        for (int p = 0; p < 16; p++) {
            int e  = p * 256 + tid;      // 0..4095
            int r  = e >> 7;             // 0..31
            int c4 = e & 127;            // float4 within row
            int b  = bi0 + r;
            if (t == 0) {
                hv[p] = h0 ? *(const float4*)&h0[(size_t)b * h0s + c4 * 4]
                           : make_float4(0.f, 0.f, 0.f, 0.f);
            } else {
                hv[p] = *(const float4*)&hseq[((size_t)b * TT + (t - 1)) * HH + c4 * 4];
            }
        }
#pragma unroll
        for (int p = 0; p < 16; p++) {
            int e  = p * 256 + tid;
            int r  = e >> 7;
            int kc = (e & 127) * 4;
            uint32_t h0w, l0w, h1w, l1w;
            split2(hv[p].x, hv[p].y, h0w, l0w);
            split2(hv[p].z, hv[p].w, h1w, l1w);
            *(uint2*)&hsh[r * WPITCH + kc] = make_uint2(h0w, h1w);
            *(uint2*)&hsl[r * WPITCH + kc] = make_uint2(l0w, l1w);
        }
        __syncthreads();

        // ---- mma: this warp's gate over its K half (16 k16 chunks) ----
        float c[2][2][4];
#pragma unroll
        for (int mt = 0; mt < 2; mt++)
#pragma unroll
            for (int nt = 0; nt < 2; nt++)
#pragma unroll
                for (int q = 0; q < 4; q++) c[mt][nt][q] = 0.0f;

#pragma unroll 4
        for (int q = 0; q < 16; q++) {
            int kc = kbase + q * 16;
            uint32_t ah[2][4], al[2][4], bh4[4], bl4[4];
#pragma unroll
            for (int mt = 0; mt < 2; mt++) {
                uint32_t off = (uint32_t)(((mt * 16 + arow) * WPITCH + kc + aoff) * 2);
                LDSM4(ah[mt], hshb + off);
                LDSM4(al[mt], hslb + off);
            }
            {
                uint32_t off = (uint32_t)((brow * WPITCH + kc + boff) * 2);
                LDSM4(bh4, wshb + off);
                LDSM4(bl4, wslb + off);
            }
#pragma unroll
            for (int mt = 0; mt < 2; mt++)
#pragma unroll
                for (int h = 0; h < 2; h++) {
                    MMA_BF16(c[mt][h], ah[mt], bh4[h * 2], bh4[h * 2 + 1]);
                    MMA_BF16(c[mt][h], ah[mt], bl4[h * 2], bl4[h * 2 + 1]);
                    MMA_BF16(c[mt][h], al[mt], bh4[h * 2], bh4[h * 2 + 1]);
                }
        }

        // ---- fragments -> smem gate buffer (own K-half section) ----
        float* ghalf = gsm + (wid >> 2) * GHALF;
#pragma unroll
        for (int mt = 0; mt < 2; mt++)
#pragma unroll
            for (int nt = 0; nt < 2; nt++) {
                int m = mt * 16 + (lane >> 2);
                int n = nt * 8 + (lane & 3) * 2;
                float* gbase = ghalf + (gate * 32 + m) * GPITCH + n;
                *(float2*)gbase                = make_float2(c[mt][nt][0], c[mt][nt][1]);
                *(float2*)(gbase + 8 * GPITCH) = make_float2(c[mt][nt][2], c[mt][nt][3]);
            }
        __syncthreads();

        // ---- gates + state update (sum both K halves; pre in regs) ----
#pragma unroll
        for (int i = 0; i < 2; i++) {
            int bl_ = bq * 2 + i;
            int b   = bi0 + bl_;
            float gi = gsm[(0 * 32 + bl_) * GPITCH + j]
                     + gsm[GHALF + (0 * 32 + bl_) * GPITCH + j] + pr[i][0];
            float gf = gsm[(1 * 32 + bl_) * GPITCH + j]
                     + gsm[GHALF + (1 * 32 + bl_) * GPITCH + j] + pr[i][1];
            float gg = gsm[(2 * 32 + bl_) * GPITCH + j]
                     + gsm[GHALF + (2 * 32 + bl_) * GPITCH + j] + pr[i][2];
            float go = gsm[(3 * 32 + bl_) * GPITCH + j]
                     + gsm[GHALF + (3 * 32 + bl_) * GPITCH + j] + pr[i][3];

            float i_ = 1.0f / (1.0f + __expf(-gi));
            float f_ = 1.0f / (1.0f + __expf(-gf));
            float e2 = __expf(2.0f * gg);
            float g_ = (e2 - 1.0f) / (e2 + 1.0f);
            float o_ = 1.0f / (1.0f + __expf(-go));

            float cn = f_ * c_r[i] + i_ * g_;
            c_r[i] = cn;
            float ec = __expf(2.0f * cn);
            float th = (ec - 1.0f) / (ec + 1.0f);
            hseq[((size_t)b * TT + t) * HH + col] = o_ * th;
        }

        // ---- arrive: counter RMW; last arriver release-stores the flag ----
        __syncthreads();
        if (tid == 0) {
            unsigned old;
            asm volatile("atom.acq_rel.gpu.global.add.u32 %0, [%1], %2;"
                         : "=r"(old) : "l"(ctr), "r"(1u) : "memory");
            if (old == (unsigned)(t * 32 + 31)) {
                asm volatile("st.release.gpu.global.u32 [%0], %1;"
                             :: "l"(flag), "r"((unsigned)(t + 1)) : "memory");
            }
        }
    }
}

// ---------------- host driver --------------------------------------------
extern "C" void kernel_launch(void* const* d_in, const int* in_sizes, int n_in,
                              void* d_out, int out_size)
{
    const float* x     = (const float*)d_in[0];
    const float* c_dec = (const float*)d_in[1];
    const float* eWih0 = (const float*)d_in[2];
    const float* eWhh0 = (const float*)d_in[3];
    const float* ebih0 = (const float*)d_in[4];
    const float* ebhh0 = (const float*)d_in[5];
    const float* eWih1 = (const float*)d_in[6];
    const float* eWhh1 = (const float*)d_in[7];
    const float* ebih1 = (const float*)d_in[8];
    const float* ebhh1 = (const float*)d_in[9];
    const float* dWih0 = (const float*)d_in[10];
    const float* dWhh0 = (const float*)d_in[11];
    const float* dbih0 = (const float*)d_in[12];
    const float* dbhh0 = (const float*)d_in[13];
    const float* dWih1 = (const float*)d_in[14];
    const float* dWhh1 = (const float*)d_in[15];
    const float* dbih1 = (const float*)d_in[16];
    const float* dbhh1 = (const float*)d_in[17];
    const float* fcW   = (const float*)d_in[18];
    const float* fcB   = (const float*)d_in[19];
    float*       out   = (float*)d_out;

    static float    *pre = nullptr, *bufX = nullptr, *bufY = nullptr;
    static unsigned *bars = nullptr;
    static bool      inited = false;
    if (!inited) {
        cudaGetSymbolAddress((void**)&pre,  g_pre);
        cudaGetSymbolAddress((void**)&bufX, g_bufX);
        cudaGetSymbolAddress((void**)&bufY, g_bufY);
        cudaGetSymbolAddress((void**)&bars, g_barrier);
        cudaFuncSetAttribute(lstm_scan,
                             cudaFuncAttributeMaxDynamicSharedMemorySize, SCAN_SMEM);
        cudaFuncSetAttribute(gemm_mma,
                             cudaFuncAttributeMaxDynamicSharedMemorySize, GM_SMEM);
        inited = true;
    }

    const int M = BB * TT;                          // 65536
    const dim3 gemmGrid2048(G4 / 128, M / 64);      // (16, 1024)
    const dim3 gemmGrid128(II / 128,  M / 64);      // (1, 1024)
    const dim3 scanGrid(4, 32);

    zero_bar<<<4, 256>>>(bars, 1024);

    // ---- encoder layer 0 ----
    gemm_mma<<<gemmGrid2048, 256, GM_SMEM>>>(x, eWih0, ebih0, ebhh0, pre, M, G4, II, 0);
    lstm_scan<<<scanGrid, 256, SCAN_SMEM>>>(pre, eWhh0, nullptr, 0, nullptr,
                                            bufX, bars + 0 * 256);

    // ---- encoder layer 1 ----
    gemm_mma<<<gemmGrid2048, 256, GM_SMEM>>>(bufX, eWih1, ebih1, ebhh1, pre, M, G4, HH, 0);
    lstm_scan<<<scanGrid, 256, SCAN_SMEM>>>(pre, eWhh1, nullptr, 0, nullptr,
                                            bufY, bars + 1 * 256);

    // ---- decoder layer 0 (shifted input; h0 = enc0 final h; c0 = c_dec[0]) ----
    gemm_mma<<<gemmGrid2048, 256, GM_SMEM>>>(x, dWih0, dbih0, dbhh0, pre, M, G4, II, TT);
    lstm_scan<<<scanGrid, 256, SCAN_SMEM>>>(pre, dWhh0,
                                            bufX + (size_t)(TT - 1) * HH,
                                            (long long)TT * HH,
                                            c_dec, bufX, bars + 2 * 256);

    // ---- decoder layer 1 (h0 = enc1 final h; c0 = c_dec[1]) ----
    gemm_mma<<<gemmGrid2048, 256, GM_SMEM>>>(bufX, dWih1, dbih1, dbhh1, pre, M, G4, HH, 0);
    lstm_scan<<<scanGrid, 256, SCAN_SMEM>>>(pre, dWhh1,
                                            bufY + (size_t)(TT - 1) * HH,
                                            (long long)TT * HH,
                                            c_dec + BB * HH, bufY, bars + 3 * 256);

    // ---- FC head ----
    gemm_mma<<<gemmGrid128, 256, GM_SMEM>>>(bufY, fcW, fcB, nullptr, out, M, II, HH, 0);
}

// round 9
// speedup vs baseline: 3.0378x; 1.0903x over previous
#include <cuda_runtime.h>
#include <cuda_bf16.h>
#include <math.h>
#include <stdint.h>

// Problem constants
#define BB   128      // batch
#define TT   512      // time steps
#define HH   512      // hidden
#define II   128      // input dim
#define G4   2048     // 4*H

// ---------------- scratch (static device memory; no allocations) ----------
__device__ float g_pre [(size_t)BB * TT * G4];
__device__ __align__(16) __nv_bfloat16 g_bufXh[(size_t)BB * TT * HH];
__device__ __align__(16) __nv_bfloat16 g_bufXl[(size_t)BB * TT * HH];
__device__ __align__(16) __nv_bfloat16 g_bufYh[(size_t)BB * TT * HH];
__device__ __align__(16) __nv_bfloat16 g_bufYl[(size_t)BB * TT * HH];
// weight planes: [enc0 2048x128][enc1 2048x512][dec0 2048x128][dec1 2048x512][fc 128x512]
#define WO0 0
#define WO1 (WO0 + 2048 * 128)
#define WO2 (WO1 + 2048 * 512)
#define WO3 (WO2 + 2048 * 128)
#define WO4 (WO3 + 2048 * 512)
#define WTOT (WO4 + 128 * 512)
__device__ __align__(16) __nv_bfloat16 g_wh[WTOT];
__device__ __align__(16) __nv_bfloat16 g_wl[WTOT];
__device__ unsigned g_barrier[1024];  // 4 layers x 4 groups: counter g*64, flag g*64+32

// ---------------- tiny init kernels ----------------------------------------
__global__ void zero_bar(unsigned* p, int n) {
    int i = blockIdx.x * blockDim.x + threadIdx.x;
    if (i < n) p[i] = 0u;
}
__global__ void split_planes(const float* __restrict__ in,
                             __nv_bfloat16* __restrict__ oh,
                             __nv_bfloat16* __restrict__ ol, int n) {
    int i = blockIdx.x * blockDim.x + threadIdx.x;
    if (i < n) {
        float v = in[i];
        __nv_bfloat16 h = __float2bfloat16_rn(v);
        oh[i] = h;
        ol[i] = __float2bfloat16_rn(v - __bfloat162float(h));
    }
}

// ======================= mma.sync helpers (compute_103-safe) ===============
__device__ __forceinline__ uint32_t smem_u32(const void* p) {
    return (uint32_t)__cvta_generic_to_shared(p);
}

#define LDSM4(d, addr)                                                        \
    asm volatile("ldmatrix.sync.aligned.m8n8.x4.shared.b16 "                  \
                 "{%0,%1,%2,%3}, [%4];"                                       \
                 : "=r"((d)[0]), "=r"((d)[1]), "=r"((d)[2]), "=r"((d)[3])     \
                 : "r"(addr))

#define MMA_BF16(cc, a, bb0, bb1)                                             \
    asm volatile("mma.sync.aligned.m16n8k16.row.col.f32.bf16.bf16.f32 "       \
                 "{%0,%1,%2,%3}, {%4,%5,%6,%7}, {%8,%9}, {%0,%1,%2,%3};"      \
                 : "+f"((cc)[0]), "+f"((cc)[1]), "+f"((cc)[2]), "+f"((cc)[3]) \
                 : "r"((a)[0]), "r"((a)[1]), "r"((a)[2]), "r"((a)[3]),        \
                   "r"(bb0), "r"(bb1))

__device__ __forceinline__ void split2(float x, float y,
                                       uint32_t& hi, uint32_t& lo) {
    __nv_bfloat16 hx = __float2bfloat16_rn(x);
    __nv_bfloat16 hy = __float2bfloat16_rn(y);
    __nv_bfloat16 lx = __float2bfloat16_rn(x - __bfloat162float(hx));
    __nv_bfloat16 ly = __float2bfloat16_rn(y - __bfloat162float(hy));
    hi = ((uint32_t)__bfloat16_as_ushort(hy) << 16) | __bfloat16_as_ushort(hx);
    lo = ((uint32_t)__bfloat16_as_ushort(ly) << 16) | __bfloat16_as_ushort(lx);
}

// ===================== bf16x3 mma.sync GEMM v3 =============================
// CTA 64x128, 8 warps, 2 CTAs/SM. W always from pre-split planes; A either
// fp32 (+shiftT teacher forcing, x layers) or pre-split planes (h layers).
#define APITCH   40
#define A_U16    (64 * APITCH)
#define W_U16G   (128 * APITCH)
#define STAGE_U16 (2 * A_U16 + 2 * W_U16G)
#define OFF_AH   0
#define OFF_AL   A_U16
#define OFF_WH   (2 * A_U16)
#define OFF_WL   (2 * A_U16 + W_U16G)
#define GM_SMEM  (2 * STAGE_U16 * 2)

template<bool PA>
__global__ __launch_bounds__(256, 2) void gemm_mma(
    const float* __restrict__ A,                  // fp32 A (PA=false)
    const __nv_bfloat16* __restrict__ Ahp,        // plane A (PA=true)
    const __nv_bfloat16* __restrict__ Alp,
    const __nv_bfloat16* __restrict__ Whp,        // plane W
    const __nv_bfloat16* __restrict__ Wlp,
    const float* __restrict__ b1, const float* __restrict__ b2,
    float* __restrict__ C, int M, int N, int K, int shiftT)
{
    extern __shared__ __align__(16) uint16_t sm16[];

    const int tid  = threadIdx.x;
    const int lane = tid & 31;
    const int wid  = tid >> 5;
    const int wm   = (wid & 1) * 32;
    const int wn   = (wid >> 1) * 32;
    const int row0 = blockIdx.y * 64;
    const int col0 = blockIdx.x * 128;

    float c[2][4][4];
#pragma unroll
    for (int i = 0; i < 2; i++)
#pragma unroll
        for (int j = 0; j < 4; j++)
#pragma unroll
            for (int q = 0; q < 4; q++) c[i][j][q] = 0.0f;

    // per-chunk staging registers
    float4 Af[2];
    uint4  Ahu, Alu;
    uint4  Whu[2], Wlu[2];

    const int nch = K / 32;

    // thread->tile mapping
    const int ar  = tid >> 2;           // plane A: row 0..63
    const int ac8 = (tid & 3) * 8;      // plane A: k offset

    auto load_chunk = [&](int k0) {
        if (PA) {
            Ahu = *(const uint4*)&Ahp[(size_t)(row0 + ar) * K + k0 + ac8];
            Alu = *(const uint4*)&Alp[(size_t)(row0 + ar) * K + k0 + ac8];
        } else {
#pragma unroll
            for (int p = 0; p < 2; p++) {
                int e  = p * 256 + tid;
                int r  = e >> 3;
                int c4 = e & 7;
                int grow = row0 + r;
                float4 av;
                if (shiftT) {
                    if ((grow % shiftT) == 0) av = make_float4(0.f, 0.f, 0.f, 0.f);
                    else av = *(const float4*)&A[(size_t)(grow - 1) * K + k0 + c4 * 4];
                } else {
                    av = *(const float4*)&A[(size_t)grow * K + k0 + c4 * 4];
                }
                Af[p] = av;
            }
        }
#pragma unroll
        for (int p = 0; p < 2; p++) {
            int e  = p * 256 + tid;      // 0..511
            int r  = e >> 2;             // 0..127
            int c8 = (e & 3) * 8;
            Whu[p] = *(const uint4*)&Whp[(size_t)(col0 + r) * K + k0 + c8];
            Wlu[p] = *(const uint4*)&Wlp[(size_t)(col0 + r) * K + k0 + c8];
        }
    };

    auto store_chunk = [&](uint16_t* st) {
        if (PA) {
            *(uint4*)&st[OFF_AH + ar * APITCH + ac8] = Ahu;
            *(uint4*)&st[OFF_AL + ar * APITCH + ac8] = Alu;
        } else {
#pragma unroll
            for (int p = 0; p < 2; p++) {
                int e  = p * 256 + tid;
                int r  = e >> 3;
                int c4 = e & 7;
                int off = r * APITCH + c4 * 4;
                uint32_t h0, l0, h1, l1;
                split2(Af[p].x, Af[p].y, h0, l0);
                split2(Af[p].z, Af[p].w, h1, l1);
                *(uint2*)&st[OFF_AH + off] = make_uint2(h0, h1);
                *(uint2*)&st[OFF_AL + off] = make_uint2(l0, l1);
            }
        }
#pragma unroll
        for (int p = 0; p < 2; p++) {
            int e  = p * 256 + tid;
            int r  = e >> 2;
            int c8 = (e & 3) * 8;
            *(uint4*)&st[OFF_WH + r * APITCH + c8] = Whu[p];
            *(uint4*)&st[OFF_WL + r * APITCH + c8] = Wlu[p];
        }
    };

    load_chunk(0);

    for (int i = 0; i < nch; i++) {
        const int s = i & 1;
        uint16_t* st = sm16 + s * STAGE_U16;
        store_chunk(st);
        __syncthreads();
        if (i + 1 < nch)
            load_chunk((i + 1) * 32);

        const uint32_t base = smem_u32(st);
#pragma unroll
        for (int kh = 0; kh < 2; kh++) {
            uint32_t ah[2][4], al[2][4];
            const int arow = wm + (lane & 15);
            const int akk  = kh * 16 + (lane >> 4) * 8;
#pragma unroll
            for (int mt = 0; mt < 2; mt++) {
                uint32_t boff = (uint32_t)(((arow + mt * 16) * APITCH + akk) * 2);
                LDSM4(ah[mt], base + OFF_AH * 2 + boff);
                LDSM4(al[mt], base + OFF_AL * 2 + boff);
            }
            uint32_t bh[2][4], bl[2][4];
            const int brow = wn + (lane & 7) + ((lane >> 4) << 3);
            const int bkk  = kh * 16 + ((lane >> 3) & 1) * 8;
#pragma unroll
            for (int np = 0; np < 2; np++) {
                uint32_t boff = (uint32_t)(((brow + np * 16) * APITCH + bkk) * 2);
                LDSM4(bh[np], base + OFF_WH * 2 + boff);
                LDSM4(bl[np], base + OFF_WL * 2 + boff);
            }
#pragma unroll
            for (int mt = 0; mt < 2; mt++)
#pragma unroll
                for (int np = 0; np < 2; np++)
#pragma unroll
                    for (int h = 0; h < 2; h++) {
                        int nt = np * 2 + h;
                        MMA_BF16(c[mt][nt], ah[mt], bh[np][h * 2], bh[np][h * 2 + 1]);
                        MMA_BF16(c[mt][nt], ah[mt], bl[np][h * 2], bl[np][h * 2 + 1]);
                        MMA_BF16(c[mt][nt], al[mt], bh[np][h * 2], bh[np][h * 2 + 1]);
                    }
        }
        __syncthreads();
    }

#pragma unroll
    for (int mt = 0; mt < 2; mt++) {
#pragma unroll
        for (int nt = 0; nt < 4; nt++) {
            int m = row0 + wm + mt * 16 + (lane >> 2);
            int n = col0 + wn + nt * 8 + (lane & 3) * 2;
            float bx = b1[n]     + (b2 ? b2[n]     : 0.f);
            float by = b1[n + 1] + (b2 ? b2[n + 1] : 0.f);
            float2 v0 = make_float2(c[mt][nt][0] + bx, c[mt][nt][1] + by);
            float2 v1 = make_float2(c[mt][nt][2] + bx, c[mt][nt][3] + by);
            *(float2*)&C[(size_t)m * N + n]       = v0;
            *(float2*)&C[(size_t)(m + 8) * N + n] = v1;
        }
    }
}

// ===================== tensor-core persistent LSTM scan v6 =================
// 256 threads, K-split warps (as v5). h stored as pre-split bf16 planes:
// staging is pure uint4 copy (no ALU); epilogue splits h once at write.
#define WPITCH 520
#define W_U16S (64 * WPITCH)
#define H_U16S (32 * WPITCH)
#define GPITCH 18
#define GHALF  (4 * 32 * GPITCH)
#define SCAN_SMEM ((2 * W_U16S + 2 * H_U16S) * 2 + 2 * GHALF * 4)

__global__ __launch_bounds__(256, 1) void lstm_scan(
    const float* __restrict__ pre,            // [B,T,4H]
    const float* __restrict__ Whh,            // [4H,H] fp32 (split once here)
    const __nv_bfloat16* __restrict__ h0h,    // initial hidden planes or null
    const __nv_bfloat16* __restrict__ h0l,
    long long h0s,
    const float* __restrict__ cinit,          // [B,H] initial cell or null
    __nv_bfloat16* __restrict__ ph,           // output hidden planes [B,T,H]
    __nv_bfloat16* __restrict__ pl,
    unsigned* __restrict__ bar)
{
    extern __shared__ __align__(16) uint16_t sm16[];
    uint16_t* wsh = sm16;
    uint16_t* wsl = wsh + W_U16S;
    uint16_t* hsh = wsl + W_U16S;
    uint16_t* hsl = hsh + H_U16S;
    float*    gsm = (float*)(hsl + H_U16S);   // [2][4][32][GPITCH]

    const int tid  = threadIdx.x;
    const int lane = tid & 31;
    const int wid  = tid >> 5;
    const int gate = wid & 3;
    const int kbase = (wid >> 2) * 256;
    const int grp  = blockIdx.x;
    const int bi0  = grp * 32;
    const int hc0  = blockIdx.y * 16;
    unsigned* ctr  = bar + grp * 64;
    unsigned* flag = ctr + 32;

    // ---- load + split Whh slice once ----
    for (int idx = tid * 4; idx < 64 * 512; idx += 256 * 4) {
        int r  = idx >> 9;
        int k  = idx & 511;
        int gt = r >> 4;
        int rr = r & 15;
        float4 v = *(const float4*)&Whh[((size_t)gt * HH + hc0 + rr) * HH + k];
        uint32_t h0w, l0w, h1w, l1w;
        split2(v.x, v.y, h0w, l0w);
        split2(v.z, v.w, h1w, l1w);
        *(uint2*)&wsh[r * WPITCH + k] = make_uint2(h0w, h1w);
        *(uint2*)&wsl[r * WPITCH + k] = make_uint2(l0w, l1w);
    }

    const int j   = tid & 15;
    const int bq  = tid >> 4;
    const int col = hc0 + j;
    float c_r[2];
#pragma unroll
    for (int i = 0; i < 2; i++) {
        int b = bi0 + bq * 2 + i;
        c_r[i] = cinit ? cinit[b * HH + col] : 0.0f;
    }

    const uint32_t hshb = smem_u32(hsh);
    const uint32_t hslb = smem_u32(hsl);
    const uint32_t wshb = smem_u32(wsh);
    const uint32_t wslb = smem_u32(wsl);

    const int arow = lane & 15;
    const int aoff = (lane >> 4) * 8;
    const int brow = gate * 16 + (lane & 7) + ((lane >> 4) << 3);
    const int boff = ((lane >> 3) & 1) * 8;

    for (int t = 0; t < TT; t++) {
        // ---- prefetch pre(t) (h-independent; overlaps poll) ----
        float pr[2][4];
#pragma unroll
        for (int i = 0; i < 2; i++) {
            int b = bi0 + bq * 2 + i;
            size_t prow = ((size_t)b * TT + t) * (size_t)G4;
#pragma unroll
            for (int g = 0; g < 4; g++)
                pr[i][g] = pre[prow + g * HH + col];
        }

        // ---- wait on read-only flag ----
        if (t > 0) {
            unsigned v;
            do {
                asm volatile("ld.acquire.gpu.global.u32 %0, [%1];"
                             : "=r"(v) : "l"(flag) : "memory");
            } while (v < (unsigned)t);
        }

        // ---- stage h(t-1): straight uint4 copies from planes ----
        uint4 vh[8], vl[8];
#pragma unroll
        for (int p = 0; p < 8; p++) {
            int e  = p * 256 + tid;          // 0..2047
            int r  = e >> 6;                 // 0..31
            int c8 = (e & 63) * 8;           // k offset (x8 bf16)
            int b  = bi0 + r;
            if (t == 0) {
                if (h0h) {
                    vh[p] = *(const uint4*)&h0h[(size_t)b * h0s + c8];
                    vl[p] = *(const uint4*)&h0l[(size_t)b * h0s + c8];
                } else {
                    vh[p] = make_uint4(0, 0, 0, 0);
                    vl[p] = make_uint4(0, 0, 0, 0);
                }
            } else {
                size_t off = ((size_t)b * TT + (t - 1)) * HH + c8;
                vh[p] = *(const uint4*)&ph[off];
                vl[p] = *(const uint4*)&pl[off];
            }
        }
#pragma unroll
        for (int p = 0; p < 8; p++) {
            int e  = p * 256 + tid;
            int r  = e >> 6;
            int c8 = (e & 63) * 8;
            *(uint4*)&hsh[r * WPITCH + c8] = vh[p];
            *(uint4*)&hsl[r * WPITCH + c8] = vl[p];
        }
        __syncthreads();

        // ---- mma: this warp's gate over its K half ----
        float c[2][2][4];
#pragma unroll
        for (int mt = 0; mt < 2; mt++)
#pragma unroll
            for (int nt = 0; nt < 2; nt++)
#pragma unroll
                for (int q = 0; q < 4; q++) c[mt][nt][q] = 0.0f;

#pragma unroll 4
        for (int q = 0; q < 16; q++) {
            int kc = kbase + q * 16;
            uint32_t ah[2][4], al[2][4], bh4[4], bl4[4];
#pragma unroll
            for (int mt = 0; mt < 2; mt++) {
                uint32_t off = (uint32_t)(((mt * 16 + arow) * WPITCH + kc + aoff) * 2);
                LDSM4(ah[mt], hshb + off);
                LDSM4(al[mt], hslb + off);
            }
            {
                uint32_t off = (uint32_t)((brow * WPITCH + kc + boff) * 2);
                LDSM4(bh4, wshb + off);
                LDSM4(bl4, wslb + off);
            }
#pragma unroll
            for (int mt = 0; mt < 2; mt++)
#pragma unroll
                for (int h = 0; h < 2; h++) {
                    MMA_BF16(c[mt][h], ah[mt], bh4[h * 2], bh4[h * 2 + 1]);
                    MMA_BF16(c[mt][h], ah[mt], bl4[h * 2], bl4[h * 2 + 1]);
                    MMA_BF16(c[mt][h], al[mt], bh4[h * 2], bh4[h * 2 + 1]);
                }
        }

        // ---- fragments -> smem gate buffer (own K-half section) ----
        float* ghalf = gsm + (wid >> 2) * GHALF;
#pragma unroll
        for (int mt = 0; mt < 2; mt++)
#pragma unroll
            for (int nt = 0; nt < 2; nt++) {
                int m = mt * 16 + (lane >> 2);
                int n = nt * 8 + (lane & 3) * 2;
                float* gbase = ghalf + (gate * 32 + m) * GPITCH + n;
                *(float2*)gbase                = make_float2(c[mt][nt][0], c[mt][nt][1]);
                *(float2*)(gbase + 8 * GPITCH) = make_float2(c[mt][nt][2], c[mt][nt][3]);
            }
        __syncthreads();

        // ---- gates + state update; write h as bf16 hi/lo planes ----
#pragma unroll
        for (int i = 0; i < 2; i++) {
            int bl_ = bq * 2 + i;
            int b   = bi0 + bl_;
            float gi = gsm[(0 * 32 + bl_) * GPITCH + j]
                     + gsm[GHALF + (0 * 32 + bl_) * GPITCH + j] + pr[i][0];
            float gf = gsm[(1 * 32 + bl_) * GPITCH + j]
                     + gsm[GHALF + (1 * 32 + bl_) * GPITCH + j] + pr[i][1];
            float gg = gsm[(2 * 32 + bl_) * GPITCH + j]
                     + gsm[GHALF + (2 * 32 + bl_) * GPITCH + j] + pr[i][2];
            float go = gsm[(3 * 32 + bl_) * GPITCH + j]
                     + gsm[GHALF + (3 * 32 + bl_) * GPITCH + j] + pr[i][3];

            float i_ = 1.0f / (1.0f + __expf(-gi));
            float f_ = 1.0f / (1.0f + __expf(-gf));
            float e2 = __expf(2.0f * gg);
            float g_ = (e2 - 1.0f) / (e2 + 1.0f);
            float o_ = 1.0f / (1.0f + __expf(-go));

            float cn = f_ * c_r[i] + i_ * g_;
            c_r[i] = cn;
            float ec = __expf(2.0f * cn);
            float th = (ec - 1.0f) / (ec + 1.0f);
            float hv = o_ * th;

            __nv_bfloat16 hh = __float2bfloat16_rn(hv);
            __nv_bfloat16 hl = __float2bfloat16_rn(hv - __bfloat162float(hh));
            size_t off = ((size_t)b * TT + t) * HH + col;
            ph[off] = hh;
            pl[off] = hl;
        }

        // ---- arrive ----
        __syncthreads();
        if (tid == 0) {
            unsigned old;
            asm volatile("atom.acq_rel.gpu.global.add.u32 %0, [%1], %2;"
                         : "=r"(old) : "l"(ctr), "r"(1u) : "memory");
            if (old == (unsigned)(t * 32 + 31)) {
                asm volatile("st.release.gpu.global.u32 [%0], %1;"
                             :: "l"(flag), "r"((unsigned)(t + 1)) : "memory");
            }
        }
    }
}

// ---------------- host driver --------------------------------------------
extern "C" void kernel_launch(void* const* d_in, const int* in_sizes, int n_in,
                              void* d_out, int out_size)
{
    const float* x     = (const float*)d_in[0];
    const float* c_dec = (const float*)d_in[1];
    const float* eWih0 = (const float*)d_in[2];
    const float* eWhh0 = (const float*)d_in[3];
    const float* ebih0 = (const float*)d_in[4];
    const float* ebhh0 = (const float*)d_in[5];
    const float* eWih1 = (const float*)d_in[6];
    const float* eWhh1 = (const float*)d_in[7];
    const float* ebih1 = (const float*)d_in[8];
    const float* ebhh1 = (const float*)d_in[9];
    const float* dWih0 = (const float*)d_in[10];
    const float* dWhh0 = (const float*)d_in[11];
    const float* dbih0 = (const float*)d_in[12];
    const float* dbhh0 = (const float*)d_in[13];
    const float* dWih1 = (const float*)d_in[14];
    const float* dWhh1 = (const float*)d_in[15];
    const float* dbih1 = (const float*)d_in[16];
    const float* dbhh1 = (const float*)d_in[17];
    const float* fcW   = (const float*)d_in[18];
    const float* fcB   = (const float*)d_in[19];
    float*       out   = (float*)d_out;

    static float *pre = nullptr;
    static __nv_bfloat16 *bXh, *bXl, *bYh, *bYl, *wh, *wl;
    static unsigned *bars = nullptr;
    static bool inited = false;
    if (!inited) {
        cudaGetSymbolAddress((void**)&pre,  g_pre);
        cudaGetSymbolAddress((void**)&bXh,  g_bufXh);
        cudaGetSymbolAddress((void**)&bXl,  g_bufXl);
        cudaGetSymbolAddress((void**)&bYh,  g_bufYh);
        cudaGetSymbolAddress((void**)&bYl,  g_bufYl);
        cudaGetSymbolAddress((void**)&wh,   g_wh);
        cudaGetSymbolAddress((void**)&wl,   g_wl);
        cudaGetSymbolAddress((void**)&bars, g_barrier);
        cudaFuncSetAttribute(lstm_scan,
                             cudaFuncAttributeMaxDynamicSharedMemorySize, SCAN_SMEM);
        cudaFuncSetAttribute(gemm_mma<false>,
                             cudaFuncAttributeMaxDynamicSharedMemorySize, GM_SMEM);
        cudaFuncSetAttribute(gemm_mma<true>,
                             cudaFuncAttributeMaxDynamicSharedMemorySize, GM_SMEM);
        inited = true;
    }

    const int M = BB * TT;
    const dim3 gemmGrid2048(G4 / 128, M / 64);
    const dim3 gemmGrid128(II / 128,  M / 64);
    const dim3 scanGrid(4, 32);
    const long long seqStride = (long long)TT * HH;

    zero_bar<<<4, 256>>>(bars, 1024);

    // ---- pre-split all feed-forward weights into bf16 planes ----
    split_planes<<<(2048 * 128 + 255) / 256, 256>>>(eWih0, wh + WO0, wl + WO0, 2048 * 128);
    split_planes<<<(2048 * 512 + 255) / 256, 256>>>(eWih1, wh + WO1, wl + WO1, 2048 * 512);
    split_planes<<<(2048 * 128 + 255) / 256, 256>>>(dWih0, wh + WO2, wl + WO2, 2048 * 128);
    split_planes<<<(2048 * 512 + 255) / 256, 256>>>(dWih1, wh + WO3, wl + WO3, 2048 * 512);
    split_planes<<<(128 * 512 + 255) / 256, 256>>>(fcW,   wh + WO4, wl + WO4, 128 * 512);

    // ---- encoder layer 0 (A = x fp32) ----
    gemm_mma<false><<<gemmGrid2048, 256, GM_SMEM>>>(
        x, nullptr, nullptr, wh + WO0, wl + WO0, ebih0, ebhh0, pre, M, G4, II, 0);
    lstm_scan<<<scanGrid, 256, SCAN_SMEM>>>(pre, eWhh0, nullptr, nullptr, 0, nullptr,
                                            bXh, bXl, bars + 0 * 256);

    // ---- encoder layer 1 (A = bufX planes) ----
    gemm_mma<true><<<gemmGrid2048, 256, GM_SMEM>>>(
        nullptr, bXh, bXl, wh + WO1, wl + WO1, ebih1, ebhh1, pre, M, G4, HH, 0);
    lstm_scan<<<scanGrid, 256, SCAN_SMEM>>>(pre, eWhh1, nullptr, nullptr, 0, nullptr,
                                            bYh, bYl, bars + 1 * 256);

    // ---- decoder layer 0 (A = x fp32 shifted; h0 = enc0 final row) ----
    gemm_mma<false><<<gemmGrid2048, 256, GM_SMEM>>>(
        x, nullptr, nullptr, wh + WO2, wl + WO2, dbih0, dbhh0, pre, M, G4, II, TT);
    lstm_scan<<<scanGrid, 256, SCAN_SMEM>>>(pre, dWhh0,
                                            bXh + (size_t)(TT - 1) * HH,
                                            bXl + (size_t)(TT - 1) * HH,
                                            seqStride, c_dec,
                                            bXh, bXl, bars + 2 * 256);

    // ---- decoder layer 1 (A = bufX planes; h0 = enc1 final row) ----
    gemm_mma<true><<<gemmGrid2048, 256, GM_SMEM>>>(
        nullptr, bXh, bXl, wh + WO3, wl + WO3, dbih1, dbhh1, pre, M, G4, HH, 0);
    lstm_scan<<<scanGrid, 256, SCAN_SMEM>>>(pre, dWhh1,
                                            bYh + (size_t)(TT - 1) * HH,
                                            bYl + (size_t)(TT - 1) * HH,
                                            seqStride, c_dec + BB * HH,
                                            bYh, bYl, bars + 3 * 256);

    // ---- FC head (A = bufY planes) ----
    gemm_mma<true><<<gemmGrid128, 256, GM_SMEM>>>(
        nullptr, bYh, bYl, wh + WO4, wl + WO4, fcB, nullptr, out, M, II, HH, 0);
}

// round 10
// speedup vs baseline: 3.0491x; 1.0037x over previous
#include <cuda_runtime.h>
#include <cuda_bf16.h>
#include <math.h>
#include <stdint.h>

// Problem constants
#define BB   128      // batch
#define TT   512      // time steps
#define HH   512      // hidden
#define II   128      // input dim
#define G4   2048     // 4*H

// ---------------- scratch (static device memory; no allocations) ----------
__device__ float g_pre [(size_t)BB * TT * G4];
__device__ __align__(16) __nv_bfloat16 g_bufXh[(size_t)BB * TT * HH];
__device__ __align__(16) __nv_bfloat16 g_bufXl[(size_t)BB * TT * HH];
__device__ __align__(16) __nv_bfloat16 g_bufYh[(size_t)BB * TT * HH];
__device__ __align__(16) __nv_bfloat16 g_bufYl[(size_t)BB * TT * HH];
// weight planes: [enc0 2048x128][enc1 2048x512][dec0 2048x128][dec1 2048x512][fc 128x512]
#define WO0 0
#define WO1 (WO0 + 2048 * 128)
#define WO2 (WO1 + 2048 * 512)
#define WO3 (WO2 + 2048 * 128)
#define WO4 (WO3 + 2048 * 512)
#define WTOT (WO4 + 128 * 512)
__device__ __align__(16) __nv_bfloat16 g_wh[WTOT];
__device__ __align__(16) __nv_bfloat16 g_wl[WTOT];
__device__ unsigned g_barrier[1024];  // 4 layers x 4 groups: counter g*64, flag g*64+32

// ---------------- tiny init kernels ----------------------------------------
__global__ void zero_bar(unsigned* p, int n) {
    int i = blockIdx.x * blockDim.x + threadIdx.x;
    if (i < n) p[i] = 0u;
}
__global__ void split_planes(const float* __restrict__ in,
                             __nv_bfloat16* __restrict__ oh,
                             __nv_bfloat16* __restrict__ ol, int n) {
    int i = blockIdx.x * blockDim.x + threadIdx.x;
    if (i < n) {
        float v = in[i];
        __nv_bfloat16 h = __float2bfloat16_rn(v);
        oh[i] = h;
        ol[i] = __float2bfloat16_rn(v - __bfloat162float(h));
    }
}

// ======================= mma.sync helpers (compute_103-safe) ===============
__device__ __forceinline__ uint32_t smem_u32(const void* p) {
    return (uint32_t)__cvta_generic_to_shared(p);
}

#define LDSM4(d, addr)                                                        \
    asm volatile("ldmatrix.sync.aligned.m8n8.x4.shared.b16 "                  \
                 "{%0,%1,%2,%3}, [%4];"                                       \
                 : "=r"((d)[0]), "=r"((d)[1]), "=r"((d)[2]), "=r"((d)[3])     \
                 : "r"(addr))

#define MMA_BF16(cc, a, bb0, bb1)                                             \
    asm volatile("mma.sync.aligned.m16n8k16.row.col.f32.bf16.bf16.f32 "       \
                 "{%0,%1,%2,%3}, {%4,%5,%6,%7}, {%8,%9}, {%0,%1,%2,%3};"      \
                 : "+f"((cc)[0]), "+f"((cc)[1]), "+f"((cc)[2]), "+f"((cc)[3]) \
                 : "r"((a)[0]), "r"((a)[1]), "r"((a)[2]), "r"((a)[3]),        \
                   "r"(bb0), "r"(bb1))

__device__ __forceinline__ void split2(float x, float y,
                                       uint32_t& hi, uint32_t& lo) {
    __nv_bfloat16 hx = __float2bfloat16_rn(x);
    __nv_bfloat16 hy = __float2bfloat16_rn(y);
    __nv_bfloat16 lx = __float2bfloat16_rn(x - __bfloat162float(hx));
    __nv_bfloat16 ly = __float2bfloat16_rn(y - __bfloat162float(hy));
    hi = ((uint32_t)__bfloat16_as_ushort(hy) << 16) | __bfloat16_as_ushort(hx);
    lo = ((uint32_t)__bfloat16_as_ushort(ly) << 16) | __bfloat16_as_ushort(lx);
}

// ===================== bf16x3 mma.sync GEMM v3 (validated, unchanged) ======
#define APITCH   40
#define A_U16    (64 * APITCH)
#define W_U16G   (128 * APITCH)
#define STAGE_U16 (2 * A_U16 + 2 * W_U16G)
#define OFF_AH   0
#define OFF_AL   A_U16
#define OFF_WH   (2 * A_U16)
#define OFF_WL   (2 * A_U16 + W_U16G)
#define GM_SMEM  (2 * STAGE_U16 * 2)

template<bool PA>
__global__ __launch_bounds__(256, 2) void gemm_mma(
    const float* __restrict__ A,
    const __nv_bfloat16* __restrict__ Ahp,
    const __nv_bfloat16* __restrict__ Alp,
    const __nv_bfloat16* __restrict__ Whp,
    const __nv_bfloat16* __restrict__ Wlp,
    const float* __restrict__ b1, const float* __restrict__ b2,
    float* __restrict__ C, int M, int N, int K, int shiftT)
{
    extern __shared__ __align__(16) uint16_t sm16[];

    const int tid  = threadIdx.x;
    const int lane = tid & 31;
    const int wid  = tid >> 5;
    const int wm   = (wid & 1) * 32;
    const int wn   = (wid >> 1) * 32;
    const int row0 = blockIdx.y * 64;
    const int col0 = blockIdx.x * 128;

    float c[2][4][4];
#pragma unroll
    for (int i = 0; i < 2; i++)
#pragma unroll
        for (int j = 0; j < 4; j++)
#pragma unroll
            for (int q = 0; q < 4; q++) c[i][j][q] = 0.0f;

    float4 Af[2];
    uint4  Ahu, Alu;
    uint4  Whu[2], Wlu[2];

    const int nch = K / 32;
    const int ar  = tid >> 2;
    const int ac8 = (tid & 3) * 8;

    auto load_chunk = [&](int k0) {
        if (PA) {
            Ahu = *(const uint4*)&Ahp[(size_t)(row0 + ar) * K + k0 + ac8];
            Alu = *(const uint4*)&Alp[(size_t)(row0 + ar) * K + k0 + ac8];
        } else {
#pragma unroll
            for (int p = 0; p < 2; p++) {
                int e  = p * 256 + tid;
                int r  = e >> 3;
                int c4 = e & 7;
                int grow = row0 + r;
                float4 av;
                if (shiftT) {
                    if ((grow % shiftT) == 0) av = make_float4(0.f, 0.f, 0.f, 0.f);
                    else av = *(const float4*)&A[(size_t)(grow - 1) * K + k0 + c4 * 4];
                } else {
                    av = *(const float4*)&A[(size_t)grow * K + k0 + c4 * 4];
                }
                Af[p] = av;
            }
        }
#pragma unroll
        for (int p = 0; p < 2; p++) {
            int e  = p * 256 + tid;
            int r  = e >> 2;
            int c8 = (e & 3) * 8;
            Whu[p] = *(const uint4*)&Whp[(size_t)(col0 + r) * K + k0 + c8];
            Wlu[p] = *(const uint4*)&Wlp[(size_t)(col0 + r) * K + k0 + c8];
        }
    };

    auto store_chunk = [&](uint16_t* st) {
        if (PA) {
            *(uint4*)&st[OFF_AH + ar * APITCH + ac8] = Ahu;
            *(uint4*)&st[OFF_AL + ar * APITCH + ac8] = Alu;
        } else {
#pragma unroll
            for (int p = 0; p < 2; p++) {
                int e  = p * 256 + tid;
                int r  = e >> 3;
                int c4 = e & 7;
                int off = r * APITCH + c4 * 4;
                uint32_t h0, l0, h1, l1;
                split2(Af[p].x, Af[p].y, h0, l0);
                split2(Af[p].z, Af[p].w, h1, l1);
                *(uint2*)&st[OFF_AH + off] = make_uint2(h0, h1);
                *(uint2*)&st[OFF_AL + off] = make_uint2(l0, l1);
            }
        }
#pragma unroll
        for (int p = 0; p < 2; p++) {
            int e  = p * 256 + tid;
            int r  = e >> 2;
            int c8 = (e & 3) * 8;
            *(uint4*)&st[OFF_WH + r * APITCH + c8] = Whu[p];
            *(uint4*)&st[OFF_WL + r * APITCH + c8] = Wlu[p];
        }
    };

    load_chunk(0);

    for (int i = 0; i < nch; i++) {
        const int s = i & 1;
        uint16_t* st = sm16 + s * STAGE_U16;
        store_chunk(st);
        __syncthreads();
        if (i + 1 < nch)
            load_chunk((i + 1) * 32);

        const uint32_t base = smem_u32(st);
#pragma unroll
        for (int kh = 0; kh < 2; kh++) {
            uint32_t ah[2][4], al[2][4];
            const int arow = wm + (lane & 15);
            const int akk  = kh * 16 + (lane >> 4) * 8;
#pragma unroll
            for (int mt = 0; mt < 2; mt++) {
                uint32_t boff = (uint32_t)(((arow + mt * 16) * APITCH + akk) * 2);
                LDSM4(ah[mt], base + OFF_AH * 2 + boff);
                LDSM4(al[mt], base + OFF_AL * 2 + boff);
            }
            uint32_t bh[2][4], bl[2][4];
            const int brow = wn + (lane & 7) + ((lane >> 4) << 3);
            const int bkk  = kh * 16 + ((lane >> 3) & 1) * 8;
#pragma unroll
            for (int np = 0; np < 2; np++) {
                uint32_t boff = (uint32_t)(((brow + np * 16) * APITCH + bkk) * 2);
                LDSM4(bh[np], base + OFF_WH * 2 + boff);
                LDSM4(bl[np], base + OFF_WL * 2 + boff);
            }
#pragma unroll
            for (int mt = 0; mt < 2; mt++)
#pragma unroll
                for (int np = 0; np < 2; np++)
#pragma unroll
                    for (int h = 0; h < 2; h++) {
                        int nt = np * 2 + h;
                        MMA_BF16(c[mt][nt], ah[mt], bh[np][h * 2], bh[np][h * 2 + 1]);
                        MMA_BF16(c[mt][nt], ah[mt], bl[np][h * 2], bl[np][h * 2 + 1]);
                        MMA_BF16(c[mt][nt], al[mt], bh[np][h * 2], bh[np][h * 2 + 1]);
                    }
        }
        __syncthreads();
    }

#pragma unroll
    for (int mt = 0; mt < 2; mt++) {
#pragma unroll
        for (int nt = 0; nt < 4; nt++) {
            int m = row0 + wm + mt * 16 + (lane >> 2);
            int n = col0 + wn + nt * 8 + (lane & 3) * 2;
            float bx = b1[n]     + (b2 ? b2[n]     : 0.f);
            float by = b1[n + 1] + (b2 ? b2[n + 1] : 0.f);
            float2 v0 = make_float2(c[mt][nt][0] + bx, c[mt][nt][1] + by);
            float2 v1 = make_float2(c[mt][nt][2] + bx, c[mt][nt][3] + by);
            *(float2*)&C[(size_t)m * N + n]       = v0;
            *(float2*)&C[(size_t)(m + 8) * N + n] = v1;
        }
    }
}

// ===================== tensor-core persistent LSTM scan v7 =================
// 512 threads (16 warps = 4/SMSP). Warp w: gate (w&3), K-quarter (w>>2),
// 96 mma each. Gate buffer (4 quarters) ALIASED onto the h staging region:
// safe because gsm is written only after all mma reads of h (extra sync) and
// h is re-staged only after the gate update consumed gsm (arrive sync).
#define WPITCH 520
#define W_U16S (64 * WPITCH)
#define H_U16S (32 * WPITCH)
#define GPITCH 18
#define GQ     (4 * 32 * GPITCH)          // one quarter's gate buffer (floats)
#define SCAN_SMEM ((2 * W_U16S + 2 * H_U16S) * 2)

__global__ __launch_bounds__(512, 1) void lstm_scan(
    const float* __restrict__ pre,            // [B,T,4H]
    const float* __restrict__ Whh,            // [4H,H] fp32 (split once here)
    const __nv_bfloat16* __restrict__ h0h,    // initial hidden planes or null
    const __nv_bfloat16* __restrict__ h0l,
    long long h0s,
    const float* __restrict__ cinit,          // [B,H] initial cell or null
    __nv_bfloat16* __restrict__ ph,           // output hidden planes [B,T,H]
    __nv_bfloat16* __restrict__ pl,
    unsigned* __restrict__ bar)
{
    extern __shared__ __align__(16) uint16_t sm16[];
    uint16_t* wsh = sm16;
    uint16_t* wsl = wsh + W_U16S;
    uint16_t* hsh = wsl + W_U16S;
    uint16_t* hsl = hsh + H_U16S;
    float*    gsm = (float*)hsh;              // ALIASED over h region

    const int tid  = threadIdx.x;
    const int lane = tid & 31;
    const int wid  = tid >> 5;                // 0..15
    const int gate = wid & 3;
    const int kbase = (wid >> 2) * 128;       // K quarter
    const int grp  = blockIdx.x;
    const int bi0  = grp * 32;
    const int hc0  = blockIdx.y * 16;
    unsigned* ctr  = bar + grp * 64;
    unsigned* flag = ctr + 32;

    // ---- load + split Whh slice once ----
    for (int idx = tid * 4; idx < 64 * 512; idx += 512 * 4) {
        int r  = idx >> 9;
        int k  = idx & 511;
        int gt = r >> 4;
        int rr = r & 15;
        float4 v = *(const float4*)&Whh[((size_t)gt * HH + hc0 + rr) * HH + k];
        uint32_t h0w, l0w, h1w, l1w;
        split2(v.x, v.y, h0w, l0w);
        split2(v.z, v.w, h1w, l1w);
        *(uint2*)&wsh[r * WPITCH + k] = make_uint2(h0w, h1w);
        *(uint2*)&wsl[r * WPITCH + k] = make_uint2(l0w, l1w);
    }

    // ---- cell state: thread owns exactly one (b, col) ----
    const int j   = tid & 15;
    const int bl_ = tid >> 4;                 // 0..31 local batch
    const int b_g = bi0 + bl_;
    const int col = hc0 + j;
    float c_r = cinit ? cinit[b_g * HH + col] : 0.0f;

    const uint32_t hshb = smem_u32(hsh);
    const uint32_t hslb = smem_u32(hsl);
    const uint32_t wshb = smem_u32(wsh);
    const uint32_t wslb = smem_u32(wsl);

    const int arow = lane & 15;
    const int aoff = (lane >> 4) * 8;
    const int brow = gate * 16 + (lane & 7) + ((lane >> 4) << 3);
    const int boff = ((lane >> 3) & 1) * 8;

    for (int t = 0; t < TT; t++) {
        // ---- prefetch pre(t) (h-independent; overlaps poll) ----
        float pr[4];
        {
            size_t prow = ((size_t)b_g * TT + t) * (size_t)G4;
#pragma unroll
            for (int g = 0; g < 4; g++)
                pr[g] = pre[prow + g * HH + col];
        }

        // ---- wait on read-only flag: step t-1 complete across group ----
        if (t > 0) {
            unsigned v;
            do {
                asm volatile("ld.acquire.gpu.global.u32 %0, [%1];"
                             : "=r"(v) : "l"(flag) : "memory");
            } while (v < (unsigned)t);
        }

        // ---- stage h(t-1): straight uint4 copies (4 per plane) ----
        uint4 vh[4], vl[4];
#pragma unroll
        for (int p = 0; p < 4; p++) {
            int e  = p * 512 + tid;           // 0..2047
            int r  = e >> 6;                  // 0..31
            int c8 = (e & 63) * 8;
            int b  = bi0 + r;
            if (t == 0) {
                if (h0h) {
                    vh[p] = *(const uint4*)&h0h[(size_t)b * h0s + c8];
                    vl[p] = *(const uint4*)&h0l[(size_t)b * h0s + c8];
                } else {
                    vh[p] = make_uint4(0, 0, 0, 0);
                    vl[p] = make_uint4(0, 0, 0, 0);
                }
            } else {
                size_t off = ((size_t)b * TT + (t - 1)) * HH + c8;
                vh[p] = *(const uint4*)&ph[off];
                vl[p] = *(const uint4*)&pl[off];
            }
        }
#pragma unroll
        for (int p = 0; p < 4; p++) {
            int e  = p * 512 + tid;
            int r  = e >> 6;
            int c8 = (e & 63) * 8;
            *(uint4*)&hsh[r * WPITCH + c8] = vh[p];
            *(uint4*)&hsl[r * WPITCH + c8] = vl[p];
        }
        __syncthreads();

        // ---- mma: this warp's gate over its K quarter (8 k16 chunks) ----
        float c[2][2][4];
#pragma unroll
        for (int mt = 0; mt < 2; mt++)
#pragma unroll
            for (int nt = 0; nt < 2; nt++)
#pragma unroll
                for (int q = 0; q < 4; q++) c[mt][nt][q] = 0.0f;

#pragma unroll
        for (int q = 0; q < 8; q++) {
            int kc = kbase + q * 16;
            uint32_t ah[2][4], al[2][4], bh4[4], bl4[4];
#pragma unroll
            for (int mt = 0; mt < 2; mt++) {
                uint32_t off = (uint32_t)(((mt * 16 + arow) * WPITCH + kc + aoff) * 2);
                LDSM4(ah[mt], hshb + off);
                LDSM4(al[mt], hslb + off);
            }
            {
                uint32_t off = (uint32_t)((brow * WPITCH + kc + boff) * 2);
                LDSM4(bh4, wshb + off);
                LDSM4(bl4, wslb + off);
            }
#pragma unroll
            for (int mt = 0; mt < 2; mt++)
#pragma unroll
                for (int h = 0; h < 2; h++) {
                    MMA_BF16(c[mt][h], ah[mt], bh4[h * 2], bh4[h * 2 + 1]);
                    MMA_BF16(c[mt][h], ah[mt], bl4[h * 2], bl4[h * 2 + 1]);
                    MMA_BF16(c[mt][h], al[mt], bh4[h * 2], bh4[h * 2 + 1]);
                }
        }
        __syncthreads();   // all mma reads of h done before gsm overwrite

        // ---- fragments -> aliased gate buffer (own quarter section) ----
        float* gq = gsm + (wid >> 2) * GQ;
#pragma unroll
        for (int mt = 0; mt < 2; mt++)
#pragma unroll
            for (int nt = 0; nt < 2; nt++) {
                int m = mt * 16 + (lane >> 2);
                int n = nt * 8 + (lane & 3) * 2;
                float* gbase = gq + (gate * 32 + m) * GPITCH + n;
                *(float2*)gbase                = make_float2(c[mt][nt][0], c[mt][nt][1]);
                *(float2*)(gbase + 8 * GPITCH) = make_float2(c[mt][nt][2], c[mt][nt][3]);
            }
        __syncthreads();

        // ---- gates + state update: one (b, col) per thread ----
        {
            float gv[4];
#pragma unroll
            for (int g = 0; g < 4; g++) {
                float s = pr[g];
#pragma unroll
                for (int q = 0; q < 4; q++)
                    s += gsm[q * GQ + (g * 32 + bl_) * GPITCH + j];
                gv[g] = s;
            }
            float i_ = 1.0f / (1.0f + __expf(-gv[0]));
            float f_ = 1.0f / (1.0f + __expf(-gv[1]));
            float e2 = __expf(2.0f * gv[2]);
            float g_ = (e2 - 1.0f) / (e2 + 1.0f);
            float o_ = 1.0f / (1.0f + __expf(-gv[3]));

            float cn = f_ * c_r + i_ * g_;
            c_r = cn;
            float ec = __expf(2.0f * cn);
            float th = (ec - 1.0f) / (ec + 1.0f);
            float hv = o_ * th;

            __nv_bfloat16 hh = __float2bfloat16_rn(hv);
            __nv_bfloat16 hl = __float2bfloat16_rn(hv - __bfloat162float(hh));
            size_t off = ((size_t)b_g * TT + t) * HH + col;
            ph[off] = hh;
            pl[off] = hl;
        }

        // ---- arrive: counter RMW; last arriver release-stores the flag ----
        __syncthreads();
        if (tid == 0) {
            unsigned old;
            asm volatile("atom.acq_rel.gpu.global.add.u32 %0, [%1], %2;"
                         : "=r"(old) : "l"(ctr), "r"(1u) : "memory");
            if (old == (unsigned)(t * 32 + 31)) {
                asm volatile("st.release.gpu.global.u32 [%0], %1;"
                             :: "l"(flag), "r"((unsigned)(t + 1)) : "memory");
            }
        }
    }
}

// ---------------- host driver --------------------------------------------
extern "C" void kernel_launch(void* const* d_in, const int* in_sizes, int n_in,
                              void* d_out, int out_size)
{
    const float* x     = (const float*)d_in[0];
    const float* c_dec = (const float*)d_in[1];
    const float* eWih0 = (const float*)d_in[2];
    const float* eWhh0 = (const float*)d_in[3];
    const float* ebih0 = (const float*)d_in[4];
    const float* ebhh0 = (const float*)d_in[5];
    const float* eWih1 = (const float*)d_in[6];
    const float* eWhh1 = (const float*)d_in[7];
    const float* ebih1 = (const float*)d_in[8];
    const float* ebhh1 = (const float*)d_in[9];
    const float* dWih0 = (const float*)d_in[10];
    const float* dWhh0 = (const float*)d_in[11];
    const float* dbih0 = (const float*)d_in[12];
    const float* dbhh0 = (const float*)d_in[13];
    const float* dWih1 = (const float*)d_in[14];
    const float* dWhh1 = (const float*)d_in[15];
    const float* dbih1 = (const float*)d_in[16];
    const float* dbhh1 = (const float*)d_in[17];
    const float* fcW   = (const float*)d_in[18];
    const float* fcB   = (const float*)d_in[19];
    float*       out   = (float*)d_out;

    static float *pre = nullptr;
    static __nv_bfloat16 *bXh, *bXl, *bYh, *bYl, *wh, *wl;
    static unsigned *bars = nullptr;
    static bool inited = false;
    if (!inited) {
        cudaGetSymbolAddress((void**)&pre,  g_pre);
        cudaGetSymbolAddress((void**)&bXh,  g_bufXh);
        cudaGetSymbolAddress((void**)&bXl,  g_bufXl);
        cudaGetSymbolAddress((void**)&bYh,  g_bufYh);
        cudaGetSymbolAddress((void**)&bYl,  g_bufYl);
        cudaGetSymbolAddress((void**)&wh,   g_wh);
        cudaGetSymbolAddress((void**)&wl,   g_wl);
        cudaGetSymbolAddress((void**)&bars, g_barrier);
        cudaFuncSetAttribute(lstm_scan,
                             cudaFuncAttributeMaxDynamicSharedMemorySize, SCAN_SMEM);
        cudaFuncSetAttribute(gemm_mma<false>,
                             cudaFuncAttributeMaxDynamicSharedMemorySize, GM_SMEM);
        cudaFuncSetAttribute(gemm_mma<true>,
                             cudaFuncAttributeMaxDynamicSharedMemorySize, GM_SMEM);
        inited = true;
    }

    const int M = BB * TT;
    const dim3 gemmGrid2048(G4 / 128, M / 64);
    const dim3 gemmGrid128(II / 128,  M / 64);
    const dim3 scanGrid(4, 32);
    const long long seqStride = (long long)TT * HH;

    zero_bar<<<4, 256>>>(bars, 1024);

    // ---- pre-split all feed-forward weights into bf16 planes ----
    split_planes<<<(2048 * 128 + 255) / 256, 256>>>(eWih0, wh + WO0, wl + WO0, 2048 * 128);
    split_planes<<<(2048 * 512 + 255) / 256, 256>>>(eWih1, wh + WO1, wl + WO1, 2048 * 512);
    split_planes<<<(2048 * 128 + 255) / 256, 256>>>(dWih0, wh + WO2, wl + WO2, 2048 * 128);
    split_planes<<<(2048 * 512 + 255) / 256, 256>>>(dWih1, wh + WO3, wl + WO3, 2048 * 512);
    split_planes<<<(128 * 512 + 255) / 256, 256>>>(fcW,   wh + WO4, wl + WO4, 128 * 512);

    // ---- encoder layer 0 (A = x fp32) ----
    gemm_mma<false><<<gemmGrid2048, 256, GM_SMEM>>>(
        x, nullptr, nullptr, wh + WO0, wl + WO0, ebih0, ebhh0, pre, M, G4, II, 0);
    lstm_scan<<<scanGrid, 512, SCAN_SMEM>>>(pre, eWhh0, nullptr, nullptr, 0, nullptr,
                                            bXh, bXl, bars + 0 * 256);

    // ---- encoder layer 1 (A = bufX planes) ----
    gemm_mma<true><<<gemmGrid2048, 256, GM_SMEM>>>(
        nullptr, bXh, bXl, wh + WO1, wl + WO1, ebih1, ebhh1, pre, M, G4, HH, 0);
    lstm_scan<<<scanGrid, 512, SCAN_SMEM>>>(pre, eWhh1, nullptr, nullptr, 0, nullptr,
                                            bYh, bYl, bars + 1 * 256);

    // ---- decoder layer 0 (A = x fp32 shifted; h0 = enc0 final row) ----
    gemm_mma<false><<<gemmGrid2048, 256, GM_SMEM>>>(
        x, nullptr, nullptr, wh + WO2, wl + WO2, dbih0, dbhh0, pre, M, G4, II, TT);
    lstm_scan<<<scanGrid, 512, SCAN_SMEM>>>(pre, dWhh0,
                                            bXh + (size_t)(TT - 1) * HH,
                                            bXl + (size_t)(TT - 1) * HH,
                                            seqStride, c_dec,
                                            bXh, bXl, bars + 2 * 256);

    // ---- decoder layer 1 (A = bufX planes; h0 = enc1 final row) ----
    gemm_mma<true><<<gemmGrid2048, 256, GM_SMEM>>>(
        nullptr, bXh, bXl, wh + WO3, wl + WO3, dbih1, dbhh1, pre, M, G4, HH, 0);
    lstm_scan<<<scanGrid, 512, SCAN_SMEM>>>(pre, dWhh1,
                                            bYh + (size_t)(TT - 1) * HH,
                                            bYl + (size_t)(TT - 1) * HH,
                                            seqStride, c_dec + BB * HH,
                                            bYh, bYl, bars + 3 * 256);

    // ---- FC head (A = bufY planes) ----
    gemm_mma<true><<<gemmGrid128, 256, GM_SMEM>>>(
        nullptr, bYh, bYl, wh + WO4, wl + WO4, fcB, nullptr, out, M, II, HH, 0);
}

// round 11
// speedup vs baseline: 3.0505x; 1.0005x over previous
#include <cuda_runtime.h>
#include <cuda_bf16.h>
#include <math.h>
#include <stdint.h>

// Problem constants
#define BB   128      // batch
#define TT   512      // time steps
#define HH   512      // hidden
#define II   128      // input dim
#define G4   2048     // 4*H

// ---------------- scratch (static device memory; no allocations) ----------
__device__ float g_pre [(size_t)BB * TT * G4];
__device__ __align__(16) __nv_bfloat16 g_bufXh[(size_t)BB * TT * HH];
__device__ __align__(16) __nv_bfloat16 g_bufXl[(size_t)BB * TT * HH];
__device__ __align__(16) __nv_bfloat16 g_bufYh[(size_t)BB * TT * HH];
__device__ __align__(16) __nv_bfloat16 g_bufYl[(size_t)BB * TT * HH];
// weight planes: [enc0 2048x128][enc1 2048x512][dec0 2048x128][dec1 2048x512][fc 128x512]
#define WO0 0
#define WO1 (WO0 + 2048 * 128)
#define WO2 (WO1 + 2048 * 512)
#define WO3 (WO2 + 2048 * 128)
#define WO4 (WO3 + 2048 * 512)
#define WTOT (WO4 + 128 * 512)
__device__ __align__(16) __nv_bfloat16 g_wh[WTOT];
__device__ __align__(16) __nv_bfloat16 g_wl[WTOT];
__device__ unsigned g_barrier[1024];  // 4 layers x 4 groups: counter g*64, flag g*64+32

// ---------------- tiny init kernels ----------------------------------------
__global__ void zero_bar(unsigned* p, int n) {
    int i = blockIdx.x * blockDim.x + threadIdx.x;
    if (i < n) p[i] = 0u;
}
__global__ void split_planes(const float* __restrict__ in,
                             __nv_bfloat16* __restrict__ oh,
                             __nv_bfloat16* __restrict__ ol, int n) {
    int i = blockIdx.x * blockDim.x + threadIdx.x;
    if (i < n) {
        float v = in[i];
        __nv_bfloat16 h = __float2bfloat16_rn(v);
        oh[i] = h;
        ol[i] = __float2bfloat16_rn(v - __bfloat162float(h));
    }
}

// ======================= mma.sync helpers (compute_103-safe) ===============
__device__ __forceinline__ uint32_t smem_u32(const void* p) {
    return (uint32_t)__cvta_generic_to_shared(p);
}

#define LDSM4(d, addr)                                                        \
    asm volatile("ldmatrix.sync.aligned.m8n8.x4.shared.b16 "                  \
                 "{%0,%1,%2,%3}, [%4];"                                       \
                 : "=r"((d)[0]), "=r"((d)[1]), "=r"((d)[2]), "=r"((d)[3])     \
                 : "r"(addr))

#define MMA_BF16(cc, a, bb0, bb1)                                             \
    asm volatile("mma.sync.aligned.m16n8k16.row.col.f32.bf16.bf16.f32 "       \
                 "{%0,%1,%2,%3}, {%4,%5,%6,%7}, {%8,%9}, {%0,%1,%2,%3};"      \
                 : "+f"((cc)[0]), "+f"((cc)[1]), "+f"((cc)[2]), "+f"((cc)[3]) \
                 : "r"((a)[0]), "r"((a)[1]), "r"((a)[2]), "r"((a)[3]),        \
                   "r"(bb0), "r"(bb1))

__device__ __forceinline__ void split2(float x, float y,
                                       uint32_t& hi, uint32_t& lo) {
    __nv_bfloat16 hx = __float2bfloat16_rn(x);
    __nv_bfloat16 hy = __float2bfloat16_rn(y);
    __nv_bfloat16 lx = __float2bfloat16_rn(x - __bfloat162float(hx));
    __nv_bfloat16 ly = __float2bfloat16_rn(y - __bfloat162float(hy));
    hi = ((uint32_t)__bfloat16_as_ushort(hy) << 16) | __bfloat16_as_ushort(hx);
    lo = ((uint32_t)__bfloat16_as_ushort(ly) << 16) | __bfloat16_as_ushort(lx);
}

// ===================== bf16x3 mma.sync GEMM v3 (validated, unchanged) ======
#define APITCH   40
#define A_U16    (64 * APITCH)
#define W_U16G   (128 * APITCH)
#define STAGE_U16 (2 * A_U16 + 2 * W_U16G)
#define OFF_AH   0
#define OFF_AL   A_U16
#define OFF_WH   (2 * A_U16)
#define OFF_WL   (2 * A_U16 + W_U16G)
#define GM_SMEM  (2 * STAGE_U16 * 2)

template<bool PA>
__global__ __launch_bounds__(256, 2) void gemm_mma(
    const float* __restrict__ A,
    const __nv_bfloat16* __restrict__ Ahp,
    const __nv_bfloat16* __restrict__ Alp,
    const __nv_bfloat16* __restrict__ Whp,
    const __nv_bfloat16* __restrict__ Wlp,
    const float* __restrict__ b1, const float* __restrict__ b2,
    float* __restrict__ C, int M, int N, int K, int shiftT)
{
    extern __shared__ __align__(16) uint16_t sm16[];

    const int tid  = threadIdx.x;
    const int lane = tid & 31;
    const int wid  = tid >> 5;
    const int wm   = (wid & 1) * 32;
    const int wn   = (wid >> 1) * 32;
    const int row0 = blockIdx.y * 64;
    const int col0 = blockIdx.x * 128;

    float c[2][4][4];
#pragma unroll
    for (int i = 0; i < 2; i++)
#pragma unroll
        for (int j = 0; j < 4; j++)
#pragma unroll
            for (int q = 0; q < 4; q++) c[i][j][q] = 0.0f;

    float4 Af[2];
    uint4  Ahu, Alu;
    uint4  Whu[2], Wlu[2];

    const int nch = K / 32;
    const int ar  = tid >> 2;
    const int ac8 = (tid & 3) * 8;

    auto load_chunk = [&](int k0) {
        if (PA) {
            Ahu = *(const uint4*)&Ahp[(size_t)(row0 + ar) * K + k0 + ac8];
            Alu = *(const uint4*)&Alp[(size_t)(row0 + ar) * K + k0 + ac8];
        } else {
#pragma unroll
            for (int p = 0; p < 2; p++) {
                int e  = p * 256 + tid;
                int r  = e >> 3;
                int c4 = e & 7;
                int grow = row0 + r;
                float4 av;
                if (shiftT) {
                    if ((grow % shiftT) == 0) av = make_float4(0.f, 0.f, 0.f, 0.f);
                    else av = *(const float4*)&A[(size_t)(grow - 1) * K + k0 + c4 * 4];
                } else {
                    av = *(const float4*)&A[(size_t)grow * K + k0 + c4 * 4];
                }
                Af[p] = av;
            }
        }
#pragma unroll
        for (int p = 0; p < 2; p++) {
            int e  = p * 256 + tid;
            int r  = e >> 2;
            int c8 = (e & 3) * 8;
            Whu[p] = *(const uint4*)&Whp[(size_t)(col0 + r) * K + k0 + c8];
            Wlu[p] = *(const uint4*)&Wlp[(size_t)(col0 + r) * K + k0 + c8];
        }
    };

    auto store_chunk = [&](uint16_t* st) {
        if (PA) {
            *(uint4*)&st[OFF_AH + ar * APITCH + ac8] = Ahu;
            *(uint4*)&st[OFF_AL + ar * APITCH + ac8] = Alu;
        } else {
#pragma unroll
            for (int p = 0; p < 2; p++) {
                int e  = p * 256 + tid;
                int r  = e >> 3;
                int c4 = e & 7;
                int off = r * APITCH + c4 * 4;
                uint32_t h0, l0, h1, l1;
                split2(Af[p].x, Af[p].y, h0, l0);
                split2(Af[p].z, Af[p].w, h1, l1);
                *(uint2*)&st[OFF_AH + off] = make_uint2(h0, h1);
                *(uint2*)&st[OFF_AL + off] = make_uint2(l0, l1);
            }
        }
#pragma unroll
        for (int p = 0; p < 2; p++) {
            int e  = p * 256 + tid;
            int r  = e >> 2;
            int c8 = (e & 3) * 8;
            *(uint4*)&st[OFF_WH + r * APITCH + c8] = Whu[p];
            *(uint4*)&st[OFF_WL + r * APITCH + c8] = Wlu[p];
        }
    };

    load_chunk(0);

    for (int i = 0; i < nch; i++) {
        const int s = i & 1;
        uint16_t* st = sm16 + s * STAGE_U16;
        store_chunk(st);
        __syncthreads();
        if (i + 1 < nch)
            load_chunk((i + 1) * 32);

        const uint32_t base = smem_u32(st);
#pragma unroll
        for (int kh = 0; kh < 2; kh++) {
            uint32_t ah[2][4], al[2][4];
            const int arow = wm + (lane & 15);
            const int akk  = kh * 16 + (lane >> 4) * 8;
#pragma unroll
            for (int mt = 0; mt < 2; mt++) {
                uint32_t boff = (uint32_t)(((arow + mt * 16) * APITCH + akk) * 2);
                LDSM4(ah[mt], base + OFF_AH * 2 + boff);
                LDSM4(al[mt], base + OFF_AL * 2 + boff);
            }
            uint32_t bh[2][4], bl[2][4];
            const int brow = wn + (lane & 7) + ((lane >> 4) << 3);
            const int bkk  = kh * 16 + ((lane >> 3) & 1) * 8;
#pragma unroll
            for (int np = 0; np < 2; np++) {
                uint32_t boff = (uint32_t)(((brow + np * 16) * APITCH + bkk) * 2);
                LDSM4(bh[np], base + OFF_WH * 2 + boff);
                LDSM4(bl[np], base + OFF_WL * 2 + boff);
            }
#pragma unroll
            for (int mt = 0; mt < 2; mt++)
#pragma unroll
                for (int np = 0; np < 2; np++)
#pragma unroll
                    for (int h = 0; h < 2; h++) {
                        int nt = np * 2 + h;
                        MMA_BF16(c[mt][nt], ah[mt], bh[np][h * 2], bh[np][h * 2 + 1]);
                        MMA_BF16(c[mt][nt], ah[mt], bl[np][h * 2], bl[np][h * 2 + 1]);
                        MMA_BF16(c[mt][nt], al[mt], bh[np][h * 2], bh[np][h * 2 + 1]);
                    }
        }
        __syncthreads();
    }

#pragma unroll
    for (int mt = 0; mt < 2; mt++) {
#pragma unroll
        for (int nt = 0; nt < 4; nt++) {
            int m = row0 + wm + mt * 16 + (lane >> 2);
            int n = col0 + wn + nt * 8 + (lane & 3) * 2;
            float bx = b1[n]     + (b2 ? b2[n]     : 0.f);
            float by = b1[n + 1] + (b2 ? b2[n + 1] : 0.f);
            float2 v0 = make_float2(c[mt][nt][0] + bx, c[mt][nt][1] + by);
            float2 v1 = make_float2(c[mt][nt][2] + bx, c[mt][nt][3] + by);
            *(float2*)&C[(size_t)m * N + n]       = v0;
            *(float2*)&C[(size_t)(m + 8) * N + n] = v1;
        }
    }
}

// ===================== tensor-core persistent LSTM scan v7 =================
// 512 threads (16 warps = 4/SMSP). Warp w: gate (w&3), K-quarter (w>>2),
// 96 mma each. Gate buffer (4 quarters) ALIASED onto the h staging region:
// safe because gsm is written only after all mma reads of h (extra sync) and
// h is re-staged only after the gate update consumed gsm (arrive sync).
#define WPITCH 520
#define W_U16S (64 * WPITCH)
#define H_U16S (32 * WPITCH)
#define GPITCH 18
#define GQ     (4 * 32 * GPITCH)          // one quarter's gate buffer (floats)
#define SCAN_SMEM ((2 * W_U16S + 2 * H_U16S) * 2)

__global__ __launch_bounds__(512, 1) void lstm_scan(
    const float* __restrict__ pre,            // [B,T,4H]
    const float* __restrict__ Whh,            // [4H,H] fp32 (split once here)
    const __nv_bfloat16* __restrict__ h0h,    // initial hidden planes or null
    const __nv_bfloat16* __restrict__ h0l,
    long long h0s,
    const float* __restrict__ cinit,          // [B,H] initial cell or null
    __nv_bfloat16* __restrict__ ph,           // output hidden planes [B,T,H]
    __nv_bfloat16* __restrict__ pl,
    unsigned* __restrict__ bar)
{
    extern __shared__ __align__(16) uint16_t sm16[];
    uint16_t* wsh = sm16;
    uint16_t* wsl = wsh + W_U16S;
    uint16_t* hsh = wsl + W_U16S;
    uint16_t* hsl = hsh + H_U16S;
    float*    gsm = (float*)hsh;              // ALIASED over h region

    const int tid  = threadIdx.x;
    const int lane = tid & 31;
    const int wid  = tid >> 5;                // 0..15
    const int gate = wid & 3;
    const int kbase = (wid >> 2) * 128;       // K quarter
    const int grp  = blockIdx.x;
    const int bi0  = grp * 32;
    const int hc0  = blockIdx.y * 16;
    unsigned* ctr  = bar + grp * 64;
    unsigned* flag = ctr + 32;

    // ---- load + split Whh slice once ----
    for (int idx = tid * 4; idx < 64 * 512; idx += 512 * 4) {
        int r  = idx >> 9;
        int k  = idx & 511;
        int gt = r >> 4;
        int rr = r & 15;
        float4 v = *(const float4*)&Whh[((size_t)gt * HH + hc0 + rr) * HH + k];
        uint32_t h0w, l0w, h1w, l1w;
        split2(v.x, v.y, h0w, l0w);
        split2(v.z, v.w, h1w, l1w);
        *(uint2*)&wsh[r * WPITCH + k] = make_uint2(h0w, h1w);
        *(uint2*)&wsl[r * WPITCH + k] = make_uint2(l0w, l1w);
    }

    // ---- cell state: thread owns exactly one (b, col) ----
    const int j   = tid & 15;
    const int bl_ = tid >> 4;                 // 0..31 local batch
    const int b_g = bi0 + bl_;
    const int col = hc0 + j;
    float c_r = cinit ? cinit[b_g * HH + col] : 0.0f;

    const uint32_t hshb = smem_u32(hsh);
    const uint32_t hslb = smem_u32(hsl);
    const uint32_t wshb = smem_u32(wsh);
    const uint32_t wslb = smem_u32(wsl);

    const int arow = lane & 15;
    const int aoff = (lane >> 4) * 8;
    const int brow = gate * 16 + (lane & 7) + ((lane >> 4) << 3);
    const int boff = ((lane >> 3) & 1) * 8;

    for (int t = 0; t < TT; t++) {
        // ---- prefetch pre(t) (h-independent; overlaps poll) ----
        float pr[4];
        {
            size_t prow = ((size_t)b_g * TT + t) * (size_t)G4;
#pragma unroll
            for (int g = 0; g < 4; g++)
                pr[g] = pre[prow + g * HH + col];
        }

        // ---- wait on read-only flag: step t-1 complete across group ----
        if (t > 0) {
            unsigned v;
            do {
                asm volatile("ld.acquire.gpu.global.u32 %0, [%1];"
                             : "=r"(v) : "l"(flag) : "memory");
            } while (v < (unsigned)t);
        }

        // ---- stage h(t-1): straight uint4 copies (4 per plane) ----
        uint4 vh[4], vl[4];
#pragma unroll
        for (int p = 0; p < 4; p++) {
            int e  = p * 512 + tid;           // 0..2047
            int r  = e >> 6;                  // 0..31
            int c8 = (e & 63) * 8;
            int b  = bi0 + r;
            if (t == 0) {
                if (h0h) {
                    vh[p] = *(const uint4*)&h0h[(size_t)b * h0s + c8];
                    vl[p] = *(const uint4*)&h0l[(size_t)b * h0s + c8];
                } else {
                    vh[p] = make_uint4(0, 0, 0, 0);
                    vl[p] = make_uint4(0, 0, 0, 0);
                }
            } else {
                size_t off = ((size_t)b * TT + (t - 1)) * HH + c8;
                vh[p] = *(const uint4*)&ph[off];
                vl[p] = *(const uint4*)&pl[off];
            }
        }
#pragma unroll
        for (int p = 0; p < 4; p++) {
            int e  = p * 512 + tid;
            int r  = e >> 6;
            int c8 = (e & 63) * 8;
            *(uint4*)&hsh[r * WPITCH + c8] = vh[p];
            *(uint4*)&hsl[r * WPITCH + c8] = vl[p];
        }
        __syncthreads();

        // ---- mma: this warp's gate over its K quarter (8 k16 chunks) ----
        float c[2][2][4];
#pragma unroll
        for (int mt = 0; mt < 2; mt++)
#pragma unroll
            for (int nt = 0; nt < 2; nt++)
#pragma unroll
                for (int q = 0; q < 4; q++) c[mt][nt][q] = 0.0f;

#pragma unroll
        for (int q = 0; q < 8; q++) {
            int kc = kbase + q * 16;
            uint32_t ah[2][4], al[2][4], bh4[4], bl4[4];
#pragma unroll
            for (int mt = 0; mt < 2; mt++) {
                uint32_t off = (uint32_t)(((mt * 16 + arow) * WPITCH + kc + aoff) * 2);
                LDSM4(ah[mt], hshb + off);
                LDSM4(al[mt], hslb + off);
            }
            {
                uint32_t off = (uint32_t)((brow * WPITCH + kc + boff) * 2);
                LDSM4(bh4, wshb + off);
                LDSM4(bl4, wslb + off);
            }
#pragma unroll
            for (int mt = 0; mt < 2; mt++)
#pragma unroll
                for (int h = 0; h < 2; h++) {
                    MMA_BF16(c[mt][h], ah[mt], bh4[h * 2], bh4[h * 2 + 1]);
                    MMA_BF16(c[mt][h], ah[mt], bl4[h * 2], bl4[h * 2 + 1]);
                    MMA_BF16(c[mt][h], al[mt], bh4[h * 2], bh4[h * 2 + 1]);
                }
        }
        __syncthreads();   // all mma reads of h done before gsm overwrite

        // ---- fragments -> aliased gate buffer (own quarter section) ----
        float* gq = gsm + (wid >> 2) * GQ;
#pragma unroll
        for (int mt = 0; mt < 2; mt++)
#pragma unroll
            for (int nt = 0; nt < 2; nt++) {
                int m = mt * 16 + (lane >> 2);
                int n = nt * 8 + (lane & 3) * 2;
                float* gbase = gq + (gate * 32 + m) * GPITCH + n;
                *(float2*)gbase                = make_float2(c[mt][nt][0], c[mt][nt][1]);
                *(float2*)(gbase + 8 * GPITCH) = make_float2(c[mt][nt][2], c[mt][nt][3]);
            }
        __syncthreads();

        // ---- gates + state update: one (b, col) per thread ----
        {
            float gv[4];
#pragma unroll
            for (int g = 0; g < 4; g++) {
                float s = pr[g];
#pragma unroll
                for (int q = 0; q < 4; q++)
                    s += gsm[q * GQ + (g * 32 + bl_) * GPITCH + j];
                gv[g] = s;
            }
            float i_ = 1.0f / (1.0f + __expf(-gv[0]));
            float f_ = 1.0f / (1.0f + __expf(-gv[1]));
            float e2 = __expf(2.0f * gv[2]);
            float g_ = (e2 - 1.0f) / (e2 + 1.0f);
            float o_ = 1.0f / (1.0f + __expf(-gv[3]));

            float cn = f_ * c_r + i_ * g_;
            c_r = cn;
            float ec = __expf(2.0f * cn);
            float th = (ec - 1.0f) / (ec + 1.0f);
            float hv = o_ * th;

            __nv_bfloat16 hh = __float2bfloat16_rn(hv);
            __nv_bfloat16 hl = __float2bfloat16_rn(hv - __bfloat162float(hh));
            size_t off = ((size_t)b_g * TT + t) * HH + col;
            ph[off] = hh;
            pl[off] = hl;
        }

        // ---- arrive: counter RMW; last arriver release-stores the flag ----
        __syncthreads();
        if (tid == 0) {
            unsigned old;
            asm volatile("atom.acq_rel.gpu.global.add.u32 %0, [%1], %2;"
                         : "=r"(old) : "l"(ctr), "r"(1u) : "memory");
            if (old == (unsigned)(t * 32 + 31)) {
                asm volatile("st.release.gpu.global.u32 [%0], %1;"
                             :: "l"(flag), "r"((unsigned)(t + 1)) : "memory");
            }
        }
    }
}

// ---------------- host driver --------------------------------------------
extern "C" void kernel_launch(void* const* d_in, const int* in_sizes, int n_in,
                              void* d_out, int out_size)
{
    const float* x     = (const float*)d_in[0];
    const float* c_dec = (const float*)d_in[1];
    const float* eWih0 = (const float*)d_in[2];
    const float* eWhh0 = (const float*)d_in[3];
    const float* ebih0 = (const float*)d_in[4];
    const float* ebhh0 = (const float*)d_in[5];
    const float* eWih1 = (const float*)d_in[6];
    const float* eWhh1 = (const float*)d_in[7];
    const float* ebih1 = (const float*)d_in[8];
    const float* ebhh1 = (const float*)d_in[9];
    const float* dWih0 = (const float*)d_in[10];
    const float* dWhh0 = (const float*)d_in[11];
    const float* dbih0 = (const float*)d_in[12];
    const float* dbhh0 = (const float*)d_in[13];
    const float* dWih1 = (const float*)d_in[14];
    const float* dWhh1 = (const float*)d_in[15];
    const float* dbih1 = (const float*)d_in[16];
    const float* dbhh1 = (const float*)d_in[17];
    const float* fcW   = (const float*)d_in[18];
    const float* fcB   = (const float*)d_in[19];
    float*       out   = (float*)d_out;

    static float *pre = nullptr;
    static __nv_bfloat16 *bXh, *bXl, *bYh, *bYl, *wh, *wl;
    static unsigned *bars = nullptr;
    static bool inited = false;
    if (!inited) {
        cudaGetSymbolAddress((void**)&pre,  g_pre);
        cudaGetSymbolAddress((void**)&bXh,  g_bufXh);
        cudaGetSymbolAddress((void**)&bXl,  g_bufXl);
        cudaGetSymbolAddress((void**)&bYh,  g_bufYh);
        cudaGetSymbolAddress((void**)&bYl,  g_bufYl);
        cudaGetSymbolAddress((void**)&wh,   g_wh);
        cudaGetSymbolAddress((void**)&wl,   g_wl);
        cudaGetSymbolAddress((void**)&bars, g_barrier);
        cudaFuncSetAttribute(lstm_scan,
                             cudaFuncAttributeMaxDynamicSharedMemorySize, SCAN_SMEM);
        cudaFuncSetAttribute(gemm_mma<false>,
                             cudaFuncAttributeMaxDynamicSharedMemorySize, GM_SMEM);
        cudaFuncSetAttribute(gemm_mma<true>,
                             cudaFuncAttributeMaxDynamicSharedMemorySize, GM_SMEM);
        inited = true;
    }

    const int M = BB * TT;
    const dim3 gemmGrid2048(G4 / 128, M / 64);
    const dim3 gemmGrid128(II / 128,  M / 64);
    const dim3 scanGrid(4, 32);
    const long long seqStride = (long long)TT * HH;

    zero_bar<<<4, 256>>>(bars, 1024);

    // ---- pre-split all feed-forward weights into bf16 planes ----
    split_planes<<<(2048 * 128 + 255) / 256, 256>>>(eWih0, wh + WO0, wl + WO0, 2048 * 128);
    split_planes<<<(2048 * 512 + 255) / 256, 256>>>(eWih1, wh + WO1, wl + WO1, 2048 * 512);
    split_planes<<<(2048 * 128 + 255) / 256, 256>>>(dWih0, wh + WO2, wl + WO2, 2048 * 128);
    split_planes<<<(2048 * 512 + 255) / 256, 256>>>(dWih1, wh + WO3, wl + WO3, 2048 * 512);
    split_planes<<<(128 * 512 + 255) / 256, 256>>>(fcW,   wh + WO4, wl + WO4, 128 * 512);

    // ---- encoder layer 0 (A = x fp32) ----
    gemm_mma<false><<<gemmGrid2048, 256, GM_SMEM>>>(
        x, nullptr, nullptr, wh + WO0, wl + WO0, ebih0, ebhh0, pre, M, G4, II, 0);
    lstm_scan<<<scanGrid, 512, SCAN_SMEM>>>(pre, eWhh0, nullptr, nullptr, 0, nullptr,
                                            bXh, bXl, bars + 0 * 256);

    // ---- encoder layer 1 (A = bufX planes) ----
    gemm_mma<true><<<gemmGrid2048, 256, GM_SMEM>>>(
        nullptr, bXh, bXl, wh + WO1, wl + WO1, ebih1, ebhh1, pre, M, G4, HH, 0);
    lstm_scan<<<scanGrid, 512, SCAN_SMEM>>>(pre, eWhh1, nullptr, nullptr, 0, nullptr,
                                            bYh, bYl, bars + 1 * 256);

    // ---- decoder layer 0 (A = x fp32 shifted; h0 = enc0 final row) ----
    gemm_mma<false><<<gemmGrid2048, 256, GM_SMEM>>>(
        x, nullptr, nullptr, wh + WO2, wl + WO2, dbih0, dbhh0, pre, M, G4, II, TT);
    lstm_scan<<<scanGrid, 512, SCAN_SMEM>>>(pre, dWhh0,
                                            bXh + (size_t)(TT - 1) * HH,
                                            bXl + (size_t)(TT - 1) * HH,
                                            seqStride, c_dec,
                                            bXh, bXl, bars + 2 * 256);

    // ---- decoder layer 1 (A = bufX planes; h0 = enc1 final row) ----
    gemm_mma<true><<<gemmGrid2048, 256, GM_SMEM>>>(
        nullptr, bXh, bXl, wh + WO3, wl + WO3, dbih1, dbhh1, pre, M, G4, HH, 0);
    lstm_scan<<<scanGrid, 512, SCAN_SMEM>>>(pre, dWhh1,
                                            bYh + (size_t)(TT - 1) * HH,
                                            bYl + (size_t)(TT - 1) * HH,
                                            seqStride, c_dec + BB * HH,
                                            bYh, bYl, bars + 3 * 256);

    // ---- FC head (A = bufY planes) ----
    gemm_mma<true><<<gemmGrid128, 256, GM_SMEM>>>(
        nullptr, bYh, bYl, wh + WO4, wl + WO4, fcB, nullptr, out, M, II, HH, 0);
}

// round 12
// speedup vs baseline: 3.1287x; 1.0256x over previous
#include <cuda_runtime.h>
#include <cuda_bf16.h>
#include <math.h>
#include <stdint.h>

// Problem constants
#define BB   128      // batch
#define TT   512      // time steps
#define HH   512      // hidden
#define II   128      // input dim
#define G4   2048     // 4*H

// ---------------- scratch (static device memory; no allocations) ----------
__device__ float g_pre [(size_t)BB * TT * G4];
__device__ __align__(16) __nv_bfloat16 g_bufXh[(size_t)BB * TT * HH];
__device__ __align__(16) __nv_bfloat16 g_bufXl[(size_t)BB * TT * HH];
__device__ __align__(16) __nv_bfloat16 g_bufYh[(size_t)BB * TT * HH];
__device__ __align__(16) __nv_bfloat16 g_bufYl[(size_t)BB * TT * HH];
__device__ __align__(16) __nv_bfloat16 g_xh[(size_t)BB * TT * II];
__device__ __align__(16) __nv_bfloat16 g_xl[(size_t)BB * TT * II];
// weight planes: [enc0 2048x128][enc1 2048x512][dec0 2048x128][dec1 2048x512][fc 128x512]
#define WO0 0
#define WO1 (WO0 + 2048 * 128)
#define WO2 (WO1 + 2048 * 512)
#define WO3 (WO2 + 2048 * 128)
#define WO4 (WO3 + 2048 * 512)
#define WTOT (WO4 + 128 * 512)
__device__ __align__(16) __nv_bfloat16 g_wh[WTOT];
__device__ __align__(16) __nv_bfloat16 g_wl[WTOT];
__device__ unsigned g_barrier[1024];  // 4 layers x 4 groups: counter g*64, flag g*64+32

// ---------------- tiny init kernels ----------------------------------------
__global__ void zero_bar(unsigned* p, int n) {
    int i = blockIdx.x * blockDim.x + threadIdx.x;
    if (i < n) p[i] = 0u;
}
__global__ void split_planes(const float* __restrict__ in,
                             __nv_bfloat16* __restrict__ oh,
                             __nv_bfloat16* __restrict__ ol, int n) {
    int i = blockIdx.x * blockDim.x + threadIdx.x;
    if (i < n) {
        float v = in[i];
        __nv_bfloat16 h = __float2bfloat16_rn(v);
        oh[i] = h;
        ol[i] = __float2bfloat16_rn(v - __bfloat162float(h));
    }
}

// ======================= helpers (compute_103-safe) ========================
__device__ __forceinline__ uint32_t smem_u32(const void* p) {
    return (uint32_t)__cvta_generic_to_shared(p);
}

#define LDSM4(d, addr)                                                        \
    asm volatile("ldmatrix.sync.aligned.m8n8.x4.shared.b16 "                  \
                 "{%0,%1,%2,%3}, [%4];"                                       \
                 : "=r"((d)[0]), "=r"((d)[1]), "=r"((d)[2]), "=r"((d)[3])     \
                 : "r"(addr))

#define MMA_BF16(cc, a, bb0, bb1)                                             \
    asm volatile("mma.sync.aligned.m16n8k16.row.col.f32.bf16.bf16.f32 "       \
                 "{%0,%1,%2,%3}, {%4,%5,%6,%7}, {%8,%9}, {%0,%1,%2,%3};"      \
                 : "+f"((cc)[0]), "+f"((cc)[1]), "+f"((cc)[2]), "+f"((cc)[3]) \
                 : "r"((a)[0]), "r"((a)[1]), "r"((a)[2]), "r"((a)[3]),        \
                   "r"(bb0), "r"(bb1))

#define CP_A16(dst, src, sz)                                                  \
    asm volatile("cp.async.cg.shared.global [%0], [%1], 16, %2;"              \
                 :: "r"(dst), "l"(src), "r"(sz) : "memory")
#define CP_COMMIT() asm volatile("cp.async.commit_group;" ::: "memory")
#define CP_WAIT1()  asm volatile("cp.async.wait_group 1;" ::: "memory")
#define CP_WAIT0()  asm volatile("cp.async.wait_group 0;" ::: "memory")

__device__ __forceinline__ void split2(float x, float y,
                                       uint32_t& hi, uint32_t& lo) {
    __nv_bfloat16 hx = __float2bfloat16_rn(x);
    __nv_bfloat16 hy = __float2bfloat16_rn(y);
    __nv_bfloat16 lx = __float2bfloat16_rn(x - __bfloat162float(hx));
    __nv_bfloat16 ly = __float2bfloat16_rn(y - __bfloat162float(hy));
    hi = ((uint32_t)__bfloat16_as_ushort(hy) << 16) | __bfloat16_as_ushort(hx);
    lo = ((uint32_t)__bfloat16_as_ushort(ly) << 16) | __bfloat16_as_ushort(lx);
}

// ===================== bf16x3 mma.sync GEMM v4 =============================
// All operands pre-split bf16 planes. cp.async 3-stage pipeline; no in-loop
// conversion. CTA 64x128, 8 warps, 2 CTAs/SM.
// shiftT != 0: logical A row r (t = r % shiftT) reads physical row r-1, or
// zero-fills (cp.async src-size 0) at t==0.
#define APITCH   40
#define A_U16    (64 * APITCH)
#define W_U16G   (128 * APITCH)
#define STAGE_U16 (2 * A_U16 + 2 * W_U16G)   // 15360 u16 = 30720 B
#define OFF_AH   0
#define OFF_AL   A_U16
#define OFF_WH   (2 * A_U16)
#define OFF_WL   (2 * A_U16 + W_U16G)
#define GM_SMEM  (3 * STAGE_U16 * 2)          // 92160 B

__global__ __launch_bounds__(256, 2) void gemm_v4(
    const __nv_bfloat16* __restrict__ Ahp,
    const __nv_bfloat16* __restrict__ Alp,
    const __nv_bfloat16* __restrict__ Whp,
    const __nv_bfloat16* __restrict__ Wlp,
    const float* __restrict__ b1, const float* __restrict__ b2,
    float* __restrict__ C, int M, int N, int K, int shiftT)
{
    extern __shared__ __align__(16) uint16_t sm16[];

    const int tid  = threadIdx.x;
    const int lane = tid & 31;
    const int wid  = tid >> 5;
    const int wm   = (wid & 1) * 32;
    const int wn   = (wid >> 1) * 32;
    const int row0 = blockIdx.y * 64;
    const int col0 = blockIdx.x * 128;

    float c[2][4][4];
#pragma unroll
    for (int i = 0; i < 2; i++)
#pragma unroll
        for (int j = 0; j < 4; j++)
#pragma unroll
            for (int q = 0; q < 4; q++) c[i][j][q] = 0.0f;

    const int nch = K / 32;

    // A mapping: thread -> (row ar, 8-elem col ac) per plane
    const int ar = tid >> 2;
    const int ac = (tid & 3) * 8;
    int grow = row0 + ar;
    int srow = grow, ssz = 16;
    if (shiftT) {
        if ((grow % shiftT) == 0) ssz = 0;
        else srow = grow - 1;
    }

    auto issue = [&](int i) {
        uint16_t* st = sm16 + (i % 3) * STAGE_U16;
        const uint32_t sb = smem_u32(st);
        const int k0 = i * 32;
        uint32_t da = sb + (uint32_t)((ar * APITCH + ac) * 2);
        CP_A16(da + OFF_AH * 2, (const void*)&Ahp[(size_t)srow * K + k0 + ac], ssz);
        CP_A16(da + OFF_AL * 2, (const void*)&Alp[(size_t)srow * K + k0 + ac], ssz);
#pragma unroll
        for (int q = 0; q < 4; q++) {
            int e  = q * 256 + tid;
            int pl = e >> 9;
            int rr = (e >> 2) & 127;
            int cc = (e & 3) * 8;
            const __nv_bfloat16* Wp = pl ? Wlp : Whp;
            uint32_t dw = sb + (uint32_t)((pl ? OFF_WL : OFF_WH) * 2)
                        + (uint32_t)((rr * APITCH + cc) * 2);
            CP_A16(dw, (const void*)&Wp[(size_t)(col0 + rr) * K + k0 + cc], 16);
        }
    };

    issue(0);
    CP_COMMIT();
    if (nch > 1) issue(1);
    CP_COMMIT();

    for (int i = 0; i < nch; i++) {
        CP_WAIT1();
        __syncthreads();
        const uint32_t base = smem_u32(sm16 + (i % 3) * STAGE_U16);
#pragma unroll
        for (int kh = 0; kh < 2; kh++) {
            uint32_t ah[2][4], al[2][4];
            const int arow = wm + (lane & 15);
            const int akk  = kh * 16 + (lane >> 4) * 8;
#pragma unroll
            for (int mt = 0; mt < 2; mt++) {
                uint32_t boff = (uint32_t)(((arow + mt * 16) * APITCH + akk) * 2);
                LDSM4(ah[mt], base + OFF_AH * 2 + boff);
                LDSM4(al[mt], base + OFF_AL * 2 + boff);
            }
            uint32_t bh[2][4], bl[2][4];
            const int brow = wn + (lane & 7) + ((lane >> 4) << 3);
            const int bkk  = kh * 16 + ((lane >> 3) & 1) * 8;
#pragma unroll
            for (int np = 0; np < 2; np++) {
                uint32_t boff = (uint32_t)(((brow + np * 16) * APITCH + bkk) * 2);
                LDSM4(bh[np], base + OFF_WH * 2 + boff);
                LDSM4(bl[np], base + OFF_WL * 2 + boff);
            }
#pragma unroll
            for (int mt = 0; mt < 2; mt++)
#pragma unroll
                for (int np = 0; np < 2; np++)
#pragma unroll
                    for (int h = 0; h < 2; h++) {
                        int nt = np * 2 + h;
                        MMA_BF16(c[mt][nt], ah[mt], bh[np][h * 2], bh[np][h * 2 + 1]);
                        MMA_BF16(c[mt][nt], ah[mt], bl[np][h * 2], bl[np][h * 2 + 1]);
                        MMA_BF16(c[mt][nt], al[mt], bh[np][h * 2], bh[np][h * 2 + 1]);
                    }
        }
        if (i + 2 < nch) issue(i + 2);
        CP_COMMIT();
    }

#pragma unroll
    for (int mt = 0; mt < 2; mt++) {
#pragma unroll
        for (int nt = 0; nt < 4; nt++) {
            int m = row0 + wm + mt * 16 + (lane >> 2);
            int n = col0 + wn + nt * 8 + (lane & 3) * 2;
            float bx = b1[n]     + (b2 ? b2[n]     : 0.f);
            float by = b1[n + 1] + (b2 ? b2[n + 1] : 0.f);
            float2 v0 = make_float2(c[mt][nt][0] + bx, c[mt][nt][1] + by);
            float2 v1 = make_float2(c[mt][nt][2] + bx, c[mt][nt][3] + by);
            *(float2*)&C[(size_t)m * N + n]       = v0;
            *(float2*)&C[(size_t)(m + 8) * N + n] = v1;
        }
    }
}

// ===================== tensor-core persistent LSTM scan v8 =================
// v7 (512 threads, K-quarter warps, aliased gate buffer) with cp.async h
// staging: global->smem directly on the post-flag critical path.
#define WPITCH 520
#define W_U16S (64 * WPITCH)
#define H_U16S (32 * WPITCH)
#define GPITCH 18
#define GQ     (4 * 32 * GPITCH)
#define SCAN_SMEM ((2 * W_U16S + 2 * H_U16S) * 2)

__global__ __launch_bounds__(512, 1) void lstm_scan(
    const float* __restrict__ pre,            // [B,T,4H]
    const float* __restrict__ Whh,            // [4H,H] fp32 (split once here)
    const __nv_bfloat16* __restrict__ h0h,    // initial hidden planes or null
    const __nv_bfloat16* __restrict__ h0l,
    long long h0s,
    const float* __restrict__ cinit,          // [B,H] initial cell or null
    __nv_bfloat16* __restrict__ ph,           // output hidden planes [B,T,H]
    __nv_bfloat16* __restrict__ pl,
    unsigned* __restrict__ bar)
{
    extern __shared__ __align__(16) uint16_t sm16[];
    uint16_t* wsh = sm16;
    uint16_t* wsl = wsh + W_U16S;
    uint16_t* hsh = wsl + W_U16S;
    uint16_t* hsl = hsh + H_U16S;
    float*    gsm = (float*)hsh;              // ALIASED over h region

    const int tid  = threadIdx.x;
    const int lane = tid & 31;
    const int wid  = tid >> 5;
    const int gate = wid & 3;
    const int kbase = (wid >> 2) * 128;
    const int grp  = blockIdx.x;
    const int bi0  = grp * 32;
    const int hc0  = blockIdx.y * 16;
    unsigned* ctr  = bar + grp * 64;
    unsigned* flag = ctr + 32;

    // ---- load + split Whh slice once ----
    for (int idx = tid * 4; idx < 64 * 512; idx += 512 * 4) {
        int r  = idx >> 9;
        int k  = idx & 511;
        int gt = r >> 4;
        int rr = r & 15;
        float4 v = *(const float4*)&Whh[((size_t)gt * HH + hc0 + rr) * HH + k];
        uint32_t h0w, l0w, h1w, l1w;
        split2(v.x, v.y, h0w, l0w);
        split2(v.z, v.w, h1w, l1w);
        *(uint2*)&wsh[r * WPITCH + k] = make_uint2(h0w, h1w);
        *(uint2*)&wsl[r * WPITCH + k] = make_uint2(l0w, l1w);
    }

    const int j   = tid & 15;
    const int bl_ = tid >> 4;
    const int b_g = bi0 + bl_;
    const int col = hc0 + j;
    float c_r = cinit ? cinit[b_g * HH + col] : 0.0f;

    const uint32_t hshb = smem_u32(hsh);
    const uint32_t hslb = smem_u32(hsl);
    const uint32_t wshb = smem_u32(wsh);
    const uint32_t wslb = smem_u32(wsl);

    const int arow = lane & 15;
    const int aoff = (lane >> 4) * 8;
    const int brow = gate * 16 + (lane & 7) + ((lane >> 4) << 3);
    const int boff = ((lane >> 3) & 1) * 8;

    for (int t = 0; t < TT; t++) {
        // ---- prefetch pre(t) (h-independent; overlaps poll) ----
        float pr[4];
        {
            size_t prow = ((size_t)b_g * TT + t) * (size_t)G4;
#pragma unroll
            for (int g = 0; g < 4; g++)
                pr[g] = pre[prow + g * HH + col];
        }

        // ---- wait on read-only flag ----
        if (t > 0) {
            unsigned v;
            do {
                asm volatile("ld.acquire.gpu.global.u32 %0, [%1];"
                             : "=r"(v) : "l"(flag) : "memory");
            } while (v < (unsigned)t);
        }

        // ---- stage h(t-1) via cp.async (global -> smem) ----
#pragma unroll
        for (int p = 0; p < 4; p++) {
            int e  = p * 512 + tid;           // 0..2047
            int r  = e >> 6;                  // 0..31
            int c8 = (e & 63) * 8;
            uint32_t d = (uint32_t)((r * WPITCH + c8) * 2);
            if (t == 0) {
                if (h0h) {
                    CP_A16(hshb + d, (const void*)&h0h[(size_t)(bi0 + r) * h0s + c8], 16);
                    CP_A16(hslb + d, (const void*)&h0l[(size_t)(bi0 + r) * h0s + c8], 16);
                } else {
                    CP_A16(hshb + d, (const void*)ph, 0);
                    CP_A16(hslb + d, (const void*)pl, 0);
                }
            } else {
                size_t off = ((size_t)(bi0 + r) * TT + (t - 1)) * HH + c8;
                CP_A16(hshb + d, (const void*)&ph[off], 16);
                CP_A16(hslb + d, (const void*)&pl[off], 16);
            }
        }
        CP_COMMIT();
        CP_WAIT0();
        __syncthreads();

        // ---- mma: this warp's gate over its K quarter ----
        float c[2][2][4];
#pragma unroll
        for (int mt = 0; mt < 2; mt++)
#pragma unroll
            for (int nt = 0; nt < 2; nt++)
#pragma unroll
                for (int q = 0; q < 4; q++) c[mt][nt][q] = 0.0f;

#pragma unroll
        for (int q = 0; q < 8; q++) {
            int kc = kbase + q * 16;
            uint32_t ah[2][4], al[2][4], bh4[4], bl4[4];
#pragma unroll
            for (int mt = 0; mt < 2; mt++) {
                uint32_t off = (uint32_t)(((mt * 16 + arow) * WPITCH + kc + aoff) * 2);
                LDSM4(ah[mt], hshb + off);
                LDSM4(al[mt], hslb + off);
            }
            {
                uint32_t off = (uint32_t)((brow * WPITCH + kc + boff) * 2);
                LDSM4(bh4, wshb + off);
                LDSM4(bl4, wslb + off);
            }
#pragma unroll
            for (int mt = 0; mt < 2; mt++)
#pragma unroll
                for (int h = 0; h < 2; h++) {
                    MMA_BF16(c[mt][h], ah[mt], bh4[h * 2], bh4[h * 2 + 1]);
                    MMA_BF16(c[mt][h], ah[mt], bl4[h * 2], bl4[h * 2 + 1]);
                    MMA_BF16(c[mt][h], al[mt], bh4[h * 2], bh4[h * 2 + 1]);
                }
        }
        __syncthreads();   // all mma reads of h done before gsm overwrite

        // ---- fragments -> aliased gate buffer (own quarter section) ----
        float* gq = gsm + (wid >> 2) * GQ;
#pragma unroll
        for (int mt = 0; mt < 2; mt++)
#pragma unroll
            for (int nt = 0; nt < 2; nt++) {
                int m = mt * 16 + (lane >> 2);
                int n = nt * 8 + (lane & 3) * 2;
                float* gbase = gq + (gate * 32 + m) * GPITCH + n;
                *(float2*)gbase                = make_float2(c[mt][nt][0], c[mt][nt][1]);
                *(float2*)(gbase + 8 * GPITCH) = make_float2(c[mt][nt][2], c[mt][nt][3]);
            }
        __syncthreads();

        // ---- gates + state update: one (b, col) per thread ----
        {
            float gv[4];
#pragma unroll
            for (int g = 0; g < 4; g++) {
                float s = pr[g];
#pragma unroll
                for (int q = 0; q < 4; q++)
                    s += gsm[q * GQ + (g * 32 + bl_) * GPITCH + j];
                gv[g] = s;
            }
            float i_ = 1.0f / (1.0f + __expf(-gv[0]));
            float f_ = 1.0f / (1.0f + __expf(-gv[1]));
            float e2 = __expf(2.0f * gv[2]);
            float g_ = (e2 - 1.0f) / (e2 + 1.0f);
            float o_ = 1.0f / (1.0f + __expf(-gv[3]));

            float cn = f_ * c_r + i_ * g_;
            c_r = cn;
            float ec = __expf(2.0f * cn);
            float th = (ec - 1.0f) / (ec + 1.0f);
            float hv = o_ * th;

            __nv_bfloat16 hh = __float2bfloat16_rn(hv);
            __nv_bfloat16 hl = __float2bfloat16_rn(hv - __bfloat162float(hh));
            size_t off = ((size_t)b_g * TT + t) * HH + col;
            ph[off] = hh;
            pl[off] = hl;
        }

        // ---- arrive: counter RMW; last arriver release-stores the flag ----
        __syncthreads();
        if (tid == 0) {
            unsigned old;
            asm volatile("atom.acq_rel.gpu.global.add.u32 %0, [%1], %2;"
                         : "=r"(old) : "l"(ctr), "r"(1u) : "memory");
            if (old == (unsigned)(t * 32 + 31)) {
                asm volatile("st.release.gpu.global.u32 [%0], %1;"
                             :: "l"(flag), "r"((unsigned)(t + 1)) : "memory");
            }
        }
    }
}

// ---------------- host driver --------------------------------------------
extern "C" void kernel_launch(void* const* d_in, const int* in_sizes, int n_in,
                              void* d_out, int out_size)
{
    const float* x     = (const float*)d_in[0];
    const float* c_dec = (const float*)d_in[1];
    const float* eWih0 = (const float*)d_in[2];
    const float* eWhh0 = (const float*)d_in[3];
    const float* ebih0 = (const float*)d_in[4];
    const float* ebhh0 = (const float*)d_in[5];
    const float* eWih1 = (const float*)d_in[6];
    const float* eWhh1 = (const float*)d_in[7];
    const float* ebih1 = (const float*)d_in[8];
    const float* ebhh1 = (const float*)d_in[9];
    const float* dWih0 = (const float*)d_in[10];
    const float* dWhh0 = (const float*)d_in[11];
    const float* dbih0 = (const float*)d_in[12];
    const float* dbhh0 = (const float*)d_in[13];
    const float* dWih1 = (const float*)d_in[14];
    const float* dWhh1 = (const float*)d_in[15];
    const float* dbih1 = (const float*)d_in[16];
    const float* dbhh1 = (const float*)d_in[17];
    const float* fcW   = (const float*)d_in[18];
    const float* fcB   = (const float*)d_in[19];
    float*       out   = (float*)d_out;

    static float *pre = nullptr;
    static __nv_bfloat16 *bXh, *bXl, *bYh, *bYl, *xh, *xl, *wh, *wl;
    static unsigned *bars = nullptr;
    static bool inited = false;
    if (!inited) {
        cudaGetSymbolAddress((void**)&pre,  g_pre);
        cudaGetSymbolAddress((void**)&bXh,  g_bufXh);
        cudaGetSymbolAddress((void**)&bXl,  g_bufXl);
        cudaGetSymbolAddress((void**)&bYh,  g_bufYh);
        cudaGetSymbolAddress((void**)&bYl,  g_bufYl);
        cudaGetSymbolAddress((void**)&xh,   g_xh);
        cudaGetSymbolAddress((void**)&xl,   g_xl);
        cudaGetSymbolAddress((void**)&wh,   g_wh);
        cudaGetSymbolAddress((void**)&wl,   g_wl);
        cudaGetSymbolAddress((void**)&bars, g_barrier);
        cudaFuncSetAttribute(lstm_scan,
                             cudaFuncAttributeMaxDynamicSharedMemorySize, SCAN_SMEM);
        cudaFuncSetAttribute(gemm_v4,
                             cudaFuncAttributeMaxDynamicSharedMemorySize, GM_SMEM);
        inited = true;
    }

    const int M = BB * TT;
    const dim3 gemmGrid2048(G4 / 128, M / 64);
    const dim3 gemmGrid128(II / 128,  M / 64);
    const dim3 scanGrid(4, 32);
    const long long seqStride = (long long)TT * HH;

    zero_bar<<<4, 256>>>(bars, 1024);

    // ---- pre-split x and all feed-forward weights into bf16 planes ----
    split_planes<<<(M * II + 255) / 256, 256>>>(x, xh, xl, M * II);
    split_planes<<<(2048 * 128 + 255) / 256, 256>>>(eWih0, wh + WO0, wl + WO0, 2048 * 128);
    split_planes<<<(2048 * 512 + 255) / 256, 256>>>(eWih1, wh + WO1, wl + WO1, 2048 * 512);
    split_planes<<<(2048 * 128 + 255) / 256, 256>>>(dWih0, wh + WO2, wl + WO2, 2048 * 128);
    split_planes<<<(2048 * 512 + 255) / 256, 256>>>(dWih1, wh + WO3, wl + WO3, 2048 * 512);
    split_planes<<<(128 * 512 + 255) / 256, 256>>>(fcW,   wh + WO4, wl + WO4, 128 * 512);

    // ---- encoder layer 0 (A = x planes) ----
    gemm_v4<<<gemmGrid2048, 256, GM_SMEM>>>(
        xh, xl, wh + WO0, wl + WO0, ebih0, ebhh0, pre, M, G4, II, 0);
    lstm_scan<<<scanGrid, 512, SCAN_SMEM>>>(pre, eWhh0, nullptr, nullptr, 0, nullptr,
                                            bXh, bXl, bars + 0 * 256);

    // ---- encoder layer 1 (A = bufX planes) ----
    gemm_v4<<<gemmGrid2048, 256, GM_SMEM>>>(
        bXh, bXl, wh + WO1, wl + WO1, ebih1, ebhh1, pre, M, G4, HH, 0);
    lstm_scan<<<scanGrid, 512, SCAN_SMEM>>>(pre, eWhh1, nullptr, nullptr, 0, nullptr,
                                            bYh, bYl, bars + 1 * 256);

    // ---- decoder layer 0 (A = x planes shifted; h0 = enc0 final row) ----
    gemm_v4<<<gemmGrid2048, 256, GM_SMEM>>>(
        xh, xl, wh + WO2, wl + WO2, dbih0, dbhh0, pre, M, G4, II, TT);
    lstm_scan<<<scanGrid, 512, SCAN_SMEM>>>(pre, dWhh0,
                                            bXh + (size_t)(TT - 1) * HH,
                                            bXl + (size_t)(TT - 1) * HH,
                                            seqStride, c_dec,
                                            bXh, bXl, bars + 2 * 256);

    // ---- decoder layer 1 (A = bufX planes; h0 = enc1 final row) ----
    gemm_v4<<<gemmGrid2048, 256, GM_SMEM>>>(
        bXh, bXl, wh + WO3, wl + WO3, dbih1, dbhh1, pre, M, G4, HH, 0);
    lstm_scan<<<scanGrid, 512, SCAN_SMEM>>>(pre, dWhh1,
                                            bYh + (size_t)(TT - 1) * HH,
                                            bYl + (size_t)(TT - 1) * HH,
                                            seqStride, c_dec + BB * HH,
                                            bYh, bYl, bars + 3 * 256);

    // ---- FC head (A = bufY planes) ----
    gemm_v4<<<gemmGrid128, 256, GM_SMEM>>>(
        bYh, bYl, wh + WO4, wl + WO4, fcB, nullptr, out, M, II, HH, 0);
}